// round 2
// baseline (speedup 1.0000x reference)
#include <cuda_runtime.h>
#include <math.h>

#define TOK   32768
#define LL    2048
#define ATT_SCALE 0.08838834764831845f

__device__ float g_Qw[TOK * 128];
__device__ float g_Kw[TOK * 128];
__device__ float g_Vw[TOK * 128];
__device__ float g_attn[TOK * 128];
__device__ float g_msg[TOK * 128];
__device__ float g_hidden[(size_t)TOK * 1024];

__device__ __forceinline__ unsigned f2tf(float f) {
    unsigned u;
    asm("cvt.rna.tf32.f32 %0, %1;" : "=r"(u) : "f"(f));
    return u;
}

__device__ __forceinline__ void mma8(float* c, unsigned a0, unsigned a1,
                                     unsigned a2, unsigned a3,
                                     unsigned b0, unsigned b1) {
    asm volatile(
        "mma.sync.aligned.m16n8k8.row.col.f32.tf32.tf32.f32 "
        "{%0,%1,%2,%3},{%4,%5,%6,%7},{%8,%9},{%0,%1,%2,%3};"
        : "+f"(c[0]), "+f"(c[1]), "+f"(c[2]), "+f"(c[3])
        : "r"(a0), "r"(a1), "r"(a2), "r"(a3), "r"(b0), "r"(b1));
}

// windowed row -> source token row (forward shift roll + window partition).
// Used for both gather (QKV) and scatter (attn out): window-merge + roll-back
// is the exact inverse of to_windows.
__device__ __forceinline__ int win_src_row(int gr) {
    int b = gr >> 13, rem = gr & 8191;
    int w4 = rem >> 11, p = rem & 2047;
    int wi = w4 >> 1, wj = w4 & 1;
    int iy = p >> 6, ix = p & 63;
    int y = (wi * 32 + iy + 16) & 63;
    int x = (wj * 64 + ix + 32) & 127;
    return (b << 13) + (y << 7) + x;
}

// ---------------- K1: QKV projection + window gather. grid(512,3) x 256 ----
__global__ void k_qkv(const float* __restrict__ src, const float* __restrict__ tgt,
                      const float* __restrict__ Wq, const float* __restrict__ Wk,
                      const float* __restrict__ Wv) {
    extern __shared__ unsigned sm[];
    unsigned* As = sm;               // [64][132]
    unsigned* Ws = sm + 64 * 132;    // [128][132] (n,k)

    const int tid = threadIdx.x, tile = blockIdx.x;
    const float* inp  = (blockIdx.y == 0) ? src : tgt;
    const float* Wsel = (blockIdx.y == 0) ? Wq : (blockIdx.y == 1) ? Wk : Wv;
    float* out = (blockIdx.y == 0) ? g_Qw : (blockIdx.y == 1) ? g_Kw : g_Vw;

    for (int i = tid; i < 64 * 128; i += 256) {
        int r = i >> 7, c = i & 127;
        As[r * 132 + c] = f2tf(inp[(size_t)win_src_row(tile * 64 + r) * 128 + c]);
    }
    for (int i = tid; i < 128 * 128; i += 256) {
        int k = i >> 7, n = i & 127;
        Ws[n * 132 + k] = f2tf(Wsel[i]);
    }
    __syncthreads();

    const int warp = tid >> 5, lane = tid & 31, g = lane >> 2, t4 = lane & 3;
    const int rb = (warp >> 1) * 16, cb = (warp & 1) * 64;
    float acc[8][4];
#pragma unroll
    for (int nt = 0; nt < 8; nt++) acc[nt][0] = acc[nt][1] = acc[nt][2] = acc[nt][3] = 0.f;

#pragma unroll
    for (int k0 = 0; k0 < 128; k0 += 8) {
        unsigned a0 = As[(rb + g) * 132 + k0 + t4];
        unsigned a1 = As[(rb + g + 8) * 132 + k0 + t4];
        unsigned a2 = As[(rb + g) * 132 + k0 + t4 + 4];
        unsigned a3 = As[(rb + g + 8) * 132 + k0 + t4 + 4];
#pragma unroll
        for (int nt = 0; nt < 8; nt++) {
            unsigned b0 = Ws[(cb + nt * 8 + g) * 132 + k0 + t4];
            unsigned b1 = Ws[(cb + nt * 8 + g) * 132 + k0 + t4 + 4];
            mma8(acc[nt], a0, a1, a2, a3, b0, b1);
        }
    }
    int row0 = tile * 64 + rb + g, row1 = row0 + 8;
#pragma unroll
    for (int nt = 0; nt < 8; nt++) {
        int c = cb + nt * 8 + 2 * t4;
        *(float2*)&out[(size_t)row0 * 128 + c] = make_float2(acc[nt][0], acc[nt][1]);
        *(float2*)&out[(size_t)row1 * 128 + c] = make_float2(acc[nt][2], acc[nt][3]);
    }
}

// ---------------- K2: flash attention. grid(16,16) x 256 -------------------
// q-tile 128 rows, k-tile 64. Each warp owns 16 q rows fully; P round-trips
// through warp-local smem (only __syncwarp between P store and PV mma).
__global__ void k_attn(const float* __restrict__ mask) {
    extern __shared__ unsigned sm[];
    unsigned* Qs = sm;                       // [128][132]
    unsigned* Ks = Qs + 128 * 132;           // [64][132]
    unsigned* Vs = Ks + 64 * 132;            // [128][68] (d,k)
    unsigned* Ps = Vs + 128 * 68;            // [128][68]
    float*    Ms = (float*)(Ps + 128 * 68);  // [128][68]

    const int tid = threadIdx.x, warp = tid >> 5, lane = tid & 31;
    const int g = lane >> 2, t4 = lane & 3;
    const int qbase = blockIdx.x * 128, win = blockIdx.y, w4 = win & 3;
    const int qw = warp * 16;

    const float* Qg = g_Qw + ((size_t)(win * LL + qbase)) * 128;
    for (int i = tid; i < 128 * 128; i += 256) {
        int r = i >> 7, c = i & 127;
        Qs[r * 132 + c] = f2tf(Qg[i]);
    }
    const float* Mrow = mask + (size_t)w4 * LL * LL + (size_t)qbase * LL;

    float o[16][4];
#pragma unroll
    for (int dt = 0; dt < 16; dt++) o[dt][0] = o[dt][1] = o[dt][2] = o[dt][3] = 0.f;
    float m0 = -1e30f, m1 = -1e30f, l0 = 0.f, l1 = 0.f;

    for (int kt = 0; kt < 32; kt++) {
        const int kbase = kt * 64;
        const float* Kg = g_Kw + ((size_t)(win * LL + kbase)) * 128;
        const float* Vg = g_Vw + ((size_t)(win * LL + kbase)) * 128;

        __syncthreads();
        for (int i = tid; i < 64 * 128; i += 256) {
            int r = i >> 7, c = i & 127;
            Ks[r * 132 + c] = f2tf(Kg[i]);
            Vs[c * 68 + r]  = f2tf(Vg[i]);
        }
        for (int i = tid; i < 128 * 64; i += 256) {
            int r = i >> 6, c = i & 63;
            Ms[r * 68 + c] = Mrow[(size_t)r * LL + kbase + c];
        }
        __syncthreads();

        float s[8][4];
#pragma unroll
        for (int nt = 0; nt < 8; nt++) s[nt][0] = s[nt][1] = s[nt][2] = s[nt][3] = 0.f;
#pragma unroll
        for (int d0 = 0; d0 < 128; d0 += 8) {
            unsigned a0 = Qs[(qw + g) * 132 + d0 + t4];
            unsigned a1 = Qs[(qw + g + 8) * 132 + d0 + t4];
            unsigned a2 = Qs[(qw + g) * 132 + d0 + t4 + 4];
            unsigned a3 = Qs[(qw + g + 8) * 132 + d0 + t4 + 4];
#pragma unroll
            for (int nt = 0; nt < 8; nt++) {
                unsigned b0 = Ks[(nt * 8 + g) * 132 + d0 + t4];
                unsigned b1 = Ks[(nt * 8 + g) * 132 + d0 + t4 + 4];
                mma8(s[nt], a0, a1, a2, a3, b0, b1);
            }
        }

        float ml0 = -1e30f, ml1 = -1e30f;
#pragma unroll
        for (int nt = 0; nt < 8; nt++) {
#pragma unroll
            for (int j = 0; j < 2; j++) {
                int col = nt * 8 + 2 * t4 + j;
                float v0 = s[nt][j]     * ATT_SCALE + Ms[(qw + g) * 68 + col];
                float v1 = s[nt][2 + j] * ATT_SCALE + Ms[(qw + g + 8) * 68 + col];
                s[nt][j] = v0; s[nt][2 + j] = v1;
                ml0 = fmaxf(ml0, v0); ml1 = fmaxf(ml1, v1);
            }
        }
        ml0 = fmaxf(ml0, __shfl_xor_sync(~0u, ml0, 1));
        ml0 = fmaxf(ml0, __shfl_xor_sync(~0u, ml0, 2));
        ml1 = fmaxf(ml1, __shfl_xor_sync(~0u, ml1, 1));
        ml1 = fmaxf(ml1, __shfl_xor_sync(~0u, ml1, 2));

        float mn0 = fmaxf(m0, ml0), mn1 = fmaxf(m1, ml1);
        float al0 = __expf(m0 - mn0), al1 = __expf(m1 - mn1);
        m0 = mn0; m1 = mn1;

        float rs0 = 0.f, rs1 = 0.f;
#pragma unroll
        for (int nt = 0; nt < 8; nt++) {
#pragma unroll
            for (int j = 0; j < 2; j++) {
                int col = nt * 8 + 2 * t4 + j;
                float p0 = __expf(s[nt][j] - mn0);
                float p1 = __expf(s[nt][2 + j] - mn1);
                rs0 += p0; rs1 += p1;
                Ps[(qw + g) * 68 + col]     = f2tf(p0);
                Ps[(qw + g + 8) * 68 + col] = f2tf(p1);
            }
        }
        rs0 += __shfl_xor_sync(~0u, rs0, 1);
        rs0 += __shfl_xor_sync(~0u, rs0, 2);
        rs1 += __shfl_xor_sync(~0u, rs1, 1);
        rs1 += __shfl_xor_sync(~0u, rs1, 2);
        l0 = l0 * al0 + rs0;
        l1 = l1 * al1 + rs1;

#pragma unroll
        for (int dt = 0; dt < 16; dt++) {
            o[dt][0] *= al0; o[dt][1] *= al0;
            o[dt][2] *= al1; o[dt][3] *= al1;
        }
        __syncwarp();

#pragma unroll
        for (int k0 = 0; k0 < 64; k0 += 8) {
            unsigned a0 = Ps[(qw + g) * 68 + k0 + t4];
            unsigned a1 = Ps[(qw + g + 8) * 68 + k0 + t4];
            unsigned a2 = Ps[(qw + g) * 68 + k0 + t4 + 4];
            unsigned a3 = Ps[(qw + g + 8) * 68 + k0 + t4 + 4];
#pragma unroll
            for (int dt = 0; dt < 16; dt++) {
                unsigned b0 = Vs[(dt * 8 + g) * 68 + k0 + t4];
                unsigned b1 = Vs[(dt * 8 + g) * 68 + k0 + t4 + 4];
                mma8(o[dt], a0, a1, a2, a3, b0, b1);
            }
        }
    }

    float i0 = 1.f / l0, i1 = 1.f / l1;
    int row0 = win_src_row(win * LL + qbase + qw + g);
    int row1 = win_src_row(win * LL + qbase + qw + g + 8);
#pragma unroll
    for (int dt = 0; dt < 16; dt++) {
        int c = dt * 8 + 2 * t4;
        *(float2*)&g_attn[(size_t)row0 * 128 + c] = make_float2(o[dt][0] * i0, o[dt][1] * i0);
        *(float2*)&g_attn[(size_t)row1 * 128 + c] = make_float2(o[dt][2] * i1, o[dt][3] * i1);
    }
}

// ---------------- K3: message = LN(attn @ Wm). grid 512 x 256 --------------
__global__ void k_wm_ln(const float* __restrict__ Wm, const float* __restrict__ g1,
                        const float* __restrict__ b1) {
    extern __shared__ unsigned sm[];
    unsigned* As = sm;                        // [64][132]
    unsigned* Ws = sm + 64 * 132;             // [128][132]
    float*    Rs = (float*)(Ws + 128 * 132);  // [64][132]

    const int tid = threadIdx.x, tile = blockIdx.x;
    for (int i = tid; i < 64 * 128; i += 256) {
        int r = i >> 7, c = i & 127;
        As[r * 132 + c] = f2tf(g_attn[(size_t)(tile * 64 + r) * 128 + c]);
    }
    for (int i = tid; i < 128 * 128; i += 256) {
        int k = i >> 7, n = i & 127;
        Ws[n * 132 + k] = f2tf(Wm[i]);
    }
    __syncthreads();

    const int warp = tid >> 5, lane = tid & 31, g = lane >> 2, t4 = lane & 3;
    const int rb = (warp >> 1) * 16, cb = (warp & 1) * 64;
    float acc[8][4];
#pragma unroll
    for (int nt = 0; nt < 8; nt++) acc[nt][0] = acc[nt][1] = acc[nt][2] = acc[nt][3] = 0.f;
#pragma unroll
    for (int k0 = 0; k0 < 128; k0 += 8) {
        unsigned a0 = As[(rb + g) * 132 + k0 + t4];
        unsigned a1 = As[(rb + g + 8) * 132 + k0 + t4];
        unsigned a2 = As[(rb + g) * 132 + k0 + t4 + 4];
        unsigned a3 = As[(rb + g + 8) * 132 + k0 + t4 + 4];
#pragma unroll
        for (int nt = 0; nt < 8; nt++) {
            unsigned b0 = Ws[(cb + nt * 8 + g) * 132 + k0 + t4];
            unsigned b1 = Ws[(cb + nt * 8 + g) * 132 + k0 + t4 + 4];
            mma8(acc[nt], a0, a1, a2, a3, b0, b1);
        }
    }
#pragma unroll
    for (int nt = 0; nt < 8; nt++) {
        int c = cb + nt * 8 + 2 * t4;
        Rs[(rb + g) * 132 + c]         = acc[nt][0];
        Rs[(rb + g) * 132 + c + 1]     = acc[nt][1];
        Rs[(rb + g + 8) * 132 + c]     = acc[nt][2];
        Rs[(rb + g + 8) * 132 + c + 1] = acc[nt][3];
    }
    __syncthreads();

    int row = tid >> 2, l4 = tid & 3;
    float sum = 0.f, sq = 0.f;
    for (int c = l4; c < 128; c += 4) {
        float v = Rs[row * 132 + c];
        sum += v; sq += v * v;
    }
    sum += __shfl_xor_sync(~0u, sum, 1); sum += __shfl_xor_sync(~0u, sum, 2);
    sq  += __shfl_xor_sync(~0u, sq, 1);  sq  += __shfl_xor_sync(~0u, sq, 2);
    float mean = sum * 0.0078125f;
    float rstd = rsqrtf(sq * 0.0078125f - mean * mean + 1e-5f);
    for (int c = l4; c < 128; c += 4) {
        g_msg[(size_t)(tile * 64 + row) * 128 + c] =
            (Rs[row * 132 + c] - mean) * rstd * g1[c] + b1[c];
    }
}

// ---------------- K4: hidden = gelu([src|msg] @ W1). grid(512,8) x 256 -----
__global__ void k_mlp1(const float* __restrict__ src, const float* __restrict__ W1) {
    extern __shared__ unsigned sm[];
    unsigned* As = sm;            // [64][68]
    unsigned* Bs = sm + 64 * 68;  // [128][68]

    const int tid = threadIdx.x, tile = blockIdx.x, nb = blockIdx.y * 128;
    const int warp = tid >> 5, lane = tid & 31, g = lane >> 2, t4 = lane & 3;
    const int rb = (warp >> 1) * 16, cb = (warp & 1) * 64;
    float acc[8][4];
#pragma unroll
    for (int nt = 0; nt < 8; nt++) acc[nt][0] = acc[nt][1] = acc[nt][2] = acc[nt][3] = 0.f;

    for (int kc = 0; kc < 256; kc += 64) {
        __syncthreads();
        for (int i = tid; i < 64 * 64; i += 256) {
            int r = i >> 6, k = i & 63, kk = kc + k, row = tile * 64 + r;
            float v = (kk < 128) ? src[(size_t)row * 128 + kk]
                                 : g_msg[(size_t)row * 128 + kk - 128];
            As[r * 68 + k] = f2tf(v);
        }
        for (int i = tid; i < 64 * 128; i += 256) {
            int k = i >> 7, n = i & 127;
            Bs[n * 68 + k] = f2tf(W1[(size_t)(kc + k) * 1024 + nb + n]);
        }
        __syncthreads();
#pragma unroll
        for (int k0 = 0; k0 < 64; k0 += 8) {
            unsigned a0 = As[(rb + g) * 68 + k0 + t4];
            unsigned a1 = As[(rb + g + 8) * 68 + k0 + t4];
            unsigned a2 = As[(rb + g) * 68 + k0 + t4 + 4];
            unsigned a3 = As[(rb + g + 8) * 68 + k0 + t4 + 4];
#pragma unroll
            for (int nt = 0; nt < 8; nt++) {
                unsigned b0 = Bs[(cb + nt * 8 + g) * 68 + k0 + t4];
                unsigned b1 = Bs[(cb + nt * 8 + g) * 68 + k0 + t4 + 4];
                mma8(acc[nt], a0, a1, a2, a3, b0, b1);
            }
        }
    }

    int row0 = tile * 64 + rb + g, row1 = row0 + 8;
#pragma unroll
    for (int nt = 0; nt < 8; nt++) {
        int c = nb + cb + nt * 8 + 2 * t4;
        float x0 = acc[nt][0], x1 = acc[nt][1], x2 = acc[nt][2], x3 = acc[nt][3];
        x0 = 0.5f * x0 * (1.f + erff(x0 * 0.70710678f));
        x1 = 0.5f * x1 * (1.f + erff(x1 * 0.70710678f));
        x2 = 0.5f * x2 * (1.f + erff(x2 * 0.70710678f));
        x3 = 0.5f * x3 * (1.f + erff(x3 * 0.70710678f));
        *(float2*)&g_hidden[(size_t)row0 * 1024 + c] = make_float2(x0, x1);
        *(float2*)&g_hidden[(size_t)row1 * 1024 + c] = make_float2(x2, x3);
    }
}

// ---------------- K5: out = src + LN(hidden @ W2). grid 512 x 256 ----------
__global__ void k_mlp2(const float* __restrict__ src, const float* __restrict__ W2,
                       const float* __restrict__ g2, const float* __restrict__ b2,
                       float* __restrict__ out) {
    extern __shared__ unsigned sm[];
    unsigned* As = sm;                       // [64][68]
    unsigned* Bs = sm + 64 * 68;             // [128][68]
    float*    Rs = (float*)(Bs + 128 * 68);  // [64][132]

    const int tid = threadIdx.x, tile = blockIdx.x;
    const int warp = tid >> 5, lane = tid & 31, g = lane >> 2, t4 = lane & 3;
    const int rb = (warp >> 1) * 16, cb = (warp & 1) * 64;
    float acc[8][4];
#pragma unroll
    for (int nt = 0; nt < 8; nt++) acc[nt][0] = acc[nt][1] = acc[nt][2] = acc[nt][3] = 0.f;

    for (int kc = 0; kc < 1024; kc += 64) {
        __syncthreads();
        for (int i = tid; i < 64 * 64; i += 256) {
            int r = i >> 6, k = i & 63;
            As[r * 68 + k] = f2tf(g_hidden[(size_t)(tile * 64 + r) * 1024 + kc + k]);
        }
        for (int i = tid; i < 64 * 128; i += 256) {
            int k = i >> 7, n = i & 127;
            Bs[n * 68 + k] = f2tf(W2[(size_t)(kc + k) * 128 + n]);
        }
        __syncthreads();
#pragma unroll
        for (int k0 = 0; k0 < 64; k0 += 8) {
            unsigned a0 = As[(rb + g) * 68 + k0 + t4];
            unsigned a1 = As[(rb + g + 8) * 68 + k0 + t4];
            unsigned a2 = As[(rb + g) * 68 + k0 + t4 + 4];
            unsigned a3 = As[(rb + g + 8) * 68 + k0 + t4 + 4];
#pragma unroll
            for (int nt = 0; nt < 8; nt++) {
                unsigned b0 = Bs[(cb + nt * 8 + g) * 68 + k0 + t4];
                unsigned b1 = Bs[(cb + nt * 8 + g) * 68 + k0 + t4 + 4];
                mma8(acc[nt], a0, a1, a2, a3, b0, b1);
            }
        }
    }

#pragma unroll
    for (int nt = 0; nt < 8; nt++) {
        int c = cb + nt * 8 + 2 * t4;
        Rs[(rb + g) * 132 + c]         = acc[nt][0];
        Rs[(rb + g) * 132 + c + 1]     = acc[nt][1];
        Rs[(rb + g + 8) * 132 + c]     = acc[nt][2];
        Rs[(rb + g + 8) * 132 + c + 1] = acc[nt][3];
    }
    __syncthreads();

    int row = tid >> 2, l4 = tid & 3;
    float sum = 0.f, sq = 0.f;
    for (int c = l4; c < 128; c += 4) {
        float v = Rs[row * 132 + c];
        sum += v; sq += v * v;
    }
    sum += __shfl_xor_sync(~0u, sum, 1); sum += __shfl_xor_sync(~0u, sum, 2);
    sq  += __shfl_xor_sync(~0u, sq, 1);  sq  += __shfl_xor_sync(~0u, sq, 2);
    float mean = sum * 0.0078125f;
    float rstd = rsqrtf(sq * 0.0078125f - mean * mean + 1e-5f);
    size_t grow = (size_t)(tile * 64 + row) * 128;
    for (int c = l4; c < 128; c += 4) {
        out[grow + c] = src[grow + c] + (Rs[row * 132 + c] - mean) * rstd * g2[c] + b2[c];
    }
}

extern "C" void kernel_launch(void* const* d_in, const int* in_sizes, int n_in,
                              void* d_out, int out_size) {
    (void)in_sizes; (void)n_in; (void)out_size;
    const float* src  = (const float*)d_in[0];
    const float* tgt  = (const float*)d_in[1];
    const float* mask = (const float*)d_in[2];
    const float* Wq   = (const float*)d_in[8];
    const float* Wk   = (const float*)d_in[9];
    const float* Wv   = (const float*)d_in[10];
    const float* Wm   = (const float*)d_in[11];
    const float* g1   = (const float*)d_in[12];
    const float* b1   = (const float*)d_in[13];
    const float* W1   = (const float*)d_in[14];
    const float* W2   = (const float*)d_in[15];
    const float* g2   = (const float*)d_in[16];
    const float* b2   = (const float*)d_in[17];
    float* out = (float*)d_out;

    const int SM1 = (64 * 132 + 128 * 132) * 4;
    const int SM2 = (128 * 132 + 64 * 132 + 3 * 128 * 68) * 4;
    const int SM3 = (64 * 132 + 128 * 132 + 64 * 132) * 4;
    const int SM4 = (64 * 68 + 128 * 68) * 4;
    const int SM5 = (64 * 68 + 128 * 68 + 64 * 132) * 4;

    static int configured = 0;
    if (!configured) {
        cudaFuncSetAttribute(k_qkv,   cudaFuncAttributeMaxDynamicSharedMemorySize, SM1);
        cudaFuncSetAttribute(k_attn,  cudaFuncAttributeMaxDynamicSharedMemorySize, SM2);
        cudaFuncSetAttribute(k_wm_ln, cudaFuncAttributeMaxDynamicSharedMemorySize, SM3);
        cudaFuncSetAttribute(k_mlp1,  cudaFuncAttributeMaxDynamicSharedMemorySize, SM4);
        cudaFuncSetAttribute(k_mlp2,  cudaFuncAttributeMaxDynamicSharedMemorySize, SM5);
        configured = 1;
    }

    k_qkv  <<<dim3(512, 3), 256, SM1>>>(src, tgt, Wq, Wk, Wv);
    k_attn <<<dim3(16, 16), 256, SM2>>>(mask);
    k_wm_ln<<<512,          256, SM3>>>(Wm, g1, b1);
    k_mlp1 <<<dim3(512, 8), 256, SM4>>>(src, W1);
    k_mlp2 <<<512,          256, SM5>>>(src, W2, g2, b2, out);
}

// round 3
// speedup vs baseline: 1.1727x; 1.1727x over previous
#include <cuda_runtime.h>
#include <math.h>

#define TOK   32768
#define LL    2048
#define ATT_SCALE 0.08838834764831845f

__device__ float g_Qw[TOK * 128];
__device__ float g_Kw[TOK * 128];
__device__ float g_Vw[TOK * 128];    // TRANSPOSED per window: [win][d=128][k=2048]
__device__ float g_attn[TOK * 128];
__device__ float g_msg[TOK * 128];
__device__ float g_hidden[(size_t)TOK * 1024];

__device__ __forceinline__ unsigned f2tf(float f) {
    unsigned u;
    asm("cvt.rna.tf32.f32 %0, %1;" : "=r"(u) : "f"(f));
    return u;
}

__device__ __forceinline__ void mma8(float* c, unsigned a0, unsigned a1,
                                     unsigned a2, unsigned a3,
                                     unsigned b0, unsigned b1) {
    asm volatile(
        "mma.sync.aligned.m16n8k8.row.col.f32.tf32.tf32.f32 "
        "{%0,%1,%2,%3},{%4,%5,%6,%7},{%8,%9},{%0,%1,%2,%3};"
        : "+f"(c[0]), "+f"(c[1]), "+f"(c[2]), "+f"(c[3])
        : "r"(a0), "r"(a1), "r"(a2), "r"(a3), "r"(b0), "r"(b1));
}

__device__ __forceinline__ int win_src_row(int gr) {
    int b = gr >> 13, rem = gr & 8191;
    int w4 = rem >> 11, p = rem & 2047;
    int wi = w4 >> 1, wj = w4 & 1;
    int iy = p >> 6, ix = p & 63;
    int y = (wi * 32 + iy + 16) & 63;
    int x = (wj * 64 + ix + 32) & 127;
    return (b << 13) + (y << 7) + x;
}

// ---------------- K1: QKV projection + window gather. grid(512,3) x 256 ----
__global__ void k_qkv(const float* __restrict__ src, const float* __restrict__ tgt,
                      const float* __restrict__ Wq, const float* __restrict__ Wk,
                      const float* __restrict__ Wv) {
    extern __shared__ unsigned sm[];
    unsigned* As = sm;               // [64][132]
    unsigned* Ws = sm + 64 * 132;    // [128][132] (n,k)

    const int tid = threadIdx.x, tile = blockIdx.x;
    const float* inp  = (blockIdx.y == 0) ? src : tgt;
    const float* Wsel = (blockIdx.y == 0) ? Wq : (blockIdx.y == 1) ? Wk : Wv;

    for (int i = tid; i < 64 * 128; i += 256) {
        int r = i >> 7, c = i & 127;
        As[r * 132 + c] = f2tf(inp[(size_t)win_src_row(tile * 64 + r) * 128 + c]);
    }
    for (int i = tid; i < 128 * 128; i += 256) {
        int k = i >> 7, n = i & 127;
        Ws[n * 132 + k] = f2tf(Wsel[i]);
    }
    __syncthreads();

    const int warp = tid >> 5, lane = tid & 31, g = lane >> 2, t4 = lane & 3;
    const int rb = (warp >> 1) * 16, cb = (warp & 1) * 64;
    float acc[8][4];
#pragma unroll
    for (int nt = 0; nt < 8; nt++) acc[nt][0] = acc[nt][1] = acc[nt][2] = acc[nt][3] = 0.f;

#pragma unroll
    for (int k0 = 0; k0 < 128; k0 += 8) {
        unsigned a0 = As[(rb + g) * 132 + k0 + t4];
        unsigned a1 = As[(rb + g + 8) * 132 + k0 + t4];
        unsigned a2 = As[(rb + g) * 132 + k0 + t4 + 4];
        unsigned a3 = As[(rb + g + 8) * 132 + k0 + t4 + 4];
#pragma unroll
        for (int nt = 0; nt < 8; nt++) {
            unsigned b0 = Ws[(cb + nt * 8 + g) * 132 + k0 + t4];
            unsigned b1 = Ws[(cb + nt * 8 + g) * 132 + k0 + t4 + 4];
            mma8(acc[nt], a0, a1, a2, a3, b0, b1);
        }
    }

    if (blockIdx.y == 2) {
        // V: write transposed per-window [d][k]
        int winw = (tile * 64) >> 11;
        int kk0 = (tile * 64 + rb + g) & 2047;
        float* Vt = g_Vw + (size_t)winw * 262144;
#pragma unroll
        for (int nt = 0; nt < 8; nt++) {
            int c = cb + nt * 8 + 2 * t4;
            Vt[(size_t)c * 2048 + kk0]           = acc[nt][0];
            Vt[(size_t)(c + 1) * 2048 + kk0]     = acc[nt][1];
            Vt[(size_t)c * 2048 + kk0 + 8]       = acc[nt][2];
            Vt[(size_t)(c + 1) * 2048 + kk0 + 8] = acc[nt][3];
        }
    } else {
        float* out = (blockIdx.y == 0) ? g_Qw : g_Kw;
        int row0 = tile * 64 + rb + g, row1 = row0 + 8;
#pragma unroll
        for (int nt = 0; nt < 8; nt++) {
            int c = cb + nt * 8 + 2 * t4;
            *(float2*)&out[(size_t)row0 * 128 + c] = make_float2(acc[nt][0], acc[nt][1]);
            *(float2*)&out[(size_t)row1 * 128 + c] = make_float2(acc[nt][2], acc[nt][3]);
        }
    }
}

// ---------------- K2: flash attention. grid(16,16) x 512 -------------------
// q-tile 128, k-tile 64, 16 warps. Warp pair (rg, nh): rows rg*16..+15;
// nh selects S-cols [nh*32,+32) and PV d-cols [nh*64,+64).
__global__ __launch_bounds__(512) void k_attn(const float* __restrict__ mask) {
    extern __shared__ unsigned sm[];
    unsigned* Qs  = sm;                       // [128][132]
    unsigned* Ks  = Qs + 128 * 132;           // [64][132]
    unsigned* Vs  = Ks + 64 * 132;            // [128][68] (d,k)
    unsigned* Ps  = Vs + 128 * 68;            // [128][68]
    float*    Msf = (float*)(Ps + 128 * 68);  // [128][68]
    float*    Rmx = Msf + 128 * 68;           // [128][2]
    float*    Rsm = Rmx + 256;                // [128][2]

    const int tid = threadIdx.x, warp = tid >> 5, lane = tid & 31;
    const int g = lane >> 2, t4 = lane & 3;
    const int qw = (warp >> 1) * 16, nh = warp & 1;
    const int qbase = blockIdx.x * 128, win = blockIdx.y, w4 = win & 3;

    const float* Qg = g_Qw + ((size_t)(win * LL + qbase)) * 128;
    for (int i = tid; i < 128 * 128; i += 512) {
        int r = i >> 7, c = i & 127;
        Qs[r * 132 + c] = f2tf(Qg[i]);
    }
    const float* Mrow = mask + (size_t)w4 * LL * LL + (size_t)qbase * LL;
    const float* Vt   = g_Vw + (size_t)win * 262144;

    float o[8][4];
#pragma unroll
    for (int dt = 0; dt < 8; dt++) o[dt][0] = o[dt][1] = o[dt][2] = o[dt][3] = 0.f;
    float m0 = -1e30f, m1 = -1e30f, l0 = 0.f, l1 = 0.f;

    for (int kt = 0; kt < 32; kt++) {
        const int kbase = kt * 64;
        const float* Kg = g_Kw + ((size_t)(win * LL + kbase)) * 128;

        __syncthreads();
        for (int i = tid; i < 64 * 128; i += 512) {
            int r = i >> 7, c = i & 127;
            Ks[r * 132 + c] = f2tf(Kg[i]);
        }
        for (int i = tid; i < 128 * 64; i += 512) {
            int d = i >> 6, k = i & 63;
            Vs[d * 68 + k] = f2tf(Vt[(size_t)d * 2048 + kbase + k]);
        }
        for (int i = tid; i < 128 * 64; i += 512) {
            int r = i >> 6, c = i & 63;
            Msf[r * 68 + c] = Mrow[(size_t)r * LL + kbase + c];
        }
        __syncthreads();

        // ---- S = Q K^T (warp: 16 rows x 32 cols) ----
        float s[4][4];
#pragma unroll
        for (int nt = 0; nt < 4; nt++) s[nt][0] = s[nt][1] = s[nt][2] = s[nt][3] = 0.f;
#pragma unroll
        for (int d0 = 0; d0 < 128; d0 += 8) {
            unsigned a0 = Qs[(qw + g) * 132 + d0 + t4];
            unsigned a1 = Qs[(qw + g + 8) * 132 + d0 + t4];
            unsigned a2 = Qs[(qw + g) * 132 + d0 + t4 + 4];
            unsigned a3 = Qs[(qw + g + 8) * 132 + d0 + t4 + 4];
#pragma unroll
            for (int nt = 0; nt < 4; nt++) {
                unsigned b0 = Ks[(nh * 32 + nt * 8 + g) * 132 + d0 + t4];
                unsigned b1 = Ks[(nh * 32 + nt * 8 + g) * 132 + d0 + t4 + 4];
                mma8(s[nt], a0, a1, a2, a3, b0, b1);
            }
        }

        // ---- scale + mask + local row max over this warp's 32 cols ----
        float ml0 = -1e30f, ml1 = -1e30f;
#pragma unroll
        for (int nt = 0; nt < 4; nt++) {
            int col = nh * 32 + nt * 8 + 2 * t4;
            float2 mA = *(float2*)&Msf[(qw + g) * 68 + col];
            float2 mB = *(float2*)&Msf[(qw + g + 8) * 68 + col];
            s[nt][0] = s[nt][0] * ATT_SCALE + mA.x;
            s[nt][1] = s[nt][1] * ATT_SCALE + mA.y;
            s[nt][2] = s[nt][2] * ATT_SCALE + mB.x;
            s[nt][3] = s[nt][3] * ATT_SCALE + mB.y;
            ml0 = fmaxf(ml0, fmaxf(s[nt][0], s[nt][1]));
            ml1 = fmaxf(ml1, fmaxf(s[nt][2], s[nt][3]));
        }
        ml0 = fmaxf(ml0, __shfl_xor_sync(~0u, ml0, 1));
        ml0 = fmaxf(ml0, __shfl_xor_sync(~0u, ml0, 2));
        ml1 = fmaxf(ml1, __shfl_xor_sync(~0u, ml1, 1));
        ml1 = fmaxf(ml1, __shfl_xor_sync(~0u, ml1, 2));
        if (t4 == 0) {
            Rmx[(qw + g) * 2 + nh]     = ml0;
            Rmx[(qw + g + 8) * 2 + nh] = ml1;
        }
        __syncthreads();
        float gm0 = fmaxf(Rmx[(qw + g) * 2],     Rmx[(qw + g) * 2 + 1]);
        float gm1 = fmaxf(Rmx[(qw + g + 8) * 2], Rmx[(qw + g + 8) * 2 + 1]);

        float mn0 = fmaxf(m0, gm0), mn1 = fmaxf(m1, gm1);
        float al0 = __expf(m0 - mn0), al1 = __expf(m1 - mn1);
        m0 = mn0; m1 = mn1;

        // ---- exp + P store + partial row sums ----
        float rs0 = 0.f, rs1 = 0.f;
#pragma unroll
        for (int nt = 0; nt < 4; nt++) {
            int col = nh * 32 + nt * 8 + 2 * t4;
            float p0 = __expf(s[nt][0] - mn0);
            float p1 = __expf(s[nt][1] - mn0);
            float p2 = __expf(s[nt][2] - mn1);
            float p3 = __expf(s[nt][3] - mn1);
            rs0 += p0 + p1; rs1 += p2 + p3;
            Ps[(qw + g) * 68 + col]         = f2tf(p0);
            Ps[(qw + g) * 68 + col + 1]     = f2tf(p1);
            Ps[(qw + g + 8) * 68 + col]     = f2tf(p2);
            Ps[(qw + g + 8) * 68 + col + 1] = f2tf(p3);
        }
        rs0 += __shfl_xor_sync(~0u, rs0, 1);
        rs0 += __shfl_xor_sync(~0u, rs0, 2);
        rs1 += __shfl_xor_sync(~0u, rs1, 1);
        rs1 += __shfl_xor_sync(~0u, rs1, 2);
        if (t4 == 0) {
            Rsm[(qw + g) * 2 + nh]     = rs0;
            Rsm[(qw + g + 8) * 2 + nh] = rs1;
        }

        // rescale O while sums/P land
#pragma unroll
        for (int dt = 0; dt < 8; dt++) {
            o[dt][0] *= al0; o[dt][1] *= al0;
            o[dt][2] *= al1; o[dt][3] *= al1;
        }
        __syncthreads();
        l0 = l0 * al0 + Rsm[(qw + g) * 2]     + Rsm[(qw + g) * 2 + 1];
        l1 = l1 * al1 + Rsm[(qw + g + 8) * 2] + Rsm[(qw + g + 8) * 2 + 1];

        // ---- O += P V  (warp: 16 rows x 64 d-cols) ----
#pragma unroll
        for (int k0 = 0; k0 < 64; k0 += 8) {
            unsigned a0 = Ps[(qw + g) * 68 + k0 + t4];
            unsigned a1 = Ps[(qw + g + 8) * 68 + k0 + t4];
            unsigned a2 = Ps[(qw + g) * 68 + k0 + t4 + 4];
            unsigned a3 = Ps[(qw + g + 8) * 68 + k0 + t4 + 4];
#pragma unroll
            for (int dt = 0; dt < 8; dt++) {
                unsigned b0 = Vs[(nh * 64 + dt * 8 + g) * 68 + k0 + t4];
                unsigned b1 = Vs[(nh * 64 + dt * 8 + g) * 68 + k0 + t4 + 4];
                mma8(o[dt], a0, a1, a2, a3, b0, b1);
            }
        }
    }

    float i0 = 1.f / l0, i1 = 1.f / l1;
    int row0 = win_src_row(win * LL + qbase + qw + g);
    int row1 = win_src_row(win * LL + qbase + qw + g + 8);
#pragma unroll
    for (int dt = 0; dt < 8; dt++) {
        int c = nh * 64 + dt * 8 + 2 * t4;
        *(float2*)&g_attn[(size_t)row0 * 128 + c] = make_float2(o[dt][0] * i0, o[dt][1] * i0);
        *(float2*)&g_attn[(size_t)row1 * 128 + c] = make_float2(o[dt][2] * i1, o[dt][3] * i1);
    }
}

// ---------------- K3: message = LN(attn @ Wm). grid 512 x 256 --------------
__global__ void k_wm_ln(const float* __restrict__ Wm, const float* __restrict__ g1,
                        const float* __restrict__ b1) {
    extern __shared__ unsigned sm[];
    unsigned* As = sm;                        // [64][132]
    unsigned* Ws = sm + 64 * 132;             // [128][132]
    float*    Rs = (float*)(Ws + 128 * 132);  // [64][132]

    const int tid = threadIdx.x, tile = blockIdx.x;
    for (int i = tid; i < 64 * 128; i += 256) {
        int r = i >> 7, c = i & 127;
        As[r * 132 + c] = f2tf(g_attn[(size_t)(tile * 64 + r) * 128 + c]);
    }
    for (int i = tid; i < 128 * 128; i += 256) {
        int k = i >> 7, n = i & 127;
        Ws[n * 132 + k] = f2tf(Wm[i]);
    }
    __syncthreads();

    const int warp = tid >> 5, lane = tid & 31, g = lane >> 2, t4 = lane & 3;
    const int rb = (warp >> 1) * 16, cb = (warp & 1) * 64;
    float acc[8][4];
#pragma unroll
    for (int nt = 0; nt < 8; nt++) acc[nt][0] = acc[nt][1] = acc[nt][2] = acc[nt][3] = 0.f;
#pragma unroll
    for (int k0 = 0; k0 < 128; k0 += 8) {
        unsigned a0 = As[(rb + g) * 132 + k0 + t4];
        unsigned a1 = As[(rb + g + 8) * 132 + k0 + t4];
        unsigned a2 = As[(rb + g) * 132 + k0 + t4 + 4];
        unsigned a3 = As[(rb + g + 8) * 132 + k0 + t4 + 4];
#pragma unroll
        for (int nt = 0; nt < 8; nt++) {
            unsigned b0 = Ws[(cb + nt * 8 + g) * 132 + k0 + t4];
            unsigned b1 = Ws[(cb + nt * 8 + g) * 132 + k0 + t4 + 4];
            mma8(acc[nt], a0, a1, a2, a3, b0, b1);
        }
    }
#pragma unroll
    for (int nt = 0; nt < 8; nt++) {
        int c = cb + nt * 8 + 2 * t4;
        Rs[(rb + g) * 132 + c]         = acc[nt][0];
        Rs[(rb + g) * 132 + c + 1]     = acc[nt][1];
        Rs[(rb + g + 8) * 132 + c]     = acc[nt][2];
        Rs[(rb + g + 8) * 132 + c + 1] = acc[nt][3];
    }
    __syncthreads();

    int row = tid >> 2, l4 = tid & 3;
    float sum = 0.f, sq = 0.f;
    for (int c = l4; c < 128; c += 4) {
        float v = Rs[row * 132 + c];
        sum += v; sq += v * v;
    }
    sum += __shfl_xor_sync(~0u, sum, 1); sum += __shfl_xor_sync(~0u, sum, 2);
    sq  += __shfl_xor_sync(~0u, sq, 1);  sq  += __shfl_xor_sync(~0u, sq, 2);
    float mean = sum * 0.0078125f;
    float rstd = rsqrtf(sq * 0.0078125f - mean * mean + 1e-5f);
    for (int c = l4; c < 128; c += 4) {
        g_msg[(size_t)(tile * 64 + row) * 128 + c] =
            (Rs[row * 132 + c] - mean) * rstd * g1[c] + b1[c];
    }
}

// ---------------- K4: hidden = gelu([src|msg] @ W1). grid(256,4) x 512 -----
// tile 128 x 256, warp 32x64 (4x4 warps), B stored [k][n] stride 264.
__global__ __launch_bounds__(512) void k_mlp1(const float* __restrict__ src,
                                              const float* __restrict__ W1) {
    extern __shared__ unsigned sm[];
    unsigned* As = sm;             // [128][68] (m,k)
    unsigned* Bs = sm + 128 * 68;  // [64][264] (k,n)

    const int tid = threadIdx.x, tile = blockIdx.x, nb = blockIdx.y * 256;
    const int warp = tid >> 5, lane = tid & 31, g = lane >> 2, t4 = lane & 3;
    const int rb = (warp >> 2) * 32, cb = (warp & 3) * 64;

    float acc[2][8][4];
#pragma unroll
    for (int mt = 0; mt < 2; mt++)
#pragma unroll
        for (int nt = 0; nt < 8; nt++)
            acc[mt][nt][0] = acc[mt][nt][1] = acc[mt][nt][2] = acc[mt][nt][3] = 0.f;

    for (int kc = 0; kc < 256; kc += 64) {
        __syncthreads();
        const float* aptr = (kc < 128) ? src : g_msg;
        const int koff = kc & 127;
        for (int i = tid; i < 128 * 64; i += 512) {
            int r = i >> 6, k = i & 63;
            As[r * 68 + k] = f2tf(aptr[(size_t)(tile * 128 + r) * 128 + koff + k]);
        }
        for (int i = tid; i < 64 * 256; i += 512) {
            int k = i >> 8, n = i & 255;
            Bs[k * 264 + n] = f2tf(W1[(size_t)(kc + k) * 1024 + nb + n]);
        }
        __syncthreads();
#pragma unroll
        for (int k0 = 0; k0 < 64; k0 += 8) {
            unsigned a00 = As[(rb + g) * 68 + k0 + t4];
            unsigned a01 = As[(rb + g + 8) * 68 + k0 + t4];
            unsigned a02 = As[(rb + g) * 68 + k0 + t4 + 4];
            unsigned a03 = As[(rb + g + 8) * 68 + k0 + t4 + 4];
            unsigned a10 = As[(rb + 16 + g) * 68 + k0 + t4];
            unsigned a11 = As[(rb + 24 + g) * 68 + k0 + t4];
            unsigned a12 = As[(rb + 16 + g) * 68 + k0 + t4 + 4];
            unsigned a13 = As[(rb + 24 + g) * 68 + k0 + t4 + 4];
#pragma unroll
            for (int nt = 0; nt < 8; nt++) {
                unsigned b0 = Bs[(k0 + t4) * 264 + cb + nt * 8 + g];
                unsigned b1 = Bs[(k0 + t4 + 4) * 264 + cb + nt * 8 + g];
                mma8(acc[0][nt], a00, a01, a02, a03, b0, b1);
                mma8(acc[1][nt], a10, a11, a12, a13, b0, b1);
            }
        }
    }

#pragma unroll
    for (int mt = 0; mt < 2; mt++) {
        int row0 = tile * 128 + rb + mt * 16 + g, row1 = row0 + 8;
#pragma unroll
        for (int nt = 0; nt < 8; nt++) {
            int c = nb + cb + nt * 8 + 2 * t4;
            float x0 = acc[mt][nt][0], x1 = acc[mt][nt][1];
            float x2 = acc[mt][nt][2], x3 = acc[mt][nt][3];
            x0 = 0.5f * x0 * (1.f + erff(x0 * 0.70710678f));
            x1 = 0.5f * x1 * (1.f + erff(x1 * 0.70710678f));
            x2 = 0.5f * x2 * (1.f + erff(x2 * 0.70710678f));
            x3 = 0.5f * x3 * (1.f + erff(x3 * 0.70710678f));
            *(float2*)&g_hidden[(size_t)row0 * 1024 + c] = make_float2(x0, x1);
            *(float2*)&g_hidden[(size_t)row1 * 1024 + c] = make_float2(x2, x3);
        }
    }
}

// ---------------- K5: out = src + LN(hidden @ W2). grid 256 x 512 ----------
// tile 128 x 128, warp 32x32, B [k][n] stride 136. Rs aliases As/Bs.
__global__ __launch_bounds__(512, 2) void k_mlp2(const float* __restrict__ src,
                                                 const float* __restrict__ W2,
                                                 const float* __restrict__ g2,
                                                 const float* __restrict__ b2,
                                                 float* __restrict__ out) {
    extern __shared__ unsigned sm[];
    unsigned* As = sm;             // [128][68]
    unsigned* Bs = sm + 128 * 68;  // [64][136]
    float*    Rs = (float*)sm;     // [128][132] (aliased after mma)

    const int tid = threadIdx.x, tile = blockIdx.x;
    const int warp = tid >> 5, lane = tid & 31, g = lane >> 2, t4 = lane & 3;
    const int rb = (warp >> 2) * 32, cb = (warp & 3) * 32;

    float acc[2][4][4];
#pragma unroll
    for (int mt = 0; mt < 2; mt++)
#pragma unroll
        for (int nt = 0; nt < 4; nt++)
            acc[mt][nt][0] = acc[mt][nt][1] = acc[mt][nt][2] = acc[mt][nt][3] = 0.f;

    for (int kc = 0; kc < 1024; kc += 64) {
        __syncthreads();
        for (int i = tid; i < 128 * 64; i += 512) {
            int r = i >> 6, k = i & 63;
            As[r * 68 + k] = f2tf(g_hidden[(size_t)(tile * 128 + r) * 1024 + kc + k]);
        }
        for (int i = tid; i < 64 * 128; i += 512) {
            int k = i >> 7, n = i & 127;
            Bs[k * 136 + n] = f2tf(W2[(size_t)(kc + k) * 128 + n]);
        }
        __syncthreads();
#pragma unroll
        for (int k0 = 0; k0 < 64; k0 += 8) {
            unsigned a00 = As[(rb + g) * 68 + k0 + t4];
            unsigned a01 = As[(rb + g + 8) * 68 + k0 + t4];
            unsigned a02 = As[(rb + g) * 68 + k0 + t4 + 4];
            unsigned a03 = As[(rb + g + 8) * 68 + k0 + t4 + 4];
            unsigned a10 = As[(rb + 16 + g) * 68 + k0 + t4];
            unsigned a11 = As[(rb + 24 + g) * 68 + k0 + t4];
            unsigned a12 = As[(rb + 16 + g) * 68 + k0 + t4 + 4];
            unsigned a13 = As[(rb + 24 + g) * 68 + k0 + t4 + 4];
#pragma unroll
            for (int nt = 0; nt < 4; nt++) {
                unsigned b0 = Bs[(k0 + t4) * 136 + cb + nt * 8 + g];
                unsigned b1 = Bs[(k0 + t4 + 4) * 136 + cb + nt * 8 + g];
                mma8(acc[0][nt], a00, a01, a02, a03, b0, b1);
                mma8(acc[1][nt], a10, a11, a12, a13, b0, b1);
            }
        }
    }

    __syncthreads();   // done reading As/Bs; safe to alias as Rs
#pragma unroll
    for (int mt = 0; mt < 2; mt++) {
        int r0 = rb + mt * 16 + g;
#pragma unroll
        for (int nt = 0; nt < 4; nt++) {
            int c = cb + nt * 8 + 2 * t4;
            Rs[r0 * 132 + c]           = acc[mt][nt][0];
            Rs[r0 * 132 + c + 1]       = acc[mt][nt][1];
            Rs[(r0 + 8) * 132 + c]     = acc[mt][nt][2];
            Rs[(r0 + 8) * 132 + c + 1] = acc[mt][nt][3];
        }
    }
    __syncthreads();

    int row = tid >> 2, l4 = tid & 3;
    float sum = 0.f, sq = 0.f;
    for (int c = l4; c < 128; c += 4) {
        float v = Rs[row * 132 + c];
        sum += v; sq += v * v;
    }
    sum += __shfl_xor_sync(~0u, sum, 1); sum += __shfl_xor_sync(~0u, sum, 2);
    sq  += __shfl_xor_sync(~0u, sq, 1);  sq  += __shfl_xor_sync(~0u, sq, 2);
    float mean = sum * 0.0078125f;
    float rstd = rsqrtf(sq * 0.0078125f - mean * mean + 1e-5f);
    size_t grow = (size_t)(tile * 128 + row) * 128;
    for (int c = l4; c < 128; c += 4) {
        out[grow + c] = src[grow + c] + (Rs[row * 132 + c] - mean) * rstd * g2[c] + b2[c];
    }
}

extern "C" void kernel_launch(void* const* d_in, const int* in_sizes, int n_in,
                              void* d_out, int out_size) {
    (void)in_sizes; (void)n_in; (void)out_size;
    const float* src  = (const float*)d_in[0];
    const float* tgt  = (const float*)d_in[1];
    const float* mask = (const float*)d_in[2];
    const float* Wq   = (const float*)d_in[8];
    const float* Wk   = (const float*)d_in[9];
    const float* Wv   = (const float*)d_in[10];
    const float* Wm   = (const float*)d_in[11];
    const float* g1   = (const float*)d_in[12];
    const float* b1   = (const float*)d_in[13];
    const float* W1   = (const float*)d_in[14];
    const float* W2   = (const float*)d_in[15];
    const float* g2   = (const float*)d_in[16];
    const float* b2   = (const float*)d_in[17];
    float* out = (float*)d_out;

    const int SM1 = (64 * 132 + 128 * 132) * 4;                         // 101376
    const int SM2 = (128 * 132 + 64 * 132 + 3 * 128 * 68 + 512) * 4;    // 207872
    const int SM3 = (64 * 132 + 128 * 132 + 64 * 132) * 4;              // 135168
    const int SM4 = (128 * 68 + 64 * 264) * 4;                          // 102400
    const int SM5 = (128 * 68 + 64 * 136) * 4;                          // 69632

    static int configured = 0;
    if (!configured) {
        cudaFuncSetAttribute(k_qkv,   cudaFuncAttributeMaxDynamicSharedMemorySize, SM1);
        cudaFuncSetAttribute(k_attn,  cudaFuncAttributeMaxDynamicSharedMemorySize, SM2);
        cudaFuncSetAttribute(k_wm_ln, cudaFuncAttributeMaxDynamicSharedMemorySize, SM3);
        cudaFuncSetAttribute(k_mlp1,  cudaFuncAttributeMaxDynamicSharedMemorySize, SM4);
        cudaFuncSetAttribute(k_mlp2,  cudaFuncAttributeMaxDynamicSharedMemorySize, SM5);
        configured = 1;
    }

    k_qkv  <<<dim3(512, 3), 256, SM1>>>(src, tgt, Wq, Wk, Wv);
    k_attn <<<dim3(16, 16), 512, SM2>>>(mask);
    k_wm_ln<<<512,          256, SM3>>>(Wm, g1, b1);
    k_mlp1 <<<dim3(256, 4), 512, SM4>>>(src, W1);
    k_mlp2 <<<256,          512, SM5>>>(src, W2, g2, b2, out);
}

// round 5
// speedup vs baseline: 1.9637x; 1.6745x over previous
#include <cuda_runtime.h>
#include <math.h>

#define TOK   32768
#define LL    2048
#define ATT_SCALE 0.08838834764831845f

// All GEMM operands stored PRE-ROUNDED to tf32 (fp32-representable) so
// consumers cp.async raw bits and feed mma directly — bit-identical to
// cvt-at-load.
__device__ float g_Qw[TOK * 128];
__device__ float g_Kw[TOK * 128];
__device__ float g_Vw[TOK * 128];    // transposed per window: [win][d=128][k=2048]
__device__ float g_attn[TOK * 128];  // fp32 (consumer cvts)
__device__ float g_cat[(size_t)TOK * 256];    // [src_tf32 | msg_tf32]
__device__ float g_hidden[(size_t)TOK * 1024];
__device__ float g_W1t[256 * 1024];
__device__ float g_W2t[1024 * 128];

__device__ __forceinline__ unsigned f2tf(float f) {
    unsigned u;
    asm("cvt.rna.tf32.f32 %0, %1;" : "=r"(u) : "f"(f));
    return u;
}
__device__ __forceinline__ float tf32r(float f) { return __uint_as_float(f2tf(f)); }

__device__ __forceinline__ void mma8(float* c, unsigned a0, unsigned a1,
                                     unsigned a2, unsigned a3,
                                     unsigned b0, unsigned b1) {
    asm volatile(
        "mma.sync.aligned.m16n8k8.row.col.f32.tf32.tf32.f32 "
        "{%0,%1,%2,%3},{%4,%5,%6,%7},{%8,%9},{%0,%1,%2,%3};"
        : "+f"(c[0]), "+f"(c[1]), "+f"(c[2]), "+f"(c[3])
        : "r"(a0), "r"(a1), "r"(a2), "r"(a3), "r"(b0), "r"(b1));
}

__device__ __forceinline__ void cpa16(unsigned* dst_smem, const float* src) {
    unsigned a = (unsigned)__cvta_generic_to_shared(dst_smem);
    asm volatile("cp.async.cg.shared.global [%0], [%1], 16;\n" :: "r"(a), "l"(src));
}
__device__ __forceinline__ void cp_commit() { asm volatile("cp.async.commit_group;\n"); }
__device__ __forceinline__ void cp_wait1()  { asm volatile("cp.async.wait_group 1;\n"); }
__device__ __forceinline__ void cp_wait2()  { asm volatile("cp.async.wait_group 2;\n"); }

__device__ __forceinline__ int win_src_row(int gr) {
    int b = gr >> 13, rem = gr & 8191;
    int w4 = rem >> 11, p = rem & 2047;
    int wi = w4 >> 1, wj = w4 & 1;
    int iy = p >> 6, ix = p & 63;
    int y = (wi * 32 + iy + 16) & 63;
    int x = (wj * 64 + ix + 32) & 127;
    return (b << 13) + (y << 7) + x;
}

// ---------------- K0: round src / W1 / W2 to tf32 scratch ------------------
#define SRC_N  4194304
#define W1_N   262144
#define W2_N   131072
__global__ void k_prep(const float* __restrict__ src, const float* __restrict__ W1,
                       const float* __restrict__ W2) {
    int i = blockIdx.x * 512 + threadIdx.x;
    if (i < SRC_N) {
        int r = i >> 7, c = i & 127;
        g_cat[(size_t)r * 256 + c] = tf32r(src[i]);
    } else if (i < SRC_N + W1_N) {
        int j = i - SRC_N;
        g_W1t[j] = tf32r(W1[j]);
    } else if (i < SRC_N + W1_N + W2_N) {
        int j = i - SRC_N - W1_N;
        g_W2t[j] = tf32r(W2[j]);
    }
}

// ---------------- K1: QKV projection + window gather. grid(512,3) x 256 ----
__global__ void k_qkv(const float* __restrict__ src, const float* __restrict__ tgt,
                      const float* __restrict__ Wq, const float* __restrict__ Wk,
                      const float* __restrict__ Wv) {
    extern __shared__ unsigned sm[];
    unsigned* As = sm;               // [64][132]
    unsigned* Ws = sm + 64 * 132;    // [128][132] (n,k)

    const int tid = threadIdx.x, tile = blockIdx.x;
    const float* inp  = (blockIdx.y == 0) ? src : tgt;
    const float* Wsel = (blockIdx.y == 0) ? Wq : (blockIdx.y == 1) ? Wk : Wv;

    for (int i = tid; i < 64 * 128; i += 256) {
        int r = i >> 7, c = i & 127;
        As[r * 132 + c] = f2tf(inp[(size_t)win_src_row(tile * 64 + r) * 128 + c]);
    }
    for (int i = tid; i < 128 * 128; i += 256) {
        int k = i >> 7, n = i & 127;
        Ws[n * 132 + k] = f2tf(Wsel[i]);
    }
    __syncthreads();

    const int warp = tid >> 5, lane = tid & 31, g = lane >> 2, t4 = lane & 3;
    const int rb = (warp >> 1) * 16, cb = (warp & 1) * 64;
    float acc[8][4];
#pragma unroll
    for (int nt = 0; nt < 8; nt++) acc[nt][0] = acc[nt][1] = acc[nt][2] = acc[nt][3] = 0.f;

#pragma unroll
    for (int k0 = 0; k0 < 128; k0 += 8) {
        unsigned a0 = As[(rb + g) * 132 + k0 + t4];
        unsigned a1 = As[(rb + g + 8) * 132 + k0 + t4];
        unsigned a2 = As[(rb + g) * 132 + k0 + t4 + 4];
        unsigned a3 = As[(rb + g + 8) * 132 + k0 + t4 + 4];
#pragma unroll
        for (int nt = 0; nt < 8; nt++) {
            unsigned b0 = Ws[(cb + nt * 8 + g) * 132 + k0 + t4];
            unsigned b1 = Ws[(cb + nt * 8 + g) * 132 + k0 + t4 + 4];
            mma8(acc[nt], a0, a1, a2, a3, b0, b1);
        }
    }

    if (blockIdx.y == 2) {
        int winw = (tile * 64) >> 11;
        int kk0 = (tile * 64 + rb + g) & 2047;
        float* Vt = g_Vw + (size_t)winw * 262144;
#pragma unroll
        for (int nt = 0; nt < 8; nt++) {
            int c = cb + nt * 8 + 2 * t4;
            Vt[(size_t)c * 2048 + kk0]           = tf32r(acc[nt][0]);
            Vt[(size_t)(c + 1) * 2048 + kk0]     = tf32r(acc[nt][1]);
            Vt[(size_t)c * 2048 + kk0 + 8]       = tf32r(acc[nt][2]);
            Vt[(size_t)(c + 1) * 2048 + kk0 + 8] = tf32r(acc[nt][3]);
        }
    } else {
        float* out = (blockIdx.y == 0) ? g_Qw : g_Kw;
        int row0 = tile * 64 + rb + g, row1 = row0 + 8;
#pragma unroll
        for (int nt = 0; nt < 8; nt++) {
            int c = cb + nt * 8 + 2 * t4;
            *(float2*)&out[(size_t)row0 * 128 + c] =
                make_float2(tf32r(acc[nt][0]), tf32r(acc[nt][1]));
            *(float2*)&out[(size_t)row1 * 128 + c] =
                make_float2(tf32r(acc[nt][2]), tf32r(acc[nt][3]));
        }
    }
}

// ---------------- K2: flash attention. grid(16,16) x 512 -------------------
// K double-buffered via cp.async (prefetch kt+1), V single-buffered in its
// own commit group (load overlaps S+softmax), mask -> registers via __ldg,
// P through [128][68] smem (full 64 cols, correctly sized).
#define QS_W 16896   // 128*132
#define KS_W 8448    // 64*132
#define VS_W 8704    // 128*68
#define PS_W 8704    // 128*68
__global__ __launch_bounds__(512, 1) void k_attn(const float* __restrict__ mask) {
    extern __shared__ unsigned sm[];
    unsigned* Qs  = sm;                        // [128][132]
    unsigned* Kst = sm + QS_W;                 // 2 x [64][132]
    unsigned* Vs  = Kst + 2 * KS_W;            // [128][68]
    unsigned* Ps  = Vs + VS_W;                 // [128][68]
    float*    Rmx = (float*)(Ps + PS_W);       // [128][2]
    float*    Rsm = Rmx + 256;                 // [128][2]

    const int tid = threadIdx.x, warp = tid >> 5, lane = tid & 31;
    const int g = lane >> 2, t4 = lane & 3;
    const int qw = (warp >> 1) * 16, nh = warp & 1;
    const int qbase = blockIdx.x * 128, win = blockIdx.y, w4 = win & 3;

    const float* Qg   = g_Qw + ((size_t)(win * LL + qbase)) * 128;
    const float* Kgb  = g_Kw + ((size_t)(win * LL)) * 128;
    const float* Vt   = g_Vw + (size_t)win * 262144;
    const float* Mrow = mask + (size_t)w4 * LL * LL + (size_t)qbase * LL;

    // prologue: Q + K stage 0 (one group)
    for (int i = tid; i < 4096; i += 512) {
        int r = i >> 5, q = i & 31;
        cpa16(Qs + r * 132 + q * 4, Qg + r * 128 + q * 4);
    }
    for (int i = tid; i < 2048; i += 512) {
        int r = i >> 5, q = i & 31;
        cpa16(Kst + r * 132 + q * 4, Kgb + r * 128 + q * 4);
    }
    cp_commit();

    float o[8][4];
#pragma unroll
    for (int dt = 0; dt < 8; dt++) o[dt][0] = o[dt][1] = o[dt][2] = o[dt][3] = 0.f;
    float m0 = -1e30f, m1 = -1e30f, l0 = 0.f, l1 = 0.f;

    for (int kt = 0; kt < 32; kt++) {
        const int st = kt & 1;
        const int kbase = kt * 64;

        if (kt > 0) __syncthreads();   // B0: prev PV readers of Vs/Ps done
        // V(kt) into Vs — own group
        for (int i = tid; i < 2048; i += 512) {
            int d = i >> 4, q = i & 15;
            cpa16(Vs + d * 68 + q * 4, Vt + (size_t)d * 2048 + kbase + q * 4);
        }
        cp_commit();                                  // GV_kt
        // K(kt+1) prefetch — own group
        if (kt + 1 < 32) {
            const float* Kg = Kgb + (size_t)(kt + 1) * 64 * 128;
            unsigned* Kd = Kst + ((kt + 1) & 1) * KS_W;
            for (int i = tid; i < 2048; i += 512) {
                int r = i >> 5, q = i & 31;
                cpa16(Kd + r * 132 + q * 4, Kg + r * 128 + q * 4);
            }
        }
        cp_commit();                                  // GK_{kt+1}
        cp_wait2();                                   // K(kt) (and Q) arrived
        __syncthreads();                              // B1: publish K stage kt

        const unsigned* Ks = Kst + st * KS_W;

        // mask chunk -> registers
        float2 mr0[4], mr1[4];
#pragma unroll
        for (int nt = 0; nt < 4; nt++) {
            int col = nh * 32 + nt * 8 + 2 * t4;
            mr0[nt] = __ldg((const float2*)(Mrow + (size_t)(qw + g) * LL + kbase + col));
            mr1[nt] = __ldg((const float2*)(Mrow + (size_t)(qw + 8 + g) * LL + kbase + col));
        }

        // ---- S = Q K^T (warp: 16 rows x 32 cols) ----
        float s[4][4];
#pragma unroll
        for (int nt = 0; nt < 4; nt++) s[nt][0] = s[nt][1] = s[nt][2] = s[nt][3] = 0.f;
#pragma unroll
        for (int d0 = 0; d0 < 128; d0 += 8) {
            unsigned a0 = Qs[(qw + g) * 132 + d0 + t4];
            unsigned a1 = Qs[(qw + g + 8) * 132 + d0 + t4];
            unsigned a2 = Qs[(qw + g) * 132 + d0 + t4 + 4];
            unsigned a3 = Qs[(qw + g + 8) * 132 + d0 + t4 + 4];
#pragma unroll
            for (int nt = 0; nt < 4; nt++) {
                unsigned b0 = Ks[(nh * 32 + nt * 8 + g) * 132 + d0 + t4];
                unsigned b1 = Ks[(nh * 32 + nt * 8 + g) * 132 + d0 + t4 + 4];
                mma8(s[nt], a0, a1, a2, a3, b0, b1);
            }
        }

        // ---- scale + mask + row max ----
        float ml0 = -1e30f, ml1 = -1e30f;
#pragma unroll
        for (int nt = 0; nt < 4; nt++) {
            s[nt][0] = s[nt][0] * ATT_SCALE + mr0[nt].x;
            s[nt][1] = s[nt][1] * ATT_SCALE + mr0[nt].y;
            s[nt][2] = s[nt][2] * ATT_SCALE + mr1[nt].x;
            s[nt][3] = s[nt][3] * ATT_SCALE + mr1[nt].y;
            ml0 = fmaxf(ml0, fmaxf(s[nt][0], s[nt][1]));
            ml1 = fmaxf(ml1, fmaxf(s[nt][2], s[nt][3]));
        }
        ml0 = fmaxf(ml0, __shfl_xor_sync(~0u, ml0, 1));
        ml0 = fmaxf(ml0, __shfl_xor_sync(~0u, ml0, 2));
        ml1 = fmaxf(ml1, __shfl_xor_sync(~0u, ml1, 1));
        ml1 = fmaxf(ml1, __shfl_xor_sync(~0u, ml1, 2));
        if (t4 == 0) {
            Rmx[(qw + g) * 2 + nh]     = ml0;
            Rmx[(qw + g + 8) * 2 + nh] = ml1;
        }
        __syncthreads();                              // B2: publish Rmx
        float gm0 = fmaxf(Rmx[(qw + g) * 2],     Rmx[(qw + g) * 2 + 1]);
        float gm1 = fmaxf(Rmx[(qw + g + 8) * 2], Rmx[(qw + g + 8) * 2 + 1]);

        float mn0 = fmaxf(m0, gm0), mn1 = fmaxf(m1, gm1);
        float al0 = __expf(m0 - mn0), al1 = __expf(m1 - mn1);
        m0 = mn0; m1 = mn1;

        // ---- exp + partial sums + P store (correct stride 68) ----
        float rs0 = 0.f, rs1 = 0.f;
#pragma unroll
        for (int nt = 0; nt < 4; nt++) {
            int col = nh * 32 + nt * 8 + 2 * t4;
            float p0 = __expf(s[nt][0] - mn0);
            float p1 = __expf(s[nt][1] - mn0);
            float p2 = __expf(s[nt][2] - mn1);
            float p3 = __expf(s[nt][3] - mn1);
            rs0 += p0 + p1; rs1 += p2 + p3;
            Ps[(qw + g) * 68 + col]         = f2tf(p0);
            Ps[(qw + g) * 68 + col + 1]     = f2tf(p1);
            Ps[(qw + g + 8) * 68 + col]     = f2tf(p2);
            Ps[(qw + g + 8) * 68 + col + 1] = f2tf(p3);
        }
        rs0 += __shfl_xor_sync(~0u, rs0, 1);
        rs0 += __shfl_xor_sync(~0u, rs0, 2);
        rs1 += __shfl_xor_sync(~0u, rs1, 1);
        rs1 += __shfl_xor_sync(~0u, rs1, 2);
        if (t4 == 0) {
            Rsm[(qw + g) * 2 + nh]     = rs0;
            Rsm[(qw + g + 8) * 2 + nh] = rs1;
        }

        // rescale O while P/Rsm land
#pragma unroll
        for (int dt = 0; dt < 8; dt++) {
            o[dt][0] *= al0; o[dt][1] *= al0;
            o[dt][2] *= al1; o[dt][3] *= al1;
        }
        cp_wait1();                                   // V(kt) arrived
        __syncthreads();                              // B3: publish V, Ps, Rsm
        l0 = l0 * al0 + Rsm[(qw + g) * 2]     + Rsm[(qw + g) * 2 + 1];
        l1 = l1 * al1 + Rsm[(qw + g + 8) * 2] + Rsm[(qw + g + 8) * 2 + 1];

        // ---- O += P V (warp: 16 rows x 64 d-cols, full 64 k) ----
#pragma unroll
        for (int k0 = 0; k0 < 64; k0 += 8) {
            unsigned a0 = Ps[(qw + g) * 68 + k0 + t4];
            unsigned a1 = Ps[(qw + g + 8) * 68 + k0 + t4];
            unsigned a2 = Ps[(qw + g) * 68 + k0 + t4 + 4];
            unsigned a3 = Ps[(qw + g + 8) * 68 + k0 + t4 + 4];
#pragma unroll
            for (int dt = 0; dt < 8; dt++) {
                unsigned b0 = Vs[(nh * 64 + dt * 8 + g) * 68 + k0 + t4];
                unsigned b1 = Vs[(nh * 64 + dt * 8 + g) * 68 + k0 + t4 + 4];
                mma8(o[dt], a0, a1, a2, a3, b0, b1);
            }
        }
    }

    float i0 = 1.f / l0, i1 = 1.f / l1;
    int row0 = win_src_row(win * LL + qbase + qw + g);
    int row1 = win_src_row(win * LL + qbase + qw + g + 8);
#pragma unroll
    for (int dt = 0; dt < 8; dt++) {
        int c = nh * 64 + dt * 8 + 2 * t4;
        *(float2*)&g_attn[(size_t)row0 * 128 + c] = make_float2(o[dt][0] * i0, o[dt][1] * i0);
        *(float2*)&g_attn[(size_t)row1 * 128 + c] = make_float2(o[dt][2] * i1, o[dt][3] * i1);
    }
}

// ---------------- K3: message = LN(attn @ Wm) -> g_cat[:,128:]. grid 512 ----
__global__ void k_wm_ln(const float* __restrict__ Wm, const float* __restrict__ g1,
                        const float* __restrict__ b1) {
    extern __shared__ unsigned sm[];
    unsigned* As = sm;                        // [64][132]
    unsigned* Ws = sm + 64 * 132;             // [128][132]
    float*    Rs = (float*)(Ws + 128 * 132);  // [64][132]

    const int tid = threadIdx.x, tile = blockIdx.x;
    for (int i = tid; i < 64 * 128; i += 256) {
        int r = i >> 7, c = i & 127;
        As[r * 132 + c] = f2tf(g_attn[(size_t)(tile * 64 + r) * 128 + c]);
    }
    for (int i = tid; i < 128 * 128; i += 256) {
        int k = i >> 7, n = i & 127;
        Ws[n * 132 + k] = f2tf(Wm[i]);
    }
    __syncthreads();

    const int warp = tid >> 5, lane = tid & 31, g = lane >> 2, t4 = lane & 3;
    const int rb = (warp >> 1) * 16, cb = (warp & 1) * 64;
    float acc[8][4];
#pragma unroll
    for (int nt = 0; nt < 8; nt++) acc[nt][0] = acc[nt][1] = acc[nt][2] = acc[nt][3] = 0.f;
#pragma unroll
    for (int k0 = 0; k0 < 128; k0 += 8) {
        unsigned a0 = As[(rb + g) * 132 + k0 + t4];
        unsigned a1 = As[(rb + g + 8) * 132 + k0 + t4];
        unsigned a2 = As[(rb + g) * 132 + k0 + t4 + 4];
        unsigned a3 = As[(rb + g + 8) * 132 + k0 + t4 + 4];
#pragma unroll
        for (int nt = 0; nt < 8; nt++) {
            unsigned b0 = Ws[(cb + nt * 8 + g) * 132 + k0 + t4];
            unsigned b1 = Ws[(cb + nt * 8 + g) * 132 + k0 + t4 + 4];
            mma8(acc[nt], a0, a1, a2, a3, b0, b1);
        }
    }
#pragma unroll
    for (int nt = 0; nt < 8; nt++) {
        int c = cb + nt * 8 + 2 * t4;
        Rs[(rb + g) * 132 + c]         = acc[nt][0];
        Rs[(rb + g) * 132 + c + 1]     = acc[nt][1];
        Rs[(rb + g + 8) * 132 + c]     = acc[nt][2];
        Rs[(rb + g + 8) * 132 + c + 1] = acc[nt][3];
    }
    __syncthreads();

    int row = tid >> 2, l4 = tid & 3;
    float sum = 0.f, sq = 0.f;
    for (int c = l4; c < 128; c += 4) {
        float v = Rs[row * 132 + c];
        sum += v; sq += v * v;
    }
    sum += __shfl_xor_sync(~0u, sum, 1); sum += __shfl_xor_sync(~0u, sum, 2);
    sq  += __shfl_xor_sync(~0u, sq, 1);  sq  += __shfl_xor_sync(~0u, sq, 2);
    float mean = sum * 0.0078125f;
    float rstd = rsqrtf(sq * 0.0078125f - mean * mean + 1e-5f);
    for (int c = l4; c < 128; c += 4) {
        g_cat[(size_t)(tile * 64 + row) * 256 + 128 + c] =
            tf32r((Rs[row * 132 + c] - mean) * rstd * g1[c] + b1[c]);
    }
}

// ---------------- K4: hidden = gelu(cat @ W1), cp.async. grid(256,4) x 512 -
#define M1_AW 4608    // [128][36]
#define M1_BW 8448    // [32][264]
__global__ __launch_bounds__(512, 1) void k_mlp1() {
    extern __shared__ unsigned sm[];
    unsigned* Ast = sm;                 // 2 x [128][36]
    unsigned* Bst = sm + 2 * M1_AW;     // 2 x [32][264]

    const int tid = threadIdx.x, tile = blockIdx.x, nb = blockIdx.y * 256;
    const int warp = tid >> 5, lane = tid & 31, g = lane >> 2, t4 = lane & 3;
    const int rb = (warp >> 2) * 32, cb = (warp & 3) * 64;

    float acc[2][8][4];
#pragma unroll
    for (int mt = 0; mt < 2; mt++)
#pragma unroll
        for (int nt = 0; nt < 8; nt++)
            acc[mt][nt][0] = acc[mt][nt][1] = acc[mt][nt][2] = acc[mt][nt][3] = 0.f;

    const float* Abase = g_cat + (size_t)tile * 128 * 256;

    for (int i = tid; i < 1024; i += 512) {
        int r = i >> 3, q = i & 7;
        cpa16(Ast + r * 36 + q * 4, Abase + r * 256 + q * 4);
    }
    for (int i = tid; i < 2048; i += 512) {
        int k = i >> 6, q = i & 63;
        cpa16(Bst + k * 264 + q * 4, g_W1t + (size_t)k * 1024 + nb + q * 4);
    }
    cp_commit();

    for (int c = 0; c < 8; c++) {
        const int st = c & 1;
        if (c > 0) __syncthreads();
        if (c + 1 < 8) {
            const int ns = (c + 1) & 1, kc = (c + 1) * 32;
            for (int i = tid; i < 1024; i += 512) {
                int r = i >> 3, q = i & 7;
                cpa16(Ast + ns * M1_AW + r * 36 + q * 4, Abase + r * 256 + kc + q * 4);
            }
            for (int i = tid; i < 2048; i += 512) {
                int k = i >> 6, q = i & 63;
                cpa16(Bst + ns * M1_BW + k * 264 + q * 4,
                      g_W1t + (size_t)(kc + k) * 1024 + nb + q * 4);
            }
        }
        cp_commit();
        cp_wait1();
        __syncthreads();

        const unsigned* As = Ast + st * M1_AW;
        const unsigned* Bs = Bst + st * M1_BW;
#pragma unroll
        for (int k0 = 0; k0 < 32; k0 += 8) {
            unsigned a00 = As[(rb + g) * 36 + k0 + t4];
            unsigned a01 = As[(rb + g + 8) * 36 + k0 + t4];
            unsigned a02 = As[(rb + g) * 36 + k0 + t4 + 4];
            unsigned a03 = As[(rb + g + 8) * 36 + k0 + t4 + 4];
            unsigned a10 = As[(rb + 16 + g) * 36 + k0 + t4];
            unsigned a11 = As[(rb + 24 + g) * 36 + k0 + t4];
            unsigned a12 = As[(rb + 16 + g) * 36 + k0 + t4 + 4];
            unsigned a13 = As[(rb + 24 + g) * 36 + k0 + t4 + 4];
#pragma unroll
            for (int nt = 0; nt < 8; nt++) {
                unsigned b0 = Bs[(k0 + t4) * 264 + cb + nt * 8 + g];
                unsigned b1 = Bs[(k0 + t4 + 4) * 264 + cb + nt * 8 + g];
                mma8(acc[0][nt], a00, a01, a02, a03, b0, b1);
                mma8(acc[1][nt], a10, a11, a12, a13, b0, b1);
            }
        }
    }

#pragma unroll
    for (int mt = 0; mt < 2; mt++) {
        int row0 = tile * 128 + rb + mt * 16 + g, row1 = row0 + 8;
#pragma unroll
        for (int nt = 0; nt < 8; nt++) {
            int cc = nb + cb + nt * 8 + 2 * t4;
            float x0 = acc[mt][nt][0], x1 = acc[mt][nt][1];
            float x2 = acc[mt][nt][2], x3 = acc[mt][nt][3];
            x0 = 0.5f * x0 * (1.f + erff(x0 * 0.70710678f));
            x1 = 0.5f * x1 * (1.f + erff(x1 * 0.70710678f));
            x2 = 0.5f * x2 * (1.f + erff(x2 * 0.70710678f));
            x3 = 0.5f * x3 * (1.f + erff(x3 * 0.70710678f));
            *(float2*)&g_hidden[(size_t)row0 * 1024 + cc] =
                make_float2(tf32r(x0), tf32r(x1));
            *(float2*)&g_hidden[(size_t)row1 * 1024 + cc] =
                make_float2(tf32r(x2), tf32r(x3));
        }
    }
}

// ---------------- K5: out = src + LN(hidden @ W2), cp.async. grid 256 x 512 -
#define M2_AW 4608    // [128][36]
#define M2_BW 4352    // [32][136]
__global__ __launch_bounds__(512, 1) void k_mlp2(const float* __restrict__ src,
                                                 const float* __restrict__ g2,
                                                 const float* __restrict__ b2,
                                                 float* __restrict__ out) {
    extern __shared__ unsigned sm[];
    unsigned* Ast = sm;                 // 2 x [128][36]
    unsigned* Bst = sm + 2 * M2_AW;     // 2 x [32][136]
    float*    Rs  = (float*)sm;         // [128][132] aliased after GEMM

    const int tid = threadIdx.x, tile = blockIdx.x;
    const int warp = tid >> 5, lane = tid & 31, g = lane >> 2, t4 = lane & 3;
    const int rb = (warp >> 2) * 32, cb = (warp & 3) * 32;

    float acc[2][4][4];
#pragma unroll
    for (int mt = 0; mt < 2; mt++)
#pragma unroll
        for (int nt = 0; nt < 4; nt++)
            acc[mt][nt][0] = acc[mt][nt][1] = acc[mt][nt][2] = acc[mt][nt][3] = 0.f;

    const float* Abase = g_hidden + (size_t)tile * 128 * 1024;

    for (int i = tid; i < 1024; i += 512) {
        int r = i >> 3, q = i & 7;
        cpa16(Ast + r * 36 + q * 4, Abase + r * 1024 + q * 4);
    }
    for (int i = tid; i < 1024; i += 512) {
        int k = i >> 5, q = i & 31;
        cpa16(Bst + k * 136 + q * 4, g_W2t + (size_t)k * 128 + q * 4);
    }
    cp_commit();

    for (int c = 0; c < 32; c++) {
        const int st = c & 1;
        if (c > 0) __syncthreads();
        if (c + 1 < 32) {
            const int ns = (c + 1) & 1, kc = (c + 1) * 32;
            for (int i = tid; i < 1024; i += 512) {
                int r = i >> 3, q = i & 7;
                cpa16(Ast + ns * M2_AW + r * 36 + q * 4, Abase + r * 1024 + kc + q * 4);
            }
            for (int i = tid; i < 1024; i += 512) {
                int k = i >> 5, q = i & 31;
                cpa16(Bst + ns * M2_BW + k * 136 + q * 4,
                      g_W2t + (size_t)(kc + k) * 128 + q * 4);
            }
        }
        cp_commit();
        cp_wait1();
        __syncthreads();

        const unsigned* As = Ast + st * M2_AW;
        const unsigned* Bs = Bst + st * M2_BW;
#pragma unroll
        for (int k0 = 0; k0 < 32; k0 += 8) {
            unsigned a00 = As[(rb + g) * 36 + k0 + t4];
            unsigned a01 = As[(rb + g + 8) * 36 + k0 + t4];
            unsigned a02 = As[(rb + g) * 36 + k0 + t4 + 4];
            unsigned a03 = As[(rb + g + 8) * 36 + k0 + t4 + 4];
            unsigned a10 = As[(rb + 16 + g) * 36 + k0 + t4];
            unsigned a11 = As[(rb + 24 + g) * 36 + k0 + t4];
            unsigned a12 = As[(rb + 16 + g) * 36 + k0 + t4 + 4];
            unsigned a13 = As[(rb + 24 + g) * 36 + k0 + t4 + 4];
#pragma unroll
            for (int nt = 0; nt < 4; nt++) {
                unsigned b0 = Bs[(k0 + t4) * 136 + cb + nt * 8 + g];
                unsigned b1 = Bs[(k0 + t4 + 4) * 136 + cb + nt * 8 + g];
                mma8(acc[0][nt], a00, a01, a02, a03, b0, b1);
                mma8(acc[1][nt], a10, a11, a12, a13, b0, b1);
            }
        }
    }

    __syncthreads();
#pragma unroll
    for (int mt = 0; mt < 2; mt++) {
        int r0 = rb + mt * 16 + g;
#pragma unroll
        for (int nt = 0; nt < 4; nt++) {
            int cc = cb + nt * 8 + 2 * t4;
            Rs[r0 * 132 + cc]           = acc[mt][nt][0];
            Rs[r0 * 132 + cc + 1]       = acc[mt][nt][1];
            Rs[(r0 + 8) * 132 + cc]     = acc[mt][nt][2];
            Rs[(r0 + 8) * 132 + cc + 1] = acc[mt][nt][3];
        }
    }
    __syncthreads();

    int row = tid >> 2, l4 = tid & 3;
    float sum = 0.f, sq = 0.f;
    for (int cc = l4; cc < 128; cc += 4) {
        float v = Rs[row * 132 + cc];
        sum += v; sq += v * v;
    }
    sum += __shfl_xor_sync(~0u, sum, 1); sum += __shfl_xor_sync(~0u, sum, 2);
    sq  += __shfl_xor_sync(~0u, sq, 1);  sq  += __shfl_xor_sync(~0u, sq, 2);
    float mean = sum * 0.0078125f;
    float rstd = rsqrtf(sq * 0.0078125f - mean * mean + 1e-5f);
    size_t grow = (size_t)(tile * 128 + row) * 128;
    for (int cc = l4; cc < 128; cc += 4) {
        out[grow + cc] = src[grow + cc] + (Rs[row * 132 + cc] - mean) * rstd * g2[cc] + b2[cc];
    }
}

extern "C" void kernel_launch(void* const* d_in, const int* in_sizes, int n_in,
                              void* d_out, int out_size) {
    (void)in_sizes; (void)n_in; (void)out_size;
    const float* src  = (const float*)d_in[0];
    const float* tgt  = (const float*)d_in[1];
    const float* mask = (const float*)d_in[2];
    const float* Wq   = (const float*)d_in[8];
    const float* Wk   = (const float*)d_in[9];
    const float* Wv   = (const float*)d_in[10];
    const float* Wm   = (const float*)d_in[11];
    const float* g1   = (const float*)d_in[12];
    const float* b1   = (const float*)d_in[13];
    const float* W1   = (const float*)d_in[14];
    const float* W2   = (const float*)d_in[15];
    const float* g2   = (const float*)d_in[16];
    const float* b2   = (const float*)d_in[17];
    float* out = (float*)d_out;

    const int SM1 = (64 * 132 + 128 * 132) * 4;                        // 101376
    const int SM2 = (QS_W + 2 * KS_W + VS_W + PS_W + 512) * 4;         // 206848
    const int SM3 = (64 * 132 + 128 * 132 + 64 * 132) * 4;             // 135168
    const int SM4 = (2 * M1_AW + 2 * M1_BW) * 4;                       // 104448
    const int SM5a = (2 * M2_AW + 2 * M2_BW) * 4;                      // 71680
    const int SM5 = (SM5a > 128 * 132 * 4) ? SM5a : 128 * 132 * 4;     // 71680

    cudaFuncSetAttribute(k_qkv,   cudaFuncAttributeMaxDynamicSharedMemorySize, SM1);
    cudaFuncSetAttribute(k_attn,  cudaFuncAttributeMaxDynamicSharedMemorySize, SM2);
    cudaFuncSetAttribute(k_wm_ln, cudaFuncAttributeMaxDynamicSharedMemorySize, SM3);
    cudaFuncSetAttribute(k_mlp1,  cudaFuncAttributeMaxDynamicSharedMemorySize, SM4);
    cudaFuncSetAttribute(k_mlp2,  cudaFuncAttributeMaxDynamicSharedMemorySize, SM5);

    k_prep <<<(SRC_N + W1_N + W2_N + 511) / 512, 512>>>(src, W1, W2);
    k_qkv  <<<dim3(512, 3), 256, SM1>>>(src, tgt, Wq, Wk, Wv);
    k_attn <<<dim3(16, 16), 512, SM2>>>(mask);
    k_wm_ln<<<512,          256, SM3>>>(Wm, g1, b1);
    k_mlp1 <<<dim3(256, 4), 512, SM4>>>();
    k_mlp2 <<<256,          512, SM5>>>(src, g2, b2, out);
}

// round 6
// speedup vs baseline: 2.1905x; 1.1155x over previous
#include <cuda_runtime.h>
#include <math.h>

#define TOK   32768
#define LL    2048
#define ATT_SCALE 0.08838834764831845f

// All GEMM operands stored PRE-ROUNDED (cvt.rna) to tf32 so consumers
// cp.async raw bits straight into mma — bit-identical to cvt-at-load.
__device__ float g_Qw[TOK * 128];
__device__ float g_Kw[TOK * 128];
__device__ float g_Vw[TOK * 128];    // transposed per window: [win][d=128][k=2048]
__device__ float g_attn[TOK * 128];  // tf32-rounded
__device__ float g_cat[(size_t)TOK * 256];    // [src_tf32 | msg_tf32]
__device__ float g_tcat[TOK * 128];           // tf32(target)
__device__ float g_hidden[(size_t)TOK * 1024];
__device__ float g_W1t[256 * 1024];
__device__ float g_W2t[1024 * 128];
__device__ float g_Wqkvt[3 * 16384];
__device__ float g_Wmt[16384];

__device__ __forceinline__ unsigned f2tf(float f) {
    unsigned u;
    asm("cvt.rna.tf32.f32 %0, %1;" : "=r"(u) : "f"(f));
    return u;
}
__device__ __forceinline__ float tf32r(float f) { return __uint_as_float(f2tf(f)); }

__device__ __forceinline__ void mma8(float* c, unsigned a0, unsigned a1,
                                     unsigned a2, unsigned a3,
                                     unsigned b0, unsigned b1) {
    asm volatile(
        "mma.sync.aligned.m16n8k8.row.col.f32.tf32.tf32.f32 "
        "{%0,%1,%2,%3},{%4,%5,%6,%7},{%8,%9},{%0,%1,%2,%3};"
        : "+f"(c[0]), "+f"(c[1]), "+f"(c[2]), "+f"(c[3])
        : "r"(a0), "r"(a1), "r"(a2), "r"(a3), "r"(b0), "r"(b1));
}

__device__ __forceinline__ void cpa16(unsigned* dst_smem, const float* src) {
    unsigned a = (unsigned)__cvta_generic_to_shared(dst_smem);
    asm volatile("cp.async.cg.shared.global [%0], [%1], 16;\n" :: "r"(a), "l"(src));
}
__device__ __forceinline__ void cp_commit() { asm volatile("cp.async.commit_group;\n"); }
__device__ __forceinline__ void cp_wait1()  { asm volatile("cp.async.wait_group 1;\n"); }
__device__ __forceinline__ void cp_wait2()  { asm volatile("cp.async.wait_group 2;\n"); }

__device__ __forceinline__ int win_src_row(int gr) {
    int b = gr >> 13, rem = gr & 8191;
    int w4 = rem >> 11, p = rem & 2047;
    int wi = w4 >> 1, wj = w4 & 1;
    int iy = p >> 6, ix = p & 63;
    int y = (wi * 32 + iy + 16) & 63;
    int x = (wj * 64 + ix + 32) & 127;
    return (b << 13) + (y << 7) + x;
}

// ---------------- K0: round all operands to tf32 scratch -------------------
#define SRC_N  4194304
#define W1_N   262144
#define W2_N   131072
#define WQKV_N 49152
#define WM_N   16384
__global__ void k_prep(const float* __restrict__ src, const float* __restrict__ tgt,
                       const float* __restrict__ W1, const float* __restrict__ W2,
                       const float* __restrict__ Wq, const float* __restrict__ Wk,
                       const float* __restrict__ Wv, const float* __restrict__ Wm) {
    int i = blockIdx.x * 512 + threadIdx.x;
    if (i < SRC_N) {
        int r = i >> 7, c = i & 127;
        g_cat[(size_t)r * 256 + c] = tf32r(src[i]);
        g_tcat[i] = tf32r(tgt[i]);
    } else if (i < SRC_N + W1_N) {
        int j = i - SRC_N;
        g_W1t[j] = tf32r(W1[j]);
    } else if (i < SRC_N + W1_N + W2_N) {
        int j = i - SRC_N - W1_N;
        g_W2t[j] = tf32r(W2[j]);
    } else if (i < SRC_N + W1_N + W2_N + WQKV_N) {
        int j = i - SRC_N - W1_N - W2_N;
        const float* W = (j < 16384) ? Wq : (j < 32768) ? Wk : Wv;
        g_Wqkvt[j] = tf32r(W[j & 16383]);
    } else if (i < SRC_N + W1_N + W2_N + WQKV_N + WM_N) {
        int j = i - SRC_N - W1_N - W2_N - WQKV_N;
        g_Wmt[j] = tf32r(Wm[j]);
    }
}

// Shared GEMM geometry: 256 thr, tile 128x128, warp 32x64 (4m x 2n),
// A [128][36] x2, B [32][136] x2, k-chunks of 32.
#define GA_W 4608
#define GB_W 4352

// ---------------- K1: QKV projection + window gather. grid(256,3) x 256 ----
__global__ __launch_bounds__(256, 2) void k_qkv() {
    extern __shared__ unsigned sm[];
    unsigned* Ast = sm;                    // 2 x [128][36]
    unsigned* Bst = sm + 2 * GA_W;         // 2 x [32][136]
    int*      rows = (int*)(Bst + 2 * GB_W);   // [128]

    const int tid = threadIdx.x, tile = blockIdx.x, sel = blockIdx.y;
    const int warp = tid >> 5, lane = tid & 31, g = lane >> 2, t4 = lane & 3;
    const int rb = (warp >> 1) * 32, cb = (warp & 1) * 64;

    const float* Asrc = (sel == 0) ? g_cat : g_tcat;
    const size_t astr = (sel == 0) ? 256 : 128;
    const float* Bsrc = g_Wqkvt + sel * 16384;

    if (tid < 128) rows[tid] = win_src_row(tile * 128 + tid);
    __syncthreads();

    float acc[2][8][4];
#pragma unroll
    for (int mt = 0; mt < 2; mt++)
#pragma unroll
        for (int nt = 0; nt < 8; nt++)
            acc[mt][nt][0] = acc[mt][nt][1] = acc[mt][nt][2] = acc[mt][nt][3] = 0.f;

    for (int i = tid; i < 1024; i += 256) {
        int r = i >> 3, q = i & 7;
        cpa16(Ast + r * 36 + q * 4, Asrc + (size_t)rows[r] * astr + q * 4);
    }
    for (int i = tid; i < 1024; i += 256) {
        int k = i >> 5, q = i & 31;
        cpa16(Bst + k * 136 + q * 4, Bsrc + (size_t)k * 128 + q * 4);
    }
    cp_commit();

    for (int c = 0; c < 4; c++) {
        const int st = c & 1;
        if (c > 0) __syncthreads();
        if (c + 1 < 4) {
            const int ns = (c + 1) & 1, kc = (c + 1) * 32;
            for (int i = tid; i < 1024; i += 256) {
                int r = i >> 3, q = i & 7;
                cpa16(Ast + ns * GA_W + r * 36 + q * 4,
                      Asrc + (size_t)rows[r] * astr + kc + q * 4);
            }
            for (int i = tid; i < 1024; i += 256) {
                int k = i >> 5, q = i & 31;
                cpa16(Bst + ns * GB_W + k * 136 + q * 4,
                      Bsrc + (size_t)(kc + k) * 128 + q * 4);
            }
        }
        cp_commit();
        cp_wait1();
        __syncthreads();

        const unsigned* As = Ast + st * GA_W;
        const unsigned* Bs = Bst + st * GB_W;
#pragma unroll
        for (int k0 = 0; k0 < 32; k0 += 8) {
            unsigned a00 = As[(rb + g) * 36 + k0 + t4];
            unsigned a01 = As[(rb + g + 8) * 36 + k0 + t4];
            unsigned a02 = As[(rb + g) * 36 + k0 + t4 + 4];
            unsigned a03 = As[(rb + g + 8) * 36 + k0 + t4 + 4];
            unsigned a10 = As[(rb + 16 + g) * 36 + k0 + t4];
            unsigned a11 = As[(rb + 24 + g) * 36 + k0 + t4];
            unsigned a12 = As[(rb + 16 + g) * 36 + k0 + t4 + 4];
            unsigned a13 = As[(rb + 24 + g) * 36 + k0 + t4 + 4];
#pragma unroll
            for (int nt = 0; nt < 8; nt++) {
                unsigned b0 = Bs[(k0 + t4) * 136 + cb + nt * 8 + g];
                unsigned b1 = Bs[(k0 + t4 + 4) * 136 + cb + nt * 8 + g];
                mma8(acc[0][nt], a00, a01, a02, a03, b0, b1);
                mma8(acc[1][nt], a10, a11, a12, a13, b0, b1);
            }
        }
    }

    if (sel == 2) {
        float* Vt = g_Vw + (size_t)(tile >> 4) * 262144;
#pragma unroll
        for (int mt = 0; mt < 2; mt++) {
            int kk = (tile * 128 + rb + mt * 16 + g) & 2047;
#pragma unroll
            for (int nt = 0; nt < 8; nt++) {
                int cc = cb + nt * 8 + 2 * t4;
                Vt[(size_t)cc * 2048 + kk]           = tf32r(acc[mt][nt][0]);
                Vt[(size_t)(cc + 1) * 2048 + kk]     = tf32r(acc[mt][nt][1]);
                Vt[(size_t)cc * 2048 + kk + 8]       = tf32r(acc[mt][nt][2]);
                Vt[(size_t)(cc + 1) * 2048 + kk + 8] = tf32r(acc[mt][nt][3]);
            }
        }
    } else {
        float* outp = (sel == 0) ? g_Qw : g_Kw;
#pragma unroll
        for (int mt = 0; mt < 2; mt++) {
            int row0 = tile * 128 + rb + mt * 16 + g, row1 = row0 + 8;
#pragma unroll
            for (int nt = 0; nt < 8; nt++) {
                int cc = cb + nt * 8 + 2 * t4;
                *(float2*)&outp[(size_t)row0 * 128 + cc] =
                    make_float2(tf32r(acc[mt][nt][0]), tf32r(acc[mt][nt][1]));
                *(float2*)&outp[(size_t)row1 * 128 + cc] =
                    make_float2(tf32r(acc[mt][nt][2]), tf32r(acc[mt][nt][3]));
            }
        }
    }
}

// ---------------- K2: flash attention. grid(16,16) x 512 (unchanged core) --
#define QS_W 16896
#define KS_W 8448
#define VS_W 8704
#define PS_W 8704
__global__ __launch_bounds__(512, 1) void k_attn(const float* __restrict__ mask) {
    extern __shared__ unsigned sm[];
    unsigned* Qs  = sm;
    unsigned* Kst = sm + QS_W;
    unsigned* Vs  = Kst + 2 * KS_W;
    unsigned* Ps  = Vs + VS_W;
    float*    Rmx = (float*)(Ps + PS_W);
    float*    Rsm = Rmx + 256;

    const int tid = threadIdx.x, warp = tid >> 5, lane = tid & 31;
    const int g = lane >> 2, t4 = lane & 3;
    const int qw = (warp >> 1) * 16, nh = warp & 1;
    const int qbase = blockIdx.x * 128, win = blockIdx.y, w4 = win & 3;

    const float* Qg   = g_Qw + ((size_t)(win * LL + qbase)) * 128;
    const float* Kgb  = g_Kw + ((size_t)(win * LL)) * 128;
    const float* Vt   = g_Vw + (size_t)win * 262144;
    const float* Mrow = mask + (size_t)w4 * LL * LL + (size_t)qbase * LL;

    for (int i = tid; i < 4096; i += 512) {
        int r = i >> 5, q = i & 31;
        cpa16(Qs + r * 132 + q * 4, Qg + r * 128 + q * 4);
    }
    for (int i = tid; i < 2048; i += 512) {
        int r = i >> 5, q = i & 31;
        cpa16(Kst + r * 132 + q * 4, Kgb + r * 128 + q * 4);
    }
    cp_commit();

    float o[8][4];
#pragma unroll
    for (int dt = 0; dt < 8; dt++) o[dt][0] = o[dt][1] = o[dt][2] = o[dt][3] = 0.f;
    float m0 = -1e30f, m1 = -1e30f, l0 = 0.f, l1 = 0.f;

    for (int kt = 0; kt < 32; kt++) {
        const int st = kt & 1;
        const int kbase = kt * 64;

        if (kt > 0) __syncthreads();
        for (int i = tid; i < 2048; i += 512) {
            int d = i >> 4, q = i & 15;
            cpa16(Vs + d * 68 + q * 4, Vt + (size_t)d * 2048 + kbase + q * 4);
        }
        cp_commit();
        if (kt + 1 < 32) {
            const float* Kg = Kgb + (size_t)(kt + 1) * 64 * 128;
            unsigned* Kd = Kst + ((kt + 1) & 1) * KS_W;
            for (int i = tid; i < 2048; i += 512) {
                int r = i >> 5, q = i & 31;
                cpa16(Kd + r * 132 + q * 4, Kg + r * 128 + q * 4);
            }
        }
        cp_commit();
        cp_wait2();
        __syncthreads();

        const unsigned* Ks = Kst + st * KS_W;

        float2 mr0[4], mr1[4];
#pragma unroll
        for (int nt = 0; nt < 4; nt++) {
            int col = nh * 32 + nt * 8 + 2 * t4;
            mr0[nt] = __ldg((const float2*)(Mrow + (size_t)(qw + g) * LL + kbase + col));
            mr1[nt] = __ldg((const float2*)(Mrow + (size_t)(qw + 8 + g) * LL + kbase + col));
        }

        float s[4][4];
#pragma unroll
        for (int nt = 0; nt < 4; nt++) s[nt][0] = s[nt][1] = s[nt][2] = s[nt][3] = 0.f;
#pragma unroll
        for (int d0 = 0; d0 < 128; d0 += 8) {
            unsigned a0 = Qs[(qw + g) * 132 + d0 + t4];
            unsigned a1 = Qs[(qw + g + 8) * 132 + d0 + t4];
            unsigned a2 = Qs[(qw + g) * 132 + d0 + t4 + 4];
            unsigned a3 = Qs[(qw + g + 8) * 132 + d0 + t4 + 4];
#pragma unroll
            for (int nt = 0; nt < 4; nt++) {
                unsigned b0 = Ks[(nh * 32 + nt * 8 + g) * 132 + d0 + t4];
                unsigned b1 = Ks[(nh * 32 + nt * 8 + g) * 132 + d0 + t4 + 4];
                mma8(s[nt], a0, a1, a2, a3, b0, b1);
            }
        }

        float ml0 = -1e30f, ml1 = -1e30f;
#pragma unroll
        for (int nt = 0; nt < 4; nt++) {
            s[nt][0] = s[nt][0] * ATT_SCALE + mr0[nt].x;
            s[nt][1] = s[nt][1] * ATT_SCALE + mr0[nt].y;
            s[nt][2] = s[nt][2] * ATT_SCALE + mr1[nt].x;
            s[nt][3] = s[nt][3] * ATT_SCALE + mr1[nt].y;
            ml0 = fmaxf(ml0, fmaxf(s[nt][0], s[nt][1]));
            ml1 = fmaxf(ml1, fmaxf(s[nt][2], s[nt][3]));
        }
        ml0 = fmaxf(ml0, __shfl_xor_sync(~0u, ml0, 1));
        ml0 = fmaxf(ml0, __shfl_xor_sync(~0u, ml0, 2));
        ml1 = fmaxf(ml1, __shfl_xor_sync(~0u, ml1, 1));
        ml1 = fmaxf(ml1, __shfl_xor_sync(~0u, ml1, 2));
        if (t4 == 0) {
            Rmx[(qw + g) * 2 + nh]     = ml0;
            Rmx[(qw + g + 8) * 2 + nh] = ml1;
        }
        __syncthreads();
        float gm0 = fmaxf(Rmx[(qw + g) * 2],     Rmx[(qw + g) * 2 + 1]);
        float gm1 = fmaxf(Rmx[(qw + g + 8) * 2], Rmx[(qw + g + 8) * 2 + 1]);

        float mn0 = fmaxf(m0, gm0), mn1 = fmaxf(m1, gm1);
        float al0 = __expf(m0 - mn0), al1 = __expf(m1 - mn1);
        m0 = mn0; m1 = mn1;

        float rs0 = 0.f, rs1 = 0.f;
#pragma unroll
        for (int nt = 0; nt < 4; nt++) {
            int col = nh * 32 + nt * 8 + 2 * t4;
            float p0 = __expf(s[nt][0] - mn0);
            float p1 = __expf(s[nt][1] - mn0);
            float p2 = __expf(s[nt][2] - mn1);
            float p3 = __expf(s[nt][3] - mn1);
            rs0 += p0 + p1; rs1 += p2 + p3;
            Ps[(qw + g) * 68 + col]         = f2tf(p0);
            Ps[(qw + g) * 68 + col + 1]     = f2tf(p1);
            Ps[(qw + g + 8) * 68 + col]     = f2tf(p2);
            Ps[(qw + g + 8) * 68 + col + 1] = f2tf(p3);
        }
        rs0 += __shfl_xor_sync(~0u, rs0, 1);
        rs0 += __shfl_xor_sync(~0u, rs0, 2);
        rs1 += __shfl_xor_sync(~0u, rs1, 1);
        rs1 += __shfl_xor_sync(~0u, rs1, 2);
        if (t4 == 0) {
            Rsm[(qw + g) * 2 + nh]     = rs0;
            Rsm[(qw + g + 8) * 2 + nh] = rs1;
        }

#pragma unroll
        for (int dt = 0; dt < 8; dt++) {
            o[dt][0] *= al0; o[dt][1] *= al0;
            o[dt][2] *= al1; o[dt][3] *= al1;
        }
        cp_wait1();
        __syncthreads();
        l0 = l0 * al0 + Rsm[(qw + g) * 2]     + Rsm[(qw + g) * 2 + 1];
        l1 = l1 * al1 + Rsm[(qw + g + 8) * 2] + Rsm[(qw + g + 8) * 2 + 1];

#pragma unroll
        for (int k0 = 0; k0 < 64; k0 += 8) {
            unsigned a0 = Ps[(qw + g) * 68 + k0 + t4];
            unsigned a1 = Ps[(qw + g + 8) * 68 + k0 + t4];
            unsigned a2 = Ps[(qw + g) * 68 + k0 + t4 + 4];
            unsigned a3 = Ps[(qw + g + 8) * 68 + k0 + t4 + 4];
#pragma unroll
            for (int dt = 0; dt < 8; dt++) {
                unsigned b0 = Vs[(nh * 64 + dt * 8 + g) * 68 + k0 + t4];
                unsigned b1 = Vs[(nh * 64 + dt * 8 + g) * 68 + k0 + t4 + 4];
                mma8(o[dt], a0, a1, a2, a3, b0, b1);
            }
        }
    }

    float i0 = 1.f / l0, i1 = 1.f / l1;
    int row0 = win_src_row(win * LL + qbase + qw + g);
    int row1 = win_src_row(win * LL + qbase + qw + g + 8);
#pragma unroll
    for (int dt = 0; dt < 8; dt++) {
        int c = nh * 64 + dt * 8 + 2 * t4;
        *(float2*)&g_attn[(size_t)row0 * 128 + c] =
            make_float2(tf32r(o[dt][0] * i0), tf32r(o[dt][1] * i0));
        *(float2*)&g_attn[(size_t)row1 * 128 + c] =
            make_float2(tf32r(o[dt][2] * i1), tf32r(o[dt][3] * i1));
    }
}

// ---------------- K3: message = LN(attn @ Wm) -> g_cat[:,128:]. grid 256 ---
__global__ __launch_bounds__(256, 2) void k_wm_ln(const float* __restrict__ g1,
                                                  const float* __restrict__ b1) {
    extern __shared__ unsigned sm[];
    unsigned* Ast = sm;
    unsigned* Bst = sm + 2 * GA_W;
    float*    Rs  = (float*)sm;       // [128][132] aliased after GEMM

    const int tid = threadIdx.x, tile = blockIdx.x;
    const int warp = tid >> 5, lane = tid & 31, g = lane >> 2, t4 = lane & 3;
    const int rb = (warp >> 1) * 32, cb = (warp & 1) * 64;
    const float* Abase = g_attn + (size_t)tile * 128 * 128;

    float acc[2][8][4];
#pragma unroll
    for (int mt = 0; mt < 2; mt++)
#pragma unroll
        for (int nt = 0; nt < 8; nt++)
            acc[mt][nt][0] = acc[mt][nt][1] = acc[mt][nt][2] = acc[mt][nt][3] = 0.f;

    for (int i = tid; i < 1024; i += 256) {
        int r = i >> 3, q = i & 7;
        cpa16(Ast + r * 36 + q * 4, Abase + (size_t)r * 128 + q * 4);
    }
    for (int i = tid; i < 1024; i += 256) {
        int k = i >> 5, q = i & 31;
        cpa16(Bst + k * 136 + q * 4, g_Wmt + (size_t)k * 128 + q * 4);
    }
    cp_commit();

    for (int c = 0; c < 4; c++) {
        const int st = c & 1;
        if (c > 0) __syncthreads();
        if (c + 1 < 4) {
            const int ns = (c + 1) & 1, kc = (c + 1) * 32;
            for (int i = tid; i < 1024; i += 256) {
                int r = i >> 3, q = i & 7;
                cpa16(Ast + ns * GA_W + r * 36 + q * 4, Abase + (size_t)r * 128 + kc + q * 4);
            }
            for (int i = tid; i < 1024; i += 256) {
                int k = i >> 5, q = i & 31;
                cpa16(Bst + ns * GB_W + k * 136 + q * 4, g_Wmt + (size_t)(kc + k) * 128 + q * 4);
            }
        }
        cp_commit();
        cp_wait1();
        __syncthreads();

        const unsigned* As = Ast + st * GA_W;
        const unsigned* Bs = Bst + st * GB_W;
#pragma unroll
        for (int k0 = 0; k0 < 32; k0 += 8) {
            unsigned a00 = As[(rb + g) * 36 + k0 + t4];
            unsigned a01 = As[(rb + g + 8) * 36 + k0 + t4];
            unsigned a02 = As[(rb + g) * 36 + k0 + t4 + 4];
            unsigned a03 = As[(rb + g + 8) * 36 + k0 + t4 + 4];
            unsigned a10 = As[(rb + 16 + g) * 36 + k0 + t4];
            unsigned a11 = As[(rb + 24 + g) * 36 + k0 + t4];
            unsigned a12 = As[(rb + 16 + g) * 36 + k0 + t4 + 4];
            unsigned a13 = As[(rb + 24 + g) * 36 + k0 + t4 + 4];
#pragma unroll
            for (int nt = 0; nt < 8; nt++) {
                unsigned b0 = Bs[(k0 + t4) * 136 + cb + nt * 8 + g];
                unsigned b1 = Bs[(k0 + t4 + 4) * 136 + cb + nt * 8 + g];
                mma8(acc[0][nt], a00, a01, a02, a03, b0, b1);
                mma8(acc[1][nt], a10, a11, a12, a13, b0, b1);
            }
        }
    }

    __syncthreads();
#pragma unroll
    for (int mt = 0; mt < 2; mt++) {
        int r0 = rb + mt * 16 + g;
#pragma unroll
        for (int nt = 0; nt < 8; nt++) {
            int cc = cb + nt * 8 + 2 * t4;
            Rs[r0 * 132 + cc]           = acc[mt][nt][0];
            Rs[r0 * 132 + cc + 1]       = acc[mt][nt][1];
            Rs[(r0 + 8) * 132 + cc]     = acc[mt][nt][2];
            Rs[(r0 + 8) * 132 + cc + 1] = acc[mt][nt][3];
        }
    }
    __syncthreads();

    int row = tid >> 1, half = tid & 1;
    float sum = 0.f, sq = 0.f;
    for (int cc = half; cc < 128; cc += 2) {
        float v = Rs[row * 132 + cc];
        sum += v; sq += v * v;
    }
    sum += __shfl_xor_sync(~0u, sum, 1);
    sq  += __shfl_xor_sync(~0u, sq, 1);
    float mean = sum * 0.0078125f;
    float rstd = rsqrtf(sq * 0.0078125f - mean * mean + 1e-5f);
    size_t orow = (size_t)(tile * 128 + row) * 256 + 128;
    for (int cc = half; cc < 128; cc += 2) {
        g_cat[orow + cc] = tf32r((Rs[row * 132 + cc] - mean) * rstd * g1[cc] + b1[cc]);
    }
}

// ---------------- K4: hidden = gelu(cat @ W1). grid(8, 256) x 256 ----------
__global__ __launch_bounds__(256, 2) void k_mlp1() {
    extern __shared__ unsigned sm[];
    unsigned* Ast = sm;
    unsigned* Bst = sm + 2 * GA_W;

    const int tid = threadIdx.x, nb = blockIdx.x * 128, tile = blockIdx.y;
    const int warp = tid >> 5, lane = tid & 31, g = lane >> 2, t4 = lane & 3;
    const int rb = (warp >> 1) * 32, cb = (warp & 1) * 64;
    const float* Abase = g_cat + (size_t)tile * 128 * 256;

    float acc[2][8][4];
#pragma unroll
    for (int mt = 0; mt < 2; mt++)
#pragma unroll
        for (int nt = 0; nt < 8; nt++)
            acc[mt][nt][0] = acc[mt][nt][1] = acc[mt][nt][2] = acc[mt][nt][3] = 0.f;

    for (int i = tid; i < 1024; i += 256) {
        int r = i >> 3, q = i & 7;
        cpa16(Ast + r * 36 + q * 4, Abase + (size_t)r * 256 + q * 4);
    }
    for (int i = tid; i < 1024; i += 256) {
        int k = i >> 5, q = i & 31;
        cpa16(Bst + k * 136 + q * 4, g_W1t + (size_t)k * 1024 + nb + q * 4);
    }
    cp_commit();

    for (int c = 0; c < 8; c++) {
        const int st = c & 1;
        if (c > 0) __syncthreads();
        if (c + 1 < 8) {
            const int ns = (c + 1) & 1, kc = (c + 1) * 32;
            for (int i = tid; i < 1024; i += 256) {
                int r = i >> 3, q = i & 7;
                cpa16(Ast + ns * GA_W + r * 36 + q * 4, Abase + (size_t)r * 256 + kc + q * 4);
            }
            for (int i = tid; i < 1024; i += 256) {
                int k = i >> 5, q = i & 31;
                cpa16(Bst + ns * GB_W + k * 136 + q * 4,
                      g_W1t + (size_t)(kc + k) * 1024 + nb + q * 4);
            }
        }
        cp_commit();
        cp_wait1();
        __syncthreads();

        const unsigned* As = Ast + st * GA_W;
        const unsigned* Bs = Bst + st * GB_W;
#pragma unroll
        for (int k0 = 0; k0 < 32; k0 += 8) {
            unsigned a00 = As[(rb + g) * 36 + k0 + t4];
            unsigned a01 = As[(rb + g + 8) * 36 + k0 + t4];
            unsigned a02 = As[(rb + g) * 36 + k0 + t4 + 4];
            unsigned a03 = As[(rb + g + 8) * 36 + k0 + t4 + 4];
            unsigned a10 = As[(rb + 16 + g) * 36 + k0 + t4];
            unsigned a11 = As[(rb + 24 + g) * 36 + k0 + t4];
            unsigned a12 = As[(rb + 16 + g) * 36 + k0 + t4 + 4];
            unsigned a13 = As[(rb + 24 + g) * 36 + k0 + t4 + 4];
#pragma unroll
            for (int nt = 0; nt < 8; nt++) {
                unsigned b0 = Bs[(k0 + t4) * 136 + cb + nt * 8 + g];
                unsigned b1 = Bs[(k0 + t4 + 4) * 136 + cb + nt * 8 + g];
                mma8(acc[0][nt], a00, a01, a02, a03, b0, b1);
                mma8(acc[1][nt], a10, a11, a12, a13, b0, b1);
            }
        }
    }

#pragma unroll
    for (int mt = 0; mt < 2; mt++) {
        int row0 = tile * 128 + rb + mt * 16 + g, row1 = row0 + 8;
#pragma unroll
        for (int nt = 0; nt < 8; nt++) {
            int cc = nb + cb + nt * 8 + 2 * t4;
            float x0 = acc[mt][nt][0], x1 = acc[mt][nt][1];
            float x2 = acc[mt][nt][2], x3 = acc[mt][nt][3];
            x0 = 0.5f * x0 * (1.f + erff(x0 * 0.70710678f));
            x1 = 0.5f * x1 * (1.f + erff(x1 * 0.70710678f));
            x2 = 0.5f * x2 * (1.f + erff(x2 * 0.70710678f));
            x3 = 0.5f * x3 * (1.f + erff(x3 * 0.70710678f));
            *(float2*)&g_hidden[(size_t)row0 * 1024 + cc] =
                make_float2(tf32r(x0), tf32r(x1));
            *(float2*)&g_hidden[(size_t)row1 * 1024 + cc] =
                make_float2(tf32r(x2), tf32r(x3));
        }
    }
}

// ---------------- K5: out = src + LN(hidden @ W2). grid 256 x 256 ----------
__global__ __launch_bounds__(256, 2) void k_mlp2(const float* __restrict__ src,
                                                 const float* __restrict__ g2,
                                                 const float* __restrict__ b2,
                                                 float* __restrict__ out) {
    extern __shared__ unsigned sm[];
    unsigned* Ast = sm;
    unsigned* Bst = sm + 2 * GA_W;
    float*    Rs  = (float*)sm;

    const int tid = threadIdx.x, tile = blockIdx.x;
    const int warp = tid >> 5, lane = tid & 31, g = lane >> 2, t4 = lane & 3;
    const int rb = (warp >> 1) * 32, cb = (warp & 1) * 64;
    const float* Abase = g_hidden + (size_t)tile * 128 * 1024;

    float acc[2][8][4];
#pragma unroll
    for (int mt = 0; mt < 2; mt++)
#pragma unroll
        for (int nt = 0; nt < 8; nt++)
            acc[mt][nt][0] = acc[mt][nt][1] = acc[mt][nt][2] = acc[mt][nt][3] = 0.f;

    for (int i = tid; i < 1024; i += 256) {
        int r = i >> 3, q = i & 7;
        cpa16(Ast + r * 36 + q * 4, Abase + (size_t)r * 1024 + q * 4);
    }
    for (int i = tid; i < 1024; i += 256) {
        int k = i >> 5, q = i & 31;
        cpa16(Bst + k * 136 + q * 4, g_W2t + (size_t)k * 128 + q * 4);
    }
    cp_commit();

    for (int c = 0; c < 32; c++) {
        const int st = c & 1;
        if (c > 0) __syncthreads();
        if (c + 1 < 32) {
            const int ns = (c + 1) & 1, kc = (c + 1) * 32;
            for (int i = tid; i < 1024; i += 256) {
                int r = i >> 3, q = i & 7;
                cpa16(Ast + ns * GA_W + r * 36 + q * 4, Abase + (size_t)r * 1024 + kc + q * 4);
            }
            for (int i = tid; i < 1024; i += 256) {
                int k = i >> 5, q = i & 31;
                cpa16(Bst + ns * GB_W + k * 136 + q * 4,
                      g_W2t + (size_t)(kc + k) * 128 + q * 4);
            }
        }
        cp_commit();
        cp_wait1();
        __syncthreads();

        const unsigned* As = Ast + st * GA_W;
        const unsigned* Bs = Bst + st * GB_W;
#pragma unroll
        for (int k0 = 0; k0 < 32; k0 += 8) {
            unsigned a00 = As[(rb + g) * 36 + k0 + t4];
            unsigned a01 = As[(rb + g + 8) * 36 + k0 + t4];
            unsigned a02 = As[(rb + g) * 36 + k0 + t4 + 4];
            unsigned a03 = As[(rb + g + 8) * 36 + k0 + t4 + 4];
            unsigned a10 = As[(rb + 16 + g) * 36 + k0 + t4];
            unsigned a11 = As[(rb + 24 + g) * 36 + k0 + t4];
            unsigned a12 = As[(rb + 16 + g) * 36 + k0 + t4 + 4];
            unsigned a13 = As[(rb + 24 + g) * 36 + k0 + t4 + 4];
#pragma unroll
            for (int nt = 0; nt < 8; nt++) {
                unsigned b0 = Bs[(k0 + t4) * 136 + cb + nt * 8 + g];
                unsigned b1 = Bs[(k0 + t4 + 4) * 136 + cb + nt * 8 + g];
                mma8(acc[0][nt], a00, a01, a02, a03, b0, b1);
                mma8(acc[1][nt], a10, a11, a12, a13, b0, b1);
            }
        }
    }

    __syncthreads();
#pragma unroll
    for (int mt = 0; mt < 2; mt++) {
        int r0 = rb + mt * 16 + g;
#pragma unroll
        for (int nt = 0; nt < 8; nt++) {
            int cc = cb + nt * 8 + 2 * t4;
            Rs[r0 * 132 + cc]           = acc[mt][nt][0];
            Rs[r0 * 132 + cc + 1]       = acc[mt][nt][1];
            Rs[(r0 + 8) * 132 + cc]     = acc[mt][nt][2];
            Rs[(r0 + 8) * 132 + cc + 1] = acc[mt][nt][3];
        }
    }
    __syncthreads();

    int row = tid >> 1, half = tid & 1;
    float sum = 0.f, sq = 0.f;
    for (int cc = half; cc < 128; cc += 2) {
        float v = Rs[row * 132 + cc];
        sum += v; sq += v * v;
    }
    sum += __shfl_xor_sync(~0u, sum, 1);
    sq  += __shfl_xor_sync(~0u, sq, 1);
    float mean = sum * 0.0078125f;
    float rstd = rsqrtf(sq * 0.0078125f - mean * mean + 1e-5f);
    size_t grow = (size_t)(tile * 128 + row) * 128;
    for (int cc = half; cc < 128; cc += 2) {
        out[grow + cc] = src[grow + cc] + (Rs[row * 132 + cc] - mean) * rstd * g2[cc] + b2[cc];
    }
}

extern "C" void kernel_launch(void* const* d_in, const int* in_sizes, int n_in,
                              void* d_out, int out_size) {
    (void)in_sizes; (void)n_in; (void)out_size;
    const float* src  = (const float*)d_in[0];
    const float* tgt  = (const float*)d_in[1];
    const float* mask = (const float*)d_in[2];
    const float* Wq   = (const float*)d_in[8];
    const float* Wk   = (const float*)d_in[9];
    const float* Wv   = (const float*)d_in[10];
    const float* Wm   = (const float*)d_in[11];
    const float* g1   = (const float*)d_in[12];
    const float* b1   = (const float*)d_in[13];
    const float* W1   = (const float*)d_in[14];
    const float* W2   = (const float*)d_in[15];
    const float* g2   = (const float*)d_in[16];
    const float* b2   = (const float*)d_in[17];
    float* out = (float*)d_out;

    const int SMG  = (2 * GA_W + 2 * GB_W) * 4;           // 71680
    const int SMQ  = SMG + 128 * 4;                       // 72192 (rows[])
    const int SM2  = (QS_W + 2 * KS_W + VS_W + PS_W + 512) * 4;   // 206848

    cudaFuncSetAttribute(k_qkv,   cudaFuncAttributeMaxDynamicSharedMemorySize, SMQ);
    cudaFuncSetAttribute(k_attn,  cudaFuncAttributeMaxDynamicSharedMemorySize, SM2);
    cudaFuncSetAttribute(k_wm_ln, cudaFuncAttributeMaxDynamicSharedMemorySize, SMG);
    cudaFuncSetAttribute(k_mlp1,  cudaFuncAttributeMaxDynamicSharedMemorySize, SMG);
    cudaFuncSetAttribute(k_mlp2,  cudaFuncAttributeMaxDynamicSharedMemorySize, SMG);

    k_prep <<<17280, 512>>>(src, tgt, W1, W2, Wq, Wk, Wv, Wm);
    k_qkv  <<<dim3(256, 3), 256, SMQ>>>();
    k_attn <<<dim3(16, 16), 512, SM2>>>(mask);
    k_wm_ln<<<256,          256, SMG>>>(g1, b1);
    k_mlp1 <<<dim3(8, 256), 256, SMG>>>();
    k_mlp2 <<<256,          256, SMG>>>(src, g2, b2, out);
}

// round 8
// speedup vs baseline: 2.4523x; 1.1195x over previous
#include <cuda_runtime.h>
#include <cuda_bf16.h>
#include <math.h>

#define TOK   32768
#define LL    2048
#define ATT_SCALE 0.08838834764831845f

// Q/K packed bf16x2 (for bf16 QK^T). Everything else tf32-prerounded fp32.
__device__ unsigned g_Qh[TOK * 64];
__device__ unsigned g_Kh[TOK * 64];
__device__ float g_Vw[TOK * 128];    // transposed per window: [win][d=128][k=2048]
__device__ float g_attn[TOK * 128];  // tf32-rounded
__device__ float g_cat[(size_t)TOK * 256];    // [src_tf32 | msg_tf32]
__device__ float g_tcat[TOK * 128];           // tf32(target)
__device__ float g_hidden[(size_t)TOK * 1024];
__device__ float g_W1t[256 * 1024];           // [k][n]
__device__ float g_W2t[1024 * 128];           // [k][n]
__device__ float g_Wqkvt[3 * 16384];          // [sel][k][n]
__device__ float g_Wmt[16384];                // [k][n]

__device__ __forceinline__ unsigned f2tf(float f) {
    unsigned u;
    asm("cvt.rna.tf32.f32 %0, %1;" : "=r"(u) : "f"(f));
    return u;
}
__device__ __forceinline__ float tf32r(float f) { return __uint_as_float(f2tf(f)); }
__device__ __forceinline__ unsigned pbf(float lo, float hi) {
    __nv_bfloat162 h = __floats2bfloat162_rn(lo, hi);   // lo -> low 16 bits
    return *(unsigned*)&h;
}

__device__ __forceinline__ void mma8(float* c, unsigned a0, unsigned a1,
                                     unsigned a2, unsigned a3,
                                     unsigned b0, unsigned b1) {
    asm volatile(
        "mma.sync.aligned.m16n8k8.row.col.f32.tf32.tf32.f32 "
        "{%0,%1,%2,%3},{%4,%5,%6,%7},{%8,%9},{%0,%1,%2,%3};"
        : "+f"(c[0]), "+f"(c[1]), "+f"(c[2]), "+f"(c[3])
        : "r"(a0), "r"(a1), "r"(a2), "r"(a3), "r"(b0), "r"(b1));
}
__device__ __forceinline__ void mma16bf(float* c, unsigned a0, unsigned a1,
                                        unsigned a2, unsigned a3,
                                        unsigned b0, unsigned b1) {
    asm volatile(
        "mma.sync.aligned.m16n8k16.row.col.f32.bf16.bf16.f32 "
        "{%0,%1,%2,%3},{%4,%5,%6,%7},{%8,%9},{%0,%1,%2,%3};"
        : "+f"(c[0]), "+f"(c[1]), "+f"(c[2]), "+f"(c[3])
        : "r"(a0), "r"(a1), "r"(a2), "r"(a3), "r"(b0), "r"(b1));
}

__device__ __forceinline__ void cpa16(void* dst_smem, const float* src) {
    unsigned a = (unsigned)__cvta_generic_to_shared(dst_smem);
    asm volatile("cp.async.cg.shared.global [%0], [%1], 16;\n" :: "r"(a), "l"(src));
}
__device__ __forceinline__ void cp_commit() { asm volatile("cp.async.commit_group;\n"); }
__device__ __forceinline__ void cp_wait1()  { asm volatile("cp.async.wait_group 1;\n"); }
__device__ __forceinline__ void cp_wait2()  { asm volatile("cp.async.wait_group 2;\n"); }

__device__ __forceinline__ int win_src_row(int gr) {
    int b = gr >> 13, rem = gr & 8191;
    int w4 = rem >> 11, p = rem & 2047;
    int wi = w4 >> 1, wj = w4 & 1;
    int iy = p >> 6, ix = p & 63;
    int y = (wi * 32 + iy + 16) & 63;
    int x = (wj * 64 + ix + 32) & 127;
    return (b << 13) + (y << 7) + x;
}

// ---------------- K0: round all operands to tf32 scratch (vectorized) ------
#define SRC4  1048576
#define W1_N  262144
#define W2_N  131072
#define WQKV_N 49152
#define WM_N  16384
__global__ void k_prep(const float* __restrict__ src, const float* __restrict__ tgt,
                       const float* __restrict__ W1, const float* __restrict__ W2,
                       const float* __restrict__ Wq, const float* __restrict__ Wk,
                       const float* __restrict__ Wv, const float* __restrict__ Wm) {
    int i = blockIdx.x * 256 + threadIdx.x;
    if (i < SRC4) {
        float4 v = ((const float4*)src)[i];
        float4 o = make_float4(tf32r(v.x), tf32r(v.y), tf32r(v.z), tf32r(v.w));
        int r = i >> 5, c = i & 31;
        ((float4*)g_cat)[(size_t)r * 64 + c] = o;
    } else if (i < 2 * SRC4) {
        int j = i - SRC4;
        float4 v = ((const float4*)tgt)[j];
        ((float4*)g_tcat)[j] = make_float4(tf32r(v.x), tf32r(v.y), tf32r(v.z), tf32r(v.w));
    } else {
        int j = i - 2 * SRC4;
        if (j < W1_N) {
            g_W1t[j] = tf32r(W1[j]);
        } else if (j < W1_N + W2_N) {
            g_W2t[j - W1_N] = tf32r(W2[j - W1_N]);
        } else if (j < W1_N + W2_N + WQKV_N) {
            int jj = j - W1_N - W2_N;
            const float* W = (jj < 16384) ? Wq : (jj < 32768) ? Wk : Wv;
            g_Wqkvt[jj] = tf32r(W[jj & 16383]);
        } else if (j < W1_N + W2_N + WQKV_N + WM_N) {
            int jj = j - W1_N - W2_N - WQKV_N;
            g_Wmt[jj] = tf32r(Wm[jj]);
        }
    }
}

// ---------------- K1: merged QKV, A resident. grid 256 x 256 ---------------
// smem: As [128][132] tf32, Bst 2 x [32][136], rows[128].
__device__ __forceinline__ void qkv_gemm(const unsigned* As, unsigned* Bst,
                                         const float* Bsrc, float acc[2][8][4],
                                         int tid, int rb, int cb, int g, int t4) {
#pragma unroll
    for (int mt = 0; mt < 2; mt++)
#pragma unroll
        for (int nt = 0; nt < 8; nt++)
            acc[mt][nt][0] = acc[mt][nt][1] = acc[mt][nt][2] = acc[mt][nt][3] = 0.f;

    for (int c = 0; c < 4; c++) {
        if (c > 0) __syncthreads();
        if (c + 1 < 4) {
            unsigned* Bd = Bst + ((c + 1) & 1) * 4352;
            int kc = (c + 1) * 32;
            for (int i = tid; i < 1024; i += 256) {
                int k = i >> 5, q = i & 31;
                cpa16(Bd + k * 136 + q * 4, Bsrc + (size_t)(kc + k) * 128 + q * 4);
            }
        }
        cp_commit();
        cp_wait1();
        __syncthreads();

        const unsigned* Bs = Bst + (c & 1) * 4352;
        const int kb = c * 32;
#pragma unroll
        for (int k0 = 0; k0 < 32; k0 += 8) {
            unsigned a00 = As[(rb + g) * 132 + kb + k0 + t4];
            unsigned a01 = As[(rb + g + 8) * 132 + kb + k0 + t4];
            unsigned a02 = As[(rb + g) * 132 + kb + k0 + t4 + 4];
            unsigned a03 = As[(rb + g + 8) * 132 + kb + k0 + t4 + 4];
            unsigned a10 = As[(rb + 16 + g) * 132 + kb + k0 + t4];
            unsigned a11 = As[(rb + 24 + g) * 132 + kb + k0 + t4];
            unsigned a12 = As[(rb + 16 + g) * 132 + kb + k0 + t4 + 4];
            unsigned a13 = As[(rb + 24 + g) * 132 + kb + k0 + t4 + 4];
#pragma unroll
            for (int nt = 0; nt < 8; nt++) {
                unsigned b0 = Bs[(k0 + t4) * 136 + cb + nt * 8 + g];
                unsigned b1 = Bs[(k0 + t4 + 4) * 136 + cb + nt * 8 + g];
                mma8(acc[0][nt], a00, a01, a02, a03, b0, b1);
                mma8(acc[1][nt], a10, a11, a12, a13, b0, b1);
            }
        }
    }
}

__global__ __launch_bounds__(256, 2) void k_qkv() {
    extern __shared__ unsigned sm[];
    unsigned* As  = sm;                    // [128][132]
    unsigned* Bst = sm + 16896;            // 2 x [32][136]
    int* rows     = (int*)(Bst + 8704);    // [128]

    const int tid = threadIdx.x, tile = blockIdx.x;
    const int warp = tid >> 5, lane = tid & 31, g = lane >> 2, t4 = lane & 3;
    const int rb = (warp >> 1) * 32, cb = (warp & 1) * 64;

    if (tid < 128) rows[tid] = win_src_row(tile * 128 + tid);
    __syncthreads();

    float acc[2][8][4];

    // ---- phase 1: A = target rows; compute K then V ----
    for (int i = tid; i < 4096; i += 256) {
        int r = i >> 5, q = i & 31;
        cpa16(As + r * 132 + q * 4, g_tcat + (size_t)rows[r] * 128 + q * 4);
    }
    for (int i = tid; i < 1024; i += 256) {        // Wk chunk 0
        int k = i >> 5, q = i & 31;
        cpa16(Bst + k * 136 + q * 4, g_Wqkvt + 16384 + (size_t)k * 128 + q * 4);
    }
    cp_commit();
    qkv_gemm(As, Bst, g_Wqkvt + 16384, acc, tid, rb, cb, g, t4);
    // K epilogue (bf16 packed)
#pragma unroll
    for (int mt = 0; mt < 2; mt++) {
        int row0 = tile * 128 + rb + mt * 16 + g, row1 = row0 + 8;
#pragma unroll
        for (int nt = 0; nt < 8; nt++) {
            int uc = (cb >> 1) + nt * 4 + t4;
            g_Kh[(size_t)row0 * 64 + uc] = pbf(acc[mt][nt][0], acc[mt][nt][1]);
            g_Kh[(size_t)row1 * 64 + uc] = pbf(acc[mt][nt][2], acc[mt][nt][3]);
        }
    }
    __syncthreads();

    for (int i = tid; i < 1024; i += 256) {        // Wv chunk 0
        int k = i >> 5, q = i & 31;
        cpa16(Bst + k * 136 + q * 4, g_Wqkvt + 32768 + (size_t)k * 128 + q * 4);
    }
    cp_commit();
    qkv_gemm(As, Bst, g_Wqkvt + 32768, acc, tid, rb, cb, g, t4);
    // V epilogue (transposed tf32)
    {
        float* Vt = g_Vw + (size_t)(tile >> 4) * 262144;
#pragma unroll
        for (int mt = 0; mt < 2; mt++) {
            int kk = (tile * 128 + rb + mt * 16 + g) & 2047;
#pragma unroll
            for (int nt = 0; nt < 8; nt++) {
                int cc = cb + nt * 8 + 2 * t4;
                Vt[(size_t)cc * 2048 + kk]           = tf32r(acc[mt][nt][0]);
                Vt[(size_t)(cc + 1) * 2048 + kk]     = tf32r(acc[mt][nt][1]);
                Vt[(size_t)cc * 2048 + kk + 8]       = tf32r(acc[mt][nt][2]);
                Vt[(size_t)(cc + 1) * 2048 + kk + 8] = tf32r(acc[mt][nt][3]);
            }
        }
    }
    __syncthreads();

    // ---- phase 2: A = source rows; compute Q ----
    for (int i = tid; i < 4096; i += 256) {
        int r = i >> 5, q = i & 31;
        cpa16(As + r * 132 + q * 4, g_cat + (size_t)rows[r] * 256 + q * 4);
    }
    for (int i = tid; i < 1024; i += 256) {        // Wq chunk 0
        int k = i >> 5, q = i & 31;
        cpa16(Bst + k * 136 + q * 4, g_Wqkvt + (size_t)k * 128 + q * 4);
    }
    cp_commit();
    qkv_gemm(As, Bst, g_Wqkvt, acc, tid, rb, cb, g, t4);
#pragma unroll
    for (int mt = 0; mt < 2; mt++) {
        int row0 = tile * 128 + rb + mt * 16 + g, row1 = row0 + 8;
#pragma unroll
        for (int nt = 0; nt < 8; nt++) {
            int uc = (cb >> 1) + nt * 4 + t4;
            g_Qh[(size_t)row0 * 64 + uc] = pbf(acc[mt][nt][0], acc[mt][nt][1]);
            g_Qh[(size_t)row1 * 64 + uc] = pbf(acc[mt][nt][2], acc[mt][nt][3]);
        }
    }
}

// ---------------- K2: flash attention, bf16 QK^T. grid(16,16) x 512 --------
#define QS_W 8704    // [128][68] u32 (bf16x2)
#define KS_W 4352    // [64][68]  u32 (bf16x2)
#define VS_W 8704    // [128][68] tf32
#define PS_W 8704    // [128][68] tf32
__global__ __launch_bounds__(512, 1) void k_attn(const float* __restrict__ mask) {
    extern __shared__ unsigned sm[];
    unsigned* Qs  = sm;
    unsigned* Kst = sm + QS_W;
    unsigned* Vs  = Kst + 2 * KS_W;
    unsigned* Ps  = Vs + VS_W;
    float*    Rmx = (float*)(Ps + PS_W);
    float*    Rsm = Rmx + 256;

    const int tid = threadIdx.x, warp = tid >> 5, lane = tid & 31;
    const int g = lane >> 2, t4 = lane & 3;
    const int qw = (warp >> 1) * 16, nh = warp & 1;
    const int qbase = blockIdx.x * 128, win = blockIdx.y, w4 = win & 3;

    const unsigned* Qg  = g_Qh + (size_t)(win * LL + qbase) * 64;
    const unsigned* Kgb = g_Kh + (size_t)(win * LL) * 64;
    const float* Vt   = g_Vw + (size_t)win * 262144;
    const float* Mrow = mask + (size_t)w4 * LL * LL + (size_t)qbase * LL;

    for (int i = tid; i < 2048; i += 512) {     // Q: 128 rows x 16 chunks
        int r = i >> 4, q = i & 15;
        cpa16(Qs + r * 68 + q * 4, (const float*)(Qg + (size_t)r * 64 + q * 4));
    }
    for (int i = tid; i < 1024; i += 512) {     // K0: 64 rows x 16 chunks
        int r = i >> 4, q = i & 15;
        cpa16(Kst + r * 68 + q * 4, (const float*)(Kgb + (size_t)r * 64 + q * 4));
    }
    cp_commit();

    float o[8][4];
#pragma unroll
    for (int dt = 0; dt < 8; dt++) o[dt][0] = o[dt][1] = o[dt][2] = o[dt][3] = 0.f;
    float m0 = -1e30f, m1 = -1e30f, l0 = 0.f, l1 = 0.f;

    for (int kt = 0; kt < 32; kt++) {
        const int st = kt & 1;
        const int kbase = kt * 64;

        if (kt > 0) __syncthreads();
        for (int i = tid; i < 2048; i += 512) {   // V(kt)
            int d = i >> 4, q = i & 15;
            cpa16(Vs + d * 68 + q * 4, Vt + (size_t)d * 2048 + kbase + q * 4);
        }
        cp_commit();
        if (kt + 1 < 32) {
            const unsigned* Kg = Kgb + (size_t)(kt + 1) * 64 * 64;
            unsigned* Kd = Kst + ((kt + 1) & 1) * KS_W;
            for (int i = tid; i < 1024; i += 512) {
                int r = i >> 4, q = i & 15;
                cpa16(Kd + r * 68 + q * 4, (const float*)(Kg + (size_t)r * 64 + q * 4));
            }
        }
        cp_commit();
        cp_wait2();
        __syncthreads();

        const unsigned* Ks = Kst + st * KS_W;

        float2 mr0[4], mr1[4];
#pragma unroll
        for (int nt = 0; nt < 4; nt++) {
            int col = nh * 32 + nt * 8 + 2 * t4;
            mr0[nt] = __ldg((const float2*)(Mrow + (size_t)(qw + g) * LL + kbase + col));
            mr1[nt] = __ldg((const float2*)(Mrow + (size_t)(qw + 8 + g) * LL + kbase + col));
        }

        // ---- S = Q K^T (bf16 m16n8k16; warp: 16 rows x 32 cols) ----
        float s[4][4];
#pragma unroll
        for (int nt = 0; nt < 4; nt++) s[nt][0] = s[nt][1] = s[nt][2] = s[nt][3] = 0.f;
#pragma unroll
        for (int d2 = 0; d2 < 64; d2 += 8) {
            unsigned a0 = Qs[(qw + g) * 68 + d2 + t4];
            unsigned a1 = Qs[(qw + g + 8) * 68 + d2 + t4];
            unsigned a2 = Qs[(qw + g) * 68 + d2 + t4 + 4];
            unsigned a3 = Qs[(qw + g + 8) * 68 + d2 + t4 + 4];
#pragma unroll
            for (int nt = 0; nt < 4; nt++) {
                unsigned b0 = Ks[(nh * 32 + nt * 8 + g) * 68 + d2 + t4];
                unsigned b1 = Ks[(nh * 32 + nt * 8 + g) * 68 + d2 + t4 + 4];
                mma16bf(s[nt], a0, a1, a2, a3, b0, b1);
            }
        }

        float ml0 = -1e30f, ml1 = -1e30f;
#pragma unroll
        for (int nt = 0; nt < 4; nt++) {
            s[nt][0] = s[nt][0] * ATT_SCALE + mr0[nt].x;
            s[nt][1] = s[nt][1] * ATT_SCALE + mr0[nt].y;
            s[nt][2] = s[nt][2] * ATT_SCALE + mr1[nt].x;
            s[nt][3] = s[nt][3] * ATT_SCALE + mr1[nt].y;
            ml0 = fmaxf(ml0, fmaxf(s[nt][0], s[nt][1]));
            ml1 = fmaxf(ml1, fmaxf(s[nt][2], s[nt][3]));
        }
        ml0 = fmaxf(ml0, __shfl_xor_sync(~0u, ml0, 1));
        ml0 = fmaxf(ml0, __shfl_xor_sync(~0u, ml0, 2));
        ml1 = fmaxf(ml1, __shfl_xor_sync(~0u, ml1, 1));
        ml1 = fmaxf(ml1, __shfl_xor_sync(~0u, ml1, 2));
        if (t4 == 0) {
            Rmx[(qw + g) * 2 + nh]     = ml0;
            Rmx[(qw + g + 8) * 2 + nh] = ml1;
        }
        __syncthreads();
        float gm0 = fmaxf(Rmx[(qw + g) * 2],     Rmx[(qw + g) * 2 + 1]);
        float gm1 = fmaxf(Rmx[(qw + g + 8) * 2], Rmx[(qw + g + 8) * 2 + 1]);

        float mn0 = fmaxf(m0, gm0), mn1 = fmaxf(m1, gm1);
        float al0 = __expf(m0 - mn0), al1 = __expf(m1 - mn1);
        m0 = mn0; m1 = mn1;

        float rs0 = 0.f, rs1 = 0.f;
#pragma unroll
        for (int nt = 0; nt < 4; nt++) {
            int col = nh * 32 + nt * 8 + 2 * t4;
            float p0 = __expf(s[nt][0] - mn0);
            float p1 = __expf(s[nt][1] - mn0);
            float p2 = __expf(s[nt][2] - mn1);
            float p3 = __expf(s[nt][3] - mn1);
            rs0 += p0 + p1; rs1 += p2 + p3;
            Ps[(qw + g) * 68 + col]         = f2tf(p0);
            Ps[(qw + g) * 68 + col + 1]     = f2tf(p1);
            Ps[(qw + g + 8) * 68 + col]     = f2tf(p2);
            Ps[(qw + g + 8) * 68 + col + 1] = f2tf(p3);
        }
        rs0 += __shfl_xor_sync(~0u, rs0, 1);
        rs0 += __shfl_xor_sync(~0u, rs0, 2);
        rs1 += __shfl_xor_sync(~0u, rs1, 1);
        rs1 += __shfl_xor_sync(~0u, rs1, 2);
        if (t4 == 0) {
            Rsm[(qw + g) * 2 + nh]     = rs0;
            Rsm[(qw + g + 8) * 2 + nh] = rs1;
        }

#pragma unroll
        for (int dt = 0; dt < 8; dt++) {
            o[dt][0] *= al0; o[dt][1] *= al0;
            o[dt][2] *= al1; o[dt][3] *= al1;
        }
        cp_wait1();
        __syncthreads();
        l0 = l0 * al0 + Rsm[(qw + g) * 2]     + Rsm[(qw + g) * 2 + 1];
        l1 = l1 * al1 + Rsm[(qw + g + 8) * 2] + Rsm[(qw + g + 8) * 2 + 1];

        // ---- O += P V (tf32; warp: 16 rows x 64 d-cols) ----
#pragma unroll
        for (int k0 = 0; k0 < 64; k0 += 8) {
            unsigned a0 = Ps[(qw + g) * 68 + k0 + t4];
            unsigned a1 = Ps[(qw + g + 8) * 68 + k0 + t4];
            unsigned a2 = Ps[(qw + g) * 68 + k0 + t4 + 4];
            unsigned a3 = Ps[(qw + g + 8) * 68 + k0 + t4 + 4];
#pragma unroll
            for (int dt = 0; dt < 8; dt++) {
                unsigned b0 = Vs[(nh * 64 + dt * 8 + g) * 68 + k0 + t4];
                unsigned b1 = Vs[(nh * 64 + dt * 8 + g) * 68 + k0 + t4 + 4];
                mma8(o[dt], a0, a1, a2, a3, b0, b1);
            }
        }
    }

    float i0 = 1.f / l0, i1 = 1.f / l1;
    int row0 = win_src_row(win * LL + qbase + qw + g);
    int row1 = win_src_row(win * LL + qbase + qw + g + 8);
#pragma unroll
    for (int dt = 0; dt < 8; dt++) {
        int c = nh * 64 + dt * 8 + 2 * t4;
        *(float2*)&g_attn[(size_t)row0 * 128 + c] =
            make_float2(tf32r(o[dt][0] * i0), tf32r(o[dt][1] * i0));
        *(float2*)&g_attn[(size_t)row1 * 128 + c] =
            make_float2(tf32r(o[dt][2] * i1), tf32r(o[dt][3] * i1));
    }
}

// Shared GEMM geometry (tf32): 256 thr, tile 128x128, warp 32x64.
#define GA_W 4608
#define GB_W 4352

// ---------------- K3: message = LN(attn @ Wm) -> g_cat[:,128:]. grid 256 ---
__global__ __launch_bounds__(256, 2) void k_wm_ln(const float* __restrict__ g1,
                                                  const float* __restrict__ b1) {
    extern __shared__ unsigned sm[];
    unsigned* Ast = sm;
    unsigned* Bst = sm + 2 * GA_W;
    float*    Rs  = (float*)sm;

    const int tid = threadIdx.x, tile = blockIdx.x;
    const int warp = tid >> 5, lane = tid & 31, g = lane >> 2, t4 = lane & 3;
    const int rb = (warp >> 1) * 32, cb = (warp & 1) * 64;
    const float* Abase = g_attn + (size_t)tile * 128 * 128;

    float acc[2][8][4];
#pragma unroll
    for (int mt = 0; mt < 2; mt++)
#pragma unroll
        for (int nt = 0; nt < 8; nt++)
            acc[mt][nt][0] = acc[mt][nt][1] = acc[mt][nt][2] = acc[mt][nt][3] = 0.f;

    for (int i = tid; i < 1024; i += 256) {
        int r = i >> 3, q = i & 7;
        cpa16(Ast + r * 36 + q * 4, Abase + (size_t)r * 128 + q * 4);
    }
    for (int i = tid; i < 1024; i += 256) {
        int k = i >> 5, q = i & 31;
        cpa16(Bst + k * 136 + q * 4, g_Wmt + (size_t)k * 128 + q * 4);
    }
    cp_commit();

    for (int c = 0; c < 4; c++) {
        const int st = c & 1;
        if (c > 0) __syncthreads();
        if (c + 1 < 4) {
            const int ns = (c + 1) & 1, kc = (c + 1) * 32;
            for (int i = tid; i < 1024; i += 256) {
                int r = i >> 3, q = i & 7;
                cpa16(Ast + ns * GA_W + r * 36 + q * 4, Abase + (size_t)r * 128 + kc + q * 4);
            }
            for (int i = tid; i < 1024; i += 256) {
                int k = i >> 5, q = i & 31;
                cpa16(Bst + ns * GB_W + k * 136 + q * 4, g_Wmt + (size_t)(kc + k) * 128 + q * 4);
            }
        }
        cp_commit();
        cp_wait1();
        __syncthreads();

        const unsigned* As = Ast + st * GA_W;
        const unsigned* Bs = Bst + st * GB_W;
#pragma unroll
        for (int k0 = 0; k0 < 32; k0 += 8) {
            unsigned a00 = As[(rb + g) * 36 + k0 + t4];
            unsigned a01 = As[(rb + g + 8) * 36 + k0 + t4];
            unsigned a02 = As[(rb + g) * 36 + k0 + t4 + 4];
            unsigned a03 = As[(rb + g + 8) * 36 + k0 + t4 + 4];
            unsigned a10 = As[(rb + 16 + g) * 36 + k0 + t4];
            unsigned a11 = As[(rb + 24 + g) * 36 + k0 + t4];
            unsigned a12 = As[(rb + 16 + g) * 36 + k0 + t4 + 4];
            unsigned a13 = As[(rb + 24 + g) * 36 + k0 + t4 + 4];
#pragma unroll
            for (int nt = 0; nt < 8; nt++) {
                unsigned b0 = Bs[(k0 + t4) * 136 + cb + nt * 8 + g];
                unsigned b1 = Bs[(k0 + t4 + 4) * 136 + cb + nt * 8 + g];
                mma8(acc[0][nt], a00, a01, a02, a03, b0, b1);
                mma8(acc[1][nt], a10, a11, a12, a13, b0, b1);
            }
        }
    }

    __syncthreads();
#pragma unroll
    for (int mt = 0; mt < 2; mt++) {
        int r0 = rb + mt * 16 + g;
#pragma unroll
        for (int nt = 0; nt < 8; nt++) {
            int cc = cb + nt * 8 + 2 * t4;
            Rs[r0 * 132 + cc]           = acc[mt][nt][0];
            Rs[r0 * 132 + cc + 1]       = acc[mt][nt][1];
            Rs[(r0 + 8) * 132 + cc]     = acc[mt][nt][2];
            Rs[(r0 + 8) * 132 + cc + 1] = acc[mt][nt][3];
        }
    }
    __syncthreads();

    int row = tid >> 1, half = tid & 1;
    float sum = 0.f, sq = 0.f;
    for (int cc = half; cc < 128; cc += 2) {
        float v = Rs[row * 132 + cc];
        sum += v; sq += v * v;
    }
    sum += __shfl_xor_sync(~0u, sum, 1);
    sq  += __shfl_xor_sync(~0u, sq, 1);
    float mean = sum * 0.0078125f;
    float rstd = rsqrtf(sq * 0.0078125f - mean * mean + 1e-5f);
    size_t orow = (size_t)(tile * 128 + row) * 256 + 128;
    for (int cc = half; cc < 128; cc += 2) {
        g_cat[orow + cc] = tf32r((Rs[row * 132 + cc] - mean) * rstd * g1[cc] + b1[cc]);
    }
}

// ---------------- K4: hidden = gelu(cat @ W1). grid(8, 256) x 256 ----------
__global__ __launch_bounds__(256, 2) void k_mlp1() {
    extern __shared__ unsigned sm[];
    unsigned* Ast = sm;
    unsigned* Bst = sm + 2 * GA_W;

    const int tid = threadIdx.x, nb = blockIdx.x * 128, tile = blockIdx.y;
    const int warp = tid >> 5, lane = tid & 31, g = lane >> 2, t4 = lane & 3;
    const int rb = (warp >> 1) * 32, cb = (warp & 1) * 64;
    const float* Abase = g_cat + (size_t)tile * 128 * 256;

    float acc[2][8][4];
#pragma unroll
    for (int mt = 0; mt < 2; mt++)
#pragma unroll
        for (int nt = 0; nt < 8; nt++)
            acc[mt][nt][0] = acc[mt][nt][1] = acc[mt][nt][2] = acc[mt][nt][3] = 0.f;

    for (int i = tid; i < 1024; i += 256) {
        int r = i >> 3, q = i & 7;
        cpa16(Ast + r * 36 + q * 4, Abase + (size_t)r * 256 + q * 4);
    }
    for (int i = tid; i < 1024; i += 256) {
        int k = i >> 5, q = i & 31;
        cpa16(Bst + k * 136 + q * 4, g_W1t + (size_t)k * 1024 + nb + q * 4);
    }
    cp_commit();

    for (int c = 0; c < 8; c++) {
        const int st = c & 1;
        if (c > 0) __syncthreads();
        if (c + 1 < 8) {
            const int ns = (c + 1) & 1, kc = (c + 1) * 32;
            for (int i = tid; i < 1024; i += 256) {
                int r = i >> 3, q = i & 7;
                cpa16(Ast + ns * GA_W + r * 36 + q * 4, Abase + (size_t)r * 256 + kc + q * 4);
            }
            for (int i = tid; i < 1024; i += 256) {
                int k = i >> 5, q = i & 31;
                cpa16(Bst + ns * GB_W + k * 136 + q * 4,
                      g_W1t + (size_t)(kc + k) * 1024 + nb + q * 4);
            }
        }
        cp_commit();
        cp_wait1();
        __syncthreads();

        const unsigned* As = Ast + st * GA_W;
        const unsigned* Bs = Bst + st * GB_W;
#pragma unroll
        for (int k0 = 0; k0 < 32; k0 += 8) {
            unsigned a00 = As[(rb + g) * 36 + k0 + t4];
            unsigned a01 = As[(rb + g + 8) * 36 + k0 + t4];
            unsigned a02 = As[(rb + g) * 36 + k0 + t4 + 4];
            unsigned a03 = As[(rb + g + 8) * 36 + k0 + t4 + 4];
            unsigned a10 = As[(rb + 16 + g) * 36 + k0 + t4];
            unsigned a11 = As[(rb + 24 + g) * 36 + k0 + t4];
            unsigned a12 = As[(rb + 16 + g) * 36 + k0 + t4 + 4];
            unsigned a13 = As[(rb + 24 + g) * 36 + k0 + t4 + 4];
#pragma unroll
            for (int nt = 0; nt < 8; nt++) {
                unsigned b0 = Bs[(k0 + t4) * 136 + cb + nt * 8 + g];
                unsigned b1 = Bs[(k0 + t4 + 4) * 136 + cb + nt * 8 + g];
                mma8(acc[0][nt], a00, a01, a02, a03, b0, b1);
                mma8(acc[1][nt], a10, a11, a12, a13, b0, b1);
            }
        }
    }

#pragma unroll
    for (int mt = 0; mt < 2; mt++) {
        int row0 = tile * 128 + rb + mt * 16 + g, row1 = row0 + 8;
#pragma unroll
        for (int nt = 0; nt < 8; nt++) {
            int cc = nb + cb + nt * 8 + 2 * t4;
            float x0 = acc[mt][nt][0], x1 = acc[mt][nt][1];
            float x2 = acc[mt][nt][2], x3 = acc[mt][nt][3];
            x0 = 0.5f * x0 * (1.f + erff(x0 * 0.70710678f));
            x1 = 0.5f * x1 * (1.f + erff(x1 * 0.70710678f));
            x2 = 0.5f * x2 * (1.f + erff(x2 * 0.70710678f));
            x3 = 0.5f * x3 * (1.f + erff(x3 * 0.70710678f));
            *(float2*)&g_hidden[(size_t)row0 * 1024 + cc] =
                make_float2(tf32r(x0), tf32r(x1));
            *(float2*)&g_hidden[(size_t)row1 * 1024 + cc] =
                make_float2(tf32r(x2), tf32r(x3));
        }
    }
}

// ---------------- K5: out = src + LN(hidden @ W2). grid 256 x 256 ----------
__global__ __launch_bounds__(256, 2) void k_mlp2(const float* __restrict__ src,
                                                 const float* __restrict__ g2,
                                                 const float* __restrict__ b2,
                                                 float* __restrict__ out) {
    extern __shared__ unsigned sm[];
    unsigned* Ast = sm;
    unsigned* Bst = sm + 2 * GA_W;
    float*    Rs  = (float*)sm;

    const int tid = threadIdx.x, tile = blockIdx.x;
    const int warp = tid >> 5, lane = tid & 31, g = lane >> 2, t4 = lane & 3;
    const int rb = (warp >> 1) * 32, cb = (warp & 1) * 64;
    const float* Abase = g_hidden + (size_t)tile * 128 * 1024;

    float acc[2][8][4];
#pragma unroll
    for (int mt = 0; mt < 2; mt++)
#pragma unroll
        for (int nt = 0; nt < 8; nt++)
            acc[mt][nt][0] = acc[mt][nt][1] = acc[mt][nt][2] = acc[mt][nt][3] = 0.f;

    for (int i = tid; i < 1024; i += 256) {
        int r = i >> 3, q = i & 7;
        cpa16(Ast + r * 36 + q * 4, Abase + (size_t)r * 1024 + q * 4);
    }
    for (int i = tid; i < 1024; i += 256) {
        int k = i >> 5, q = i & 31;
        cpa16(Bst + k * 136 + q * 4, g_W2t + (size_t)k * 128 + q * 4);
    }
    cp_commit();

    for (int c = 0; c < 32; c++) {
        const int st = c & 1;
        if (c > 0) __syncthreads();
        if (c + 1 < 32) {
            const int ns = (c + 1) & 1, kc = (c + 1) * 32;
            for (int i = tid; i < 1024; i += 256) {
                int r = i >> 3, q = i & 7;
                cpa16(Ast + ns * GA_W + r * 36 + q * 4, Abase + (size_t)r * 1024 + kc + q * 4);
            }
            for (int i = tid; i < 1024; i += 256) {
                int k = i >> 5, q = i & 31;
                cpa16(Bst + ns * GB_W + k * 136 + q * 4,
                      g_W2t + (size_t)(kc + k) * 128 + q * 4);
            }
        }
        cp_commit();
        cp_wait1();
        __syncthreads();

        const unsigned* As = Ast + st * GA_W;
        const unsigned* Bs = Bst + st * GB_W;
#pragma unroll
        for (int k0 = 0; k0 < 32; k0 += 8) {
            unsigned a00 = As[(rb + g) * 36 + k0 + t4];
            unsigned a01 = As[(rb + g + 8) * 36 + k0 + t4];
            unsigned a02 = As[(rb + g) * 36 + k0 + t4 + 4];
            unsigned a03 = As[(rb + g + 8) * 36 + k0 + t4 + 4];
            unsigned a10 = As[(rb + 16 + g) * 36 + k0 + t4];
            unsigned a11 = As[(rb + 24 + g) * 36 + k0 + t4];
            unsigned a12 = As[(rb + 16 + g) * 36 + k0 + t4 + 4];
            unsigned a13 = As[(rb + 24 + g) * 36 + k0 + t4 + 4];
#pragma unroll
            for (int nt = 0; nt < 8; nt++) {
                unsigned b0 = Bs[(k0 + t4) * 136 + cb + nt * 8 + g];
                unsigned b1 = Bs[(k0 + t4 + 4) * 136 + cb + nt * 8 + g];
                mma8(acc[0][nt], a00, a01, a02, a03, b0, b1);
                mma8(acc[1][nt], a10, a11, a12, a13, b0, b1);
            }
        }
    }

    __syncthreads();
#pragma unroll
    for (int mt = 0; mt < 2; mt++) {
        int r0 = rb + mt * 16 + g;
#pragma unroll
        for (int nt = 0; nt < 8; nt++) {
            int cc = cb + nt * 8 + 2 * t4;
            Rs[r0 * 132 + cc]           = acc[mt][nt][0];
            Rs[r0 * 132 + cc + 1]       = acc[mt][nt][1];
            Rs[(r0 + 8) * 132 + cc]     = acc[mt][nt][2];
            Rs[(r0 + 8) * 132 + cc + 1] = acc[mt][nt][3];
        }
    }
    __syncthreads();

    int row = tid >> 1, half = tid & 1;
    float sum = 0.f, sq = 0.f;
    for (int cc = half; cc < 128; cc += 2) {
        float v = Rs[row * 132 + cc];
        sum += v; sq += v * v;
    }
    sum += __shfl_xor_sync(~0u, sum, 1);
    sq  += __shfl_xor_sync(~0u, sq, 1);
    float mean = sum * 0.0078125f;
    float rstd = rsqrtf(sq * 0.0078125f - mean * mean + 1e-5f);
    size_t grow = (size_t)(tile * 128 + row) * 128;
    for (int cc = half; cc < 128; cc += 2) {
        out[grow + cc] = src[grow + cc] + (Rs[row * 132 + cc] - mean) * rstd * g2[cc] + b2[cc];
    }
}

extern "C" void kernel_launch(void* const* d_in, const int* in_sizes, int n_in,
                              void* d_out, int out_size) {
    (void)in_sizes; (void)n_in; (void)out_size;
    const float* src  = (const float*)d_in[0];
    const float* tgt  = (const float*)d_in[1];
    const float* mask = (const float*)d_in[2];
    const float* Wq   = (const float*)d_in[8];
    const float* Wk   = (const float*)d_in[9];
    const float* Wv   = (const float*)d_in[10];
    const float* Wm   = (const float*)d_in[11];
    const float* g1   = (const float*)d_in[12];
    const float* b1   = (const float*)d_in[13];
    const float* W1   = (const float*)d_in[14];
    const float* W2   = (const float*)d_in[15];
    const float* g2   = (const float*)d_in[16];
    const float* b2   = (const float*)d_in[17];
    float* out = (float*)d_out;

    const int SMQ = (16896 + 2 * 4352 + 128) * 4;                    // 102912
    const int SM2 = (QS_W + 2 * KS_W + VS_W + PS_W + 512) * 4;       // 141312
    const int SMG = (2 * GA_W + 2 * GB_W) * 4;                       // 71680

    cudaFuncSetAttribute(k_qkv,   cudaFuncAttributeMaxDynamicSharedMemorySize, SMQ);
    cudaFuncSetAttribute(k_attn,  cudaFuncAttributeMaxDynamicSharedMemorySize, SM2);
    cudaFuncSetAttribute(k_wm_ln, cudaFuncAttributeMaxDynamicSharedMemorySize, SMG);
    cudaFuncSetAttribute(k_mlp1,  cudaFuncAttributeMaxDynamicSharedMemorySize, SMG);
    cudaFuncSetAttribute(k_mlp2,  cudaFuncAttributeMaxDynamicSharedMemorySize, SMG);

    k_prep <<<9984, 256>>>(src, tgt, W1, W2, Wq, Wk, Wv, Wm);
    k_qkv  <<<256,          256, SMQ>>>();
    k_attn <<<dim3(16, 16), 512, SM2>>>(mask);
    k_wm_ln<<<256,          256, SMG>>>(g1, b1);
    k_mlp1 <<<dim3(8, 256), 256, SMG>>>();
    k_mlp2 <<<256,          256, SMG>>>(src, g2, b2, out);
}

// round 11
// speedup vs baseline: 4.0881x; 1.6671x over previous
#include <cuda_runtime.h>
#include <cuda_fp16.h>
#include <math.h>

#define TOK   32768
#define LL    2048
#define ATT_SCALE 0.08838834764831845f

// All operands packed fp16 (u32 = half2 pair along k/cols).
__device__ unsigned g_srch[TOK * 64];          // src rows
__device__ unsigned g_tgth[TOK * 64];          // tgt rows
__device__ unsigned g_msgh[TOK * 64];          // LN(attn@Wm)
__device__ unsigned g_Qh[TOK * 64];
__device__ unsigned g_Kh[TOK * 64];
__device__ __half   g_Vh[(size_t)TOK * 128];   // [win][d=128][k=2048] halfs
__device__ unsigned g_attnh[TOK * 64];
__device__ unsigned g_hidh[(size_t)TOK * 512];
__device__ unsigned g_Wqkvh[4 * 8192];         // [Wq|Wk|Wv|Wm], each [n=128][k/2=64]
__device__ unsigned g_W1h[1024 * 128];         // [n][k/2]
__device__ unsigned g_W2h[128 * 512];          // [n][k/2]

__device__ __forceinline__ unsigned phf(float lo, float hi) {
    __half2 h = __floats2half2_rn(lo, hi);
    return *(unsigned*)&h;
}
__device__ __forceinline__ void mma16f(float* c, unsigned a0, unsigned a1,
                                       unsigned a2, unsigned a3,
                                       unsigned b0, unsigned b1) {
    asm volatile(
        "mma.sync.aligned.m16n8k16.row.col.f32.f16.f16.f32 "
        "{%0,%1,%2,%3},{%4,%5,%6,%7},{%8,%9},{%0,%1,%2,%3};"
        : "+f"(c[0]), "+f"(c[1]), "+f"(c[2]), "+f"(c[3])
        : "r"(a0), "r"(a1), "r"(a2), "r"(a3), "r"(b0), "r"(b1));
}
__device__ __forceinline__ void cpa16(void* dst_smem, const void* src) {
    unsigned a = (unsigned)__cvta_generic_to_shared(dst_smem);
    asm volatile("cp.async.cg.shared.global [%0], [%1], 16;\n" :: "r"(a), "l"(src));
}
__device__ __forceinline__ void cp_commit() { asm volatile("cp.async.commit_group;\n"); }
__device__ __forceinline__ void cp_wait0()  { asm volatile("cp.async.wait_group 0;\n"); }
__device__ __forceinline__ void cp_wait1()  { asm volatile("cp.async.wait_group 1;\n"); }
__device__ __forceinline__ void cp_wait2()  { asm volatile("cp.async.wait_group 2;\n"); }

__device__ __forceinline__ int win_src_row(int gr) {
    int b = gr >> 13, rem = gr & 8191;
    int w4 = rem >> 11, p = rem & 2047;
    int wi = w4 >> 1, wj = w4 & 1;
    int iy = p >> 6, ix = p & 63;
    int y = (wi * 32 + iy + 16) & 63;
    int x = (wj * 64 + ix + 32) & 127;
    return (b << 13) + (y << 7) + x;
}

// ---------------- K0: pack inputs/weights to fp16 --------------------------
#define SRCU  2097152
__global__ void k_prep(const float* __restrict__ src, const float* __restrict__ tgt,
                       const float* __restrict__ W1, const float* __restrict__ W2,
                       const float* __restrict__ Wq, const float* __restrict__ Wk,
                       const float* __restrict__ Wv, const float* __restrict__ Wm) {
    int i = blockIdx.x * 256 + threadIdx.x;
    if (i < SRCU) {
        float2 v = ((const float2*)src)[i];
        g_srch[i] = phf(v.x, v.y);
        float2 t = ((const float2*)tgt)[i];
        g_tgth[i] = phf(t.x, t.y);
    } else {
        int j = i - SRCU;
        if (j < 32768) {
            int sel = j >> 13, r = j & 8191;
            int n = r >> 6, kp = r & 63;
            const float* W = (sel == 0) ? Wq : (sel == 1) ? Wk : (sel == 2) ? Wv : Wm;
            g_Wqkvh[sel * 8192 + n * 64 + kp] = phf(W[2 * kp * 128 + n], W[(2 * kp + 1) * 128 + n]);
        } else if (j < 32768 + 131072) {
            int jj = j - 32768;
            int n = jj >> 7, kp = jj & 127;
            g_W1h[n * 128 + kp] = phf(W1[2 * kp * 1024 + n], W1[(2 * kp + 1) * 1024 + n]);
        } else if (j < 32768 + 131072 + 65536) {
            int jj = j - 32768 - 131072;
            int n = jj >> 9, kp = jj & 511;
            g_W2h[n * 512 + kp] = phf(W2[2 * kp * 128 + n], W2[(2 * kp + 1) * 128 + n]);
        }
    }
}

// ============ shared fp16 dense-GEMM mainloop (tile 128x128) ===============
// smem: Ast 2x[128][36], Bst 2x[128][36]. k-chunk = 64 halfs (32 u32).
__device__ __forceinline__ void stage_ab(unsigned* Ast, unsigned* Bst, int buf,
                                         const unsigned* A1, const unsigned* A2, int swc,
                                         int aKu, const unsigned* Bg, int bKu, int c, int tid) {
    const unsigned* asrc = (c < swc) ? A1 + c * 32 : A2 + (c - swc) * 32;
    for (int i = tid; i < 1024; i += 256) {
        int r = i >> 3, q = i & 7;
        cpa16(Ast + buf * 4608 + r * 36 + q * 4, asrc + (size_t)r * aKu + q * 4);
    }
    for (int i = tid; i < 1024; i += 256) {
        int n = i >> 3, q = i & 7;
        cpa16(Bst + buf * 4608 + n * 36 + q * 4, Bg + (size_t)n * bKu + c * 32 + q * 4);
    }
}

__device__ __forceinline__ void gemm_h(unsigned* sm, const unsigned* A1, const unsigned* A2,
                                       int swc, int aKu, const unsigned* Bg, int bKu,
                                       int nch, float acc[2][8][4]) {
    const int tid = threadIdx.x;
    const int warp = tid >> 5, lane = tid & 31, g = lane >> 2, t4 = lane & 3;
    const int rb = (warp >> 1) * 32, cb = (warp & 1) * 64;
    unsigned* Ast = sm;
    unsigned* Bst = sm + 9216;

#pragma unroll
    for (int mt = 0; mt < 2; mt++)
#pragma unroll
        for (int nt = 0; nt < 8; nt++)
            acc[mt][nt][0] = acc[mt][nt][1] = acc[mt][nt][2] = acc[mt][nt][3] = 0.f;

    stage_ab(Ast, Bst, 0, A1, A2, swc, aKu, Bg, bKu, 0, tid);
    cp_commit();

#pragma unroll 1
    for (int c = 0; c < nch; c++) {
        const int st = c & 1;
        if (c > 0) __syncthreads();
        if (c + 1 < nch) stage_ab(Ast, Bst, st ^ 1, A1, A2, swc, aKu, Bg, bKu, c + 1, tid);
        cp_commit();
        cp_wait1();
        __syncthreads();

        const unsigned* As = Ast + st * 4608;
        const unsigned* Bs = Bst + st * 4608;
#pragma unroll
        for (int ko = 0; ko < 4; ko++) {
            unsigned a00 = As[(rb + g) * 36 + ko * 8 + t4];
            unsigned a01 = As[(rb + 8 + g) * 36 + ko * 8 + t4];
            unsigned a02 = As[(rb + g) * 36 + ko * 8 + 4 + t4];
            unsigned a03 = As[(rb + 8 + g) * 36 + ko * 8 + 4 + t4];
            unsigned a10 = As[(rb + 16 + g) * 36 + ko * 8 + t4];
            unsigned a11 = As[(rb + 24 + g) * 36 + ko * 8 + t4];
            unsigned a12 = As[(rb + 16 + g) * 36 + ko * 8 + 4 + t4];
            unsigned a13 = As[(rb + 24 + g) * 36 + ko * 8 + 4 + t4];
#pragma unroll
            for (int nt = 0; nt < 8; nt++) {
                unsigned b0 = Bs[(cb + nt * 8 + g) * 36 + ko * 8 + t4];
                unsigned b1 = Bs[(cb + nt * 8 + g) * 36 + ko * 8 + 4 + t4];
                mma16f(acc[0][nt], a00, a01, a02, a03, b0, b1);
                mma16f(acc[1][nt], a10, a11, a12, a13, b0, b1);
            }
        }
    }
}

// ---------------- K1: merged QKV (A resident). grid 256 x 256 --------------
__device__ __forceinline__ void qkv_compute(const unsigned* As, const unsigned* Bs,
                                            float acc[2][8][4], int rb, int cb, int g, int t4) {
#pragma unroll
    for (int mt = 0; mt < 2; mt++)
#pragma unroll
        for (int nt = 0; nt < 8; nt++)
            acc[mt][nt][0] = acc[mt][nt][1] = acc[mt][nt][2] = acc[mt][nt][3] = 0.f;
#pragma unroll
    for (int ko = 0; ko < 8; ko++) {
        unsigned a00 = As[(rb + g) * 68 + ko * 8 + t4];
        unsigned a01 = As[(rb + 8 + g) * 68 + ko * 8 + t4];
        unsigned a02 = As[(rb + g) * 68 + ko * 8 + 4 + t4];
        unsigned a03 = As[(rb + 8 + g) * 68 + ko * 8 + 4 + t4];
        unsigned a10 = As[(rb + 16 + g) * 68 + ko * 8 + t4];
        unsigned a11 = As[(rb + 24 + g) * 68 + ko * 8 + t4];
        unsigned a12 = As[(rb + 16 + g) * 68 + ko * 8 + 4 + t4];
        unsigned a13 = As[(rb + 24 + g) * 68 + ko * 8 + 4 + t4];
#pragma unroll
        for (int nt = 0; nt < 8; nt++) {
            unsigned b0 = Bs[(cb + nt * 8 + g) * 68 + ko * 8 + t4];
            unsigned b1 = Bs[(cb + nt * 8 + g) * 68 + ko * 8 + 4 + t4];
            mma16f(acc[0][nt], a00, a01, a02, a03, b0, b1);
            mma16f(acc[1][nt], a10, a11, a12, a13, b0, b1);
        }
    }
}

__global__ __launch_bounds__(256, 2) void k_qkv() {
    extern __shared__ unsigned sm[];
    unsigned* As  = sm;                 // [128][68]
    unsigned* Bst = sm + 8704;          // 2 x [128][68]
    int* rows     = (int*)(Bst + 17408);

    const int tid = threadIdx.x, tile = blockIdx.x;
    const int warp = tid >> 5, lane = tid & 31, g = lane >> 2, t4 = lane & 3;
    const int rb = (warp >> 1) * 32, cb = (warp & 1) * 64;

    if (tid < 128) rows[tid] = win_src_row(tile * 128 + tid);
    __syncthreads();

    // A(tgt) + B0(Wk)
    for (int i = tid; i < 2048; i += 256) {
        int r = i >> 4, q = i & 15;
        cpa16(As + r * 68 + q * 4, g_tgth + (size_t)rows[r] * 64 + q * 4);
    }
    for (int i = tid; i < 2048; i += 256) {
        int n = i >> 4, q = i & 15;
        cpa16(Bst + n * 68 + q * 4, g_Wqkvh + 8192 + n * 64 + q * 4);
    }
    cp_commit();
    // B1(Wv)
    for (int i = tid; i < 2048; i += 256) {
        int n = i >> 4, q = i & 15;
        cpa16(Bst + 8704 + n * 68 + q * 4, g_Wqkvh + 16384 + n * 64 + q * 4);
    }
    cp_commit();
    cp_wait1();
    __syncthreads();

    float acc[2][8][4];
    qkv_compute(As, Bst, acc, rb, cb, g, t4);      // K
#pragma unroll
    for (int mt = 0; mt < 2; mt++) {
        int row0 = tile * 128 + rb + mt * 16 + g, row1 = row0 + 8;
#pragma unroll
        for (int nt = 0; nt < 8; nt++) {
            int uc = (cb >> 1) + nt * 4 + t4;
            g_Kh[(size_t)row0 * 64 + uc] = phf(acc[mt][nt][0], acc[mt][nt][1]);
            g_Kh[(size_t)row1 * 64 + uc] = phf(acc[mt][nt][2], acc[mt][nt][3]);
        }
    }
    __syncthreads();   // *** all warps done reading Wk from Bst[0] before Wq overwrites it ***

    // prefetch B0(Wq)
    for (int i = tid; i < 2048; i += 256) {
        int n = i >> 4, q = i & 15;
        cpa16(Bst + n * 68 + q * 4, g_Wqkvh + n * 64 + q * 4);
    }
    cp_commit();
    cp_wait1();
    __syncthreads();

    qkv_compute(As, Bst + 8704, acc, rb, cb, g, t4);   // V
    {
        __half* Vh = g_Vh + (size_t)(tile >> 4) * 262144;
#pragma unroll
        for (int mt = 0; mt < 2; mt++) {
            int kk = (tile * 128 + rb + mt * 16 + g) & 2047;
#pragma unroll
            for (int nt = 0; nt < 8; nt++) {
                int cc = cb + nt * 8 + 2 * t4;
                Vh[(size_t)cc * 2048 + kk]           = __float2half(acc[mt][nt][0]);
                Vh[(size_t)(cc + 1) * 2048 + kk]     = __float2half(acc[mt][nt][1]);
                Vh[(size_t)cc * 2048 + kk + 8]       = __float2half(acc[mt][nt][2]);
                Vh[(size_t)(cc + 1) * 2048 + kk + 8] = __float2half(acc[mt][nt][3]);
            }
        }
    }
    __syncthreads();   // done reading As (and Bst[1])

    // restage A(src)
    for (int i = tid; i < 2048; i += 256) {
        int r = i >> 4, q = i & 15;
        cpa16(As + r * 68 + q * 4, g_srch + (size_t)rows[r] * 64 + q * 4);
    }
    cp_commit();
    cp_wait0();
    __syncthreads();

    qkv_compute(As, Bst, acc, rb, cb, g, t4);      // Q
#pragma unroll
    for (int mt = 0; mt < 2; mt++) {
        int row0 = tile * 128 + rb + mt * 16 + g, row1 = row0 + 8;
#pragma unroll
        for (int nt = 0; nt < 8; nt++) {
            int uc = (cb >> 1) + nt * 4 + t4;
            g_Qh[(size_t)row0 * 64 + uc] = phf(acc[mt][nt][0], acc[mt][nt][1]);
            g_Qh[(size_t)row1 * 64 + uc] = phf(acc[mt][nt][2], acc[mt][nt][3]);
        }
    }
}

// ---------------- K2: flash attention, all-fp16. grid(16,16) x 256 ---------
// warp owns 16 rows x full 64 S-cols x full 128 d. P in registers.
#define AQ_W 8704   // [128][68]
#define AK_W 4352   // [64][68]
#define AV_W 4608   // [128][36]
__global__ __launch_bounds__(256, 2) void k_attn(const float* __restrict__ mask) {
    extern __shared__ unsigned sm[];
    unsigned* Qs  = sm;
    unsigned* Kst = sm + AQ_W;
    unsigned* Vs  = Kst + 2 * AK_W;

    const int tid = threadIdx.x, warp = tid >> 5, lane = tid & 31;
    const int g = lane >> 2, t4 = lane & 3;
    const int qw = warp * 16;
    const int qbase = blockIdx.x * 128, win = blockIdx.y, w4 = win & 3;

    const unsigned* Qg  = g_Qh + (size_t)(win * LL + qbase) * 64;
    const unsigned* Kgb = g_Kh + (size_t)(win * LL) * 64;
    const unsigned* Vu  = (const unsigned*)g_Vh + (size_t)win * 131072;
    const float* Mrow = mask + (size_t)w4 * LL * LL + (size_t)qbase * LL;

    for (int i = tid; i < 2048; i += 256) {
        int r = i >> 4, q = i & 15;
        cpa16(Qs + r * 68 + q * 4, Qg + (size_t)r * 64 + q * 4);
    }
    for (int i = tid; i < 1024; i += 256) {
        int r = i >> 4, q = i & 15;
        cpa16(Kst + r * 68 + q * 4, Kgb + (size_t)r * 64 + q * 4);
    }
    cp_commit();

    float o[16][4];
#pragma unroll
    for (int dt = 0; dt < 16; dt++) o[dt][0] = o[dt][1] = o[dt][2] = o[dt][3] = 0.f;
    float m0 = -1e30f, m1 = -1e30f, l0 = 0.f, l1 = 0.f;

#pragma unroll 1
    for (int kt = 0; kt < 32; kt++) {
        const int st = kt & 1;
        const int kbase = kt * 64;

        if (kt > 0) __syncthreads();                 // B0: Vs / K[st^1] reuse guard
        for (int i = tid; i < 1024; i += 256) {      // V(kt): 128 d x 8 chunks
            int d = i >> 3, q = i & 7;
            cpa16(Vs + d * 36 + q * 4, Vu + (size_t)d * 1024 + (kbase >> 1) + q * 4);
        }
        cp_commit();                                 // GV_kt
        if (kt + 1 < 32) {
            const unsigned* Kg = Kgb + (size_t)(kt + 1) * 64 * 64;
            unsigned* Kd = Kst + (st ^ 1) * AK_W;
            for (int i = tid; i < 1024; i += 256) {
                int r = i >> 4, q = i & 15;
                cpa16(Kd + r * 68 + q * 4, Kg + (size_t)r * 64 + q * 4);
            }
        }
        cp_commit();                                 // GK_{kt+1}
        cp_wait2();
        __syncthreads();                             // B1: K(kt) (and Q) visible

        const unsigned* Ks = Kst + st * AK_W;

        // ---- S = Q K^T (fp16; 16 rows x 64 cols per warp) ----
        float s[8][4];
#pragma unroll
        for (int nt = 0; nt < 8; nt++) s[nt][0] = s[nt][1] = s[nt][2] = s[nt][3] = 0.f;
#pragma unroll
        for (int d2 = 0; d2 < 64; d2 += 8) {
            unsigned a0 = Qs[(qw + g) * 68 + d2 + t4];
            unsigned a1 = Qs[(qw + 8 + g) * 68 + d2 + t4];
            unsigned a2 = Qs[(qw + g) * 68 + d2 + 4 + t4];
            unsigned a3 = Qs[(qw + 8 + g) * 68 + d2 + 4 + t4];
#pragma unroll
            for (int nt = 0; nt < 8; nt++) {
                unsigned b0 = Ks[(nt * 8 + g) * 68 + d2 + t4];
                unsigned b1 = Ks[(nt * 8 + g) * 68 + d2 + 4 + t4];
                mma16f(s[nt], a0, a1, a2, a3, b0, b1);
            }
        }

        // ---- scale + mask + row max (warp-local rows) ----
        float ml0 = -1e30f, ml1 = -1e30f;
#pragma unroll
        for (int nt = 0; nt < 8; nt++) {
            int col = nt * 8 + 2 * t4;
            float2 ma = __ldg((const float2*)(Mrow + (size_t)(qw + g) * LL + kbase + col));
            float2 mb = __ldg((const float2*)(Mrow + (size_t)(qw + 8 + g) * LL + kbase + col));
            s[nt][0] = s[nt][0] * ATT_SCALE + ma.x;
            s[nt][1] = s[nt][1] * ATT_SCALE + ma.y;
            s[nt][2] = s[nt][2] * ATT_SCALE + mb.x;
            s[nt][3] = s[nt][3] * ATT_SCALE + mb.y;
            ml0 = fmaxf(ml0, fmaxf(s[nt][0], s[nt][1]));
            ml1 = fmaxf(ml1, fmaxf(s[nt][2], s[nt][3]));
        }
        ml0 = fmaxf(ml0, __shfl_xor_sync(~0u, ml0, 1));
        ml0 = fmaxf(ml0, __shfl_xor_sync(~0u, ml0, 2));
        ml1 = fmaxf(ml1, __shfl_xor_sync(~0u, ml1, 1));
        ml1 = fmaxf(ml1, __shfl_xor_sync(~0u, ml1, 2));

        float mn0 = fmaxf(m0, ml0), mn1 = fmaxf(m1, ml1);
        float al0 = __expf(m0 - mn0), al1 = __expf(m1 - mn1);
        m0 = mn0; m1 = mn1;

        // ---- exp; P packed straight into A-fragments ----
        float rs0 = 0.f, rs1 = 0.f;
        unsigned ph0[8], ph1[8];
#pragma unroll
        for (int nt = 0; nt < 8; nt++) {
            float p0 = __expf(s[nt][0] - mn0);
            float p1 = __expf(s[nt][1] - mn0);
            float p2 = __expf(s[nt][2] - mn1);
            float p3 = __expf(s[nt][3] - mn1);
            rs0 += p0 + p1; rs1 += p2 + p3;
            ph0[nt] = phf(p0, p1);
            ph1[nt] = phf(p2, p3);
        }
        rs0 += __shfl_xor_sync(~0u, rs0, 1);
        rs0 += __shfl_xor_sync(~0u, rs0, 2);
        rs1 += __shfl_xor_sync(~0u, rs1, 1);
        rs1 += __shfl_xor_sync(~0u, rs1, 2);
        l0 = l0 * al0 + rs0;
        l1 = l1 * al1 + rs1;

#pragma unroll
        for (int dt = 0; dt < 16; dt++) {
            o[dt][0] *= al0; o[dt][1] *= al0;
            o[dt][2] *= al1; o[dt][3] *= al1;
        }
        cp_wait1();
        __syncthreads();                             // B3: V(kt) visible

        // ---- O += P V (fp16; P from registers, full 64 k x 128 d) ----
#pragma unroll
        for (int ko = 0; ko < 4; ko++) {
            unsigned a0 = ph0[2 * ko], a1 = ph1[2 * ko];
            unsigned a2 = ph0[2 * ko + 1], a3 = ph1[2 * ko + 1];
#pragma unroll
            for (int dt = 0; dt < 16; dt++) {
                unsigned b0 = Vs[(dt * 8 + g) * 36 + ko * 8 + t4];
                unsigned b1 = Vs[(dt * 8 + g) * 36 + ko * 8 + 4 + t4];
                mma16f(o[dt], a0, a1, a2, a3, b0, b1);
            }
        }
    }

    float i0 = 1.f / l0, i1 = 1.f / l1;
    int row0 = win_src_row(win * LL + qbase + qw + g);
    int row1 = win_src_row(win * LL + qbase + qw + 8 + g);
#pragma unroll
    for (int dt = 0; dt < 16; dt++) {
        int uc = dt * 4 + t4;
        g_attnh[(size_t)row0 * 64 + uc] = phf(o[dt][0] * i0, o[dt][1] * i0);
        g_attnh[(size_t)row1 * 64 + uc] = phf(o[dt][2] * i1, o[dt][3] * i1);
    }
}

// ---------------- K3: message = LN(attn @ Wm). grid 256 x 256 --------------
__global__ __launch_bounds__(256, 2) void k_wm_ln(const float* __restrict__ g1,
                                                  const float* __restrict__ b1) {
    extern __shared__ unsigned sm[];
    float* Rs = (float*)sm;

    const int tid = threadIdx.x, tile = blockIdx.x;
    const int warp = tid >> 5, lane = tid & 31, g = lane >> 2, t4 = lane & 3;
    const int rb = (warp >> 1) * 32, cb = (warp & 1) * 64;

    float acc[2][8][4];
    gemm_h(sm, g_attnh + (size_t)tile * 128 * 64, 0, 99, 64,
           g_Wqkvh + 24576, 64, 2, acc);

    __syncthreads();
#pragma unroll
    for (int mt = 0; mt < 2; mt++) {
        int r0 = rb + mt * 16 + g;
#pragma unroll
        for (int nt = 0; nt < 8; nt++) {
            int cc = cb + nt * 8 + 2 * t4;
            Rs[r0 * 132 + cc]           = acc[mt][nt][0];
            Rs[r0 * 132 + cc + 1]       = acc[mt][nt][1];
            Rs[(r0 + 8) * 132 + cc]     = acc[mt][nt][2];
            Rs[(r0 + 8) * 132 + cc + 1] = acc[mt][nt][3];
        }
    }
    __syncthreads();

    int row = tid >> 1, half = tid & 1;
    float sum = 0.f, sq = 0.f;
    for (int j = 0; j < 64; j++) {
        float v = Rs[row * 132 + half * 64 + j];
        sum += v; sq += v * v;
    }
    sum += __shfl_xor_sync(~0u, sum, 1);
    sq  += __shfl_xor_sync(~0u, sq, 1);
    float mean = sum * 0.0078125f;
    float rstd = rsqrtf(sq * 0.0078125f - mean * mean + 1e-5f);
    size_t orow = (size_t)(tile * 128 + row) * 64 + half * 32;
    for (int j = 0; j < 32; j++) {
        int c0 = half * 64 + 2 * j;
        float v0 = (Rs[row * 132 + c0] - mean) * rstd * g1[c0] + b1[c0];
        float v1 = (Rs[row * 132 + c0 + 1] - mean) * rstd * g1[c0 + 1] + b1[c0 + 1];
        g_msgh[orow + j] = phf(v0, v1);
    }
}

// ---------------- K4: hidden = gelu([src|msg] @ W1). grid(8,256) x 256 -----
__global__ __launch_bounds__(256, 2) void k_mlp1() {
    extern __shared__ unsigned sm[];
    const int tid = threadIdx.x, nb = blockIdx.x * 128, tile = blockIdx.y;
    const int warp = tid >> 5, lane = tid & 31, g = lane >> 2, t4 = lane & 3;
    const int rb = (warp >> 1) * 32, cb = (warp & 1) * 64;

    float acc[2][8][4];
    gemm_h(sm, g_srch + (size_t)tile * 128 * 64, g_msgh + (size_t)tile * 128 * 64,
           2, 64, g_W1h + (size_t)nb * 128, 128, 4, acc);

#pragma unroll
    for (int mt = 0; mt < 2; mt++) {
        int row0 = tile * 128 + rb + mt * 16 + g, row1 = row0 + 8;
#pragma unroll
        for (int nt = 0; nt < 8; nt++) {
            int uc = (nb >> 1) + (cb >> 1) + nt * 4 + t4;
            float x0 = acc[mt][nt][0], x1 = acc[mt][nt][1];
            float x2 = acc[mt][nt][2], x3 = acc[mt][nt][3];
            x0 = 0.5f * x0 * (1.f + erff(x0 * 0.70710678f));
            x1 = 0.5f * x1 * (1.f + erff(x1 * 0.70710678f));
            x2 = 0.5f * x2 * (1.f + erff(x2 * 0.70710678f));
            x3 = 0.5f * x3 * (1.f + erff(x3 * 0.70710678f));
            g_hidh[(size_t)row0 * 512 + uc] = phf(x0, x1);
            g_hidh[(size_t)row1 * 512 + uc] = phf(x2, x3);
        }
    }
}

// ---------------- K5: out = src + LN(hidden @ W2). grid 256 x 256 ----------
__global__ __launch_bounds__(256, 2) void k_mlp2(const float* __restrict__ src,
                                                 const float* __restrict__ g2,
                                                 const float* __restrict__ b2,
                                                 float* __restrict__ out) {
    extern __shared__ unsigned sm[];
    float* Rs = (float*)sm;
    const int tid = threadIdx.x, tile = blockIdx.x;
    const int warp = tid >> 5, lane = tid & 31, g = lane >> 2, t4 = lane & 3;
    const int rb = (warp >> 1) * 32, cb = (warp & 1) * 64;

    float acc[2][8][4];
    gemm_h(sm, g_hidh + (size_t)tile * 128 * 512, 0, 99, 512, g_W2h, 512, 16, acc);

    __syncthreads();
#pragma unroll
    for (int mt = 0; mt < 2; mt++) {
        int r0 = rb + mt * 16 + g;
#pragma unroll
        for (int nt = 0; nt < 8; nt++) {
            int cc = cb + nt * 8 + 2 * t4;
            Rs[r0 * 132 + cc]           = acc[mt][nt][0];
            Rs[r0 * 132 + cc + 1]       = acc[mt][nt][1];
            Rs[(r0 + 8) * 132 + cc]     = acc[mt][nt][2];
            Rs[(r0 + 8) * 132 + cc + 1] = acc[mt][nt][3];
        }
    }
    __syncthreads();

    int row = tid >> 1, half = tid & 1;
    float sum = 0.f, sq = 0.f;
    for (int j = 0; j < 64; j++) {
        float v = Rs[row * 132 + half * 64 + j];
        sum += v; sq += v * v;
    }
    sum += __shfl_xor_sync(~0u, sum, 1);
    sq  += __shfl_xor_sync(~0u, sq, 1);
    float mean = sum * 0.0078125f;
    float rstd = rsqrtf(sq * 0.0078125f - mean * mean + 1e-5f);
    size_t grow = (size_t)(tile * 128 + row) * 128 + half * 64;
    for (int j = 0; j < 64; j += 2) {
        int cc = half * 64 + j;
        float2 sv = *(const float2*)(src + grow + j);
        float2 ov;
        ov.x = sv.x + (Rs[row * 132 + cc] - mean) * rstd * g2[cc] + b2[cc];
        ov.y = sv.y + (Rs[row * 132 + cc + 1] - mean) * rstd * g2[cc + 1] + b2[cc + 1];
        *(float2*)(out + grow + j) = ov;
    }
}

extern "C" void kernel_launch(void* const* d_in, const int* in_sizes, int n_in,
                              void* d_out, int out_size) {
    (void)in_sizes; (void)n_in; (void)out_size;
    const float* src  = (const float*)d_in[0];
    const float* tgt  = (const float*)d_in[1];
    const float* mask = (const float*)d_in[2];
    const float* Wq   = (const float*)d_in[8];
    const float* Wk   = (const float*)d_in[9];
    const float* Wv   = (const float*)d_in[10];
    const float* Wm   = (const float*)d_in[11];
    const float* g1   = (const float*)d_in[12];
    const float* b1   = (const float*)d_in[13];
    const float* W1   = (const float*)d_in[14];
    const float* W2   = (const float*)d_in[15];
    const float* g2   = (const float*)d_in[16];
    const float* b2   = (const float*)d_in[17];
    float* out = (float*)d_out;

    const int SMQ = (8704 + 2 * 8704 + 128) * 4;             // 104960
    const int SMA = (AQ_W + 2 * AK_W + AV_W) * 4;            // 88064
    const int SMG = 18432 * 4;                               // 73728

    cudaFuncSetAttribute(k_qkv,   cudaFuncAttributeMaxDynamicSharedMemorySize, SMQ);
    cudaFuncSetAttribute(k_attn,  cudaFuncAttributeMaxDynamicSharedMemorySize, SMA);
    cudaFuncSetAttribute(k_wm_ln, cudaFuncAttributeMaxDynamicSharedMemorySize, SMG);
    cudaFuncSetAttribute(k_mlp1,  cudaFuncAttributeMaxDynamicSharedMemorySize, SMG);
    cudaFuncSetAttribute(k_mlp2,  cudaFuncAttributeMaxDynamicSharedMemorySize, SMG);

    k_prep <<<9089, 256>>>(src, tgt, W1, W2, Wq, Wk, Wv, Wm);
    k_qkv  <<<256,          256, SMQ>>>();
    k_attn <<<dim3(16, 16), 256, SMA>>>(mask);
    k_wm_ln<<<256,          256, SMG>>>(g1, b1);
    k_mlp1 <<<dim3(8, 256), 256, SMG>>>();
    k_mlp2 <<<256,          256, SMG>>>(src, g2, b2, out);
}

// round 12
// speedup vs baseline: 4.2395x; 1.0370x over previous
#include <cuda_runtime.h>
#include <cuda_fp16.h>
#include <math.h>

#define TOK   32768
#define LL    2048
#define ATT_SCALE 0.08838834764831845f

// All operands packed fp16 (u32 = half2 pair along k/cols).
__device__ unsigned g_srch[TOK * 64];
__device__ unsigned g_tgth[TOK * 64];
__device__ unsigned g_msgh[TOK * 64];
__device__ unsigned g_Qh[TOK * 64];
__device__ unsigned g_Kh[TOK * 64];
__device__ __half   g_Vh[(size_t)TOK * 128];   // [win][d=128][k=2048]
__device__ unsigned g_attnh[TOK * 64];
__device__ unsigned g_hidh[(size_t)TOK * 512];
__device__ unsigned g_Wqkvh[4 * 8192];         // [Wq|Wk|Wv|Wm], each [n=128][k/2=64]
__device__ unsigned g_W1h[1024 * 128];         // [n][k/2]
__device__ unsigned g_W2h[128 * 512];          // [n][k/2]

__device__ __forceinline__ unsigned phf(float lo, float hi) {
    __half2 h = __floats2half2_rn(lo, hi);
    return *(unsigned*)&h;
}
__device__ __forceinline__ void mma16f(float* c, unsigned a0, unsigned a1,
                                       unsigned a2, unsigned a3,
                                       unsigned b0, unsigned b1) {
    asm volatile(
        "mma.sync.aligned.m16n8k16.row.col.f32.f16.f16.f32 "
        "{%0,%1,%2,%3},{%4,%5,%6,%7},{%8,%9},{%0,%1,%2,%3};"
        : "+f"(c[0]), "+f"(c[1]), "+f"(c[2]), "+f"(c[3])
        : "r"(a0), "r"(a1), "r"(a2), "r"(a3), "r"(b0), "r"(b1));
}
__device__ __forceinline__ void ldm4(unsigned* r, unsigned addr) {
    asm volatile("ldmatrix.sync.aligned.m8n8.x4.shared.b16 {%0,%1,%2,%3}, [%4];"
                 : "=r"(r[0]), "=r"(r[1]), "=r"(r[2]), "=r"(r[3]) : "r"(addr));
}
__device__ __forceinline__ unsigned smu32(const void* p) {
    return (unsigned)__cvta_generic_to_shared(p);
}
__device__ __forceinline__ void cpa16(void* dst_smem, const void* src) {
    unsigned a = (unsigned)__cvta_generic_to_shared(dst_smem);
    asm volatile("cp.async.cg.shared.global [%0], [%1], 16;\n" :: "r"(a), "l"(src));
}
__device__ __forceinline__ void cp_commit() { asm volatile("cp.async.commit_group;\n"); }
__device__ __forceinline__ void cp_wait0()  { asm volatile("cp.async.wait_group 0;\n"); }
__device__ __forceinline__ void cp_wait1()  { asm volatile("cp.async.wait_group 1;\n"); }
__device__ __forceinline__ void cp_wait2()  { asm volatile("cp.async.wait_group 2;\n"); }

__device__ __forceinline__ int win_src_row(int gr) {
    int b = gr >> 13, rem = gr & 8191;
    int w4 = rem >> 11, p = rem & 2047;
    int wi = w4 >> 1, wj = w4 & 1;
    int iy = p >> 6, ix = p & 63;
    int y = (wi * 32 + iy + 16) & 63;
    int x = (wj * 64 + ix + 32) & 127;
    return (b << 13) + (y << 7) + x;
}

// ---------------- K0: pack inputs/weights to fp16 --------------------------
#define SRCU  2097152
__global__ void k_prep(const float* __restrict__ src, const float* __restrict__ tgt,
                       const float* __restrict__ W1, const float* __restrict__ W2,
                       const float* __restrict__ Wq, const float* __restrict__ Wk,
                       const float* __restrict__ Wv, const float* __restrict__ Wm) {
    int i = blockIdx.x * 256 + threadIdx.x;
    if (i < SRCU) {
        float2 v = ((const float2*)src)[i];
        g_srch[i] = phf(v.x, v.y);
        float2 t = ((const float2*)tgt)[i];
        g_tgth[i] = phf(t.x, t.y);
    } else {
        int j = i - SRCU;
        if (j < 32768) {
            int sel = j >> 13, r = j & 8191;
            int n = r >> 6, kp = r & 63;
            const float* W = (sel == 0) ? Wq : (sel == 1) ? Wk : (sel == 2) ? Wv : Wm;
            g_Wqkvh[sel * 8192 + n * 64 + kp] = phf(W[2 * kp * 128 + n], W[(2 * kp + 1) * 128 + n]);
        } else if (j < 32768 + 131072) {
            int jj = j - 32768;
            int n = jj >> 7, kp = jj & 127;
            g_W1h[n * 128 + kp] = phf(W1[2 * kp * 1024 + n], W1[(2 * kp + 1) * 1024 + n]);
        } else if (j < 32768 + 131072 + 65536) {
            int jj = j - 32768 - 131072;
            int n = jj >> 9, kp = jj & 511;
            g_W2h[n * 512 + kp] = phf(W2[2 * kp * 128 + n], W2[(2 * kp + 1) * 128 + n]);
        }
    }
}

// ============ shared fp16 dense-GEMM mainloop (tile 128x128) ===============
__device__ __forceinline__ void stage_ab(unsigned* Ast, unsigned* Bst, int buf,
                                         const unsigned* A1, const unsigned* A2, int swc,
                                         int aKu, const unsigned* Bg, int bKu, int c, int tid) {
    const unsigned* asrc = (c < swc) ? A1 + c * 32 : A2 + (c - swc) * 32;
    for (int i = tid; i < 1024; i += 256) {
        int r = i >> 3, q = i & 7;
        cpa16(Ast + buf * 4608 + r * 36 + q * 4, asrc + (size_t)r * aKu + q * 4);
    }
    for (int i = tid; i < 1024; i += 256) {
        int n = i >> 3, q = i & 7;
        cpa16(Bst + buf * 4608 + n * 36 + q * 4, Bg + (size_t)n * bKu + c * 32 + q * 4);
    }
}

__device__ __forceinline__ void gemm_h(unsigned* sm, const unsigned* A1, const unsigned* A2,
                                       int swc, int aKu, const unsigned* Bg, int bKu,
                                       int nch, float acc[2][8][4]) {
    const int tid = threadIdx.x;
    const int warp = tid >> 5, lane = tid & 31;
    const int rb = (warp >> 1) * 32, cb = (warp & 1) * 64;
    const int mat = lane >> 3, rid = lane & 7;
    const int arow = rb + ((mat & 1) << 3) + rid;     // A m-tile 0 row
    const int akoff = (mat & 2) ? 4 : 0;
    const int brow = ((mat >> 1) << 3) + rid;          // B intra-pair row
    const int bkoff = (mat & 1) ? 4 : 0;
    unsigned* Ast = sm;
    unsigned* Bst = sm + 9216;
    const unsigned Abase = smu32(Ast), Bbase = smu32(Bst);

#pragma unroll
    for (int mt = 0; mt < 2; mt++)
#pragma unroll
        for (int nt = 0; nt < 8; nt++)
            acc[mt][nt][0] = acc[mt][nt][1] = acc[mt][nt][2] = acc[mt][nt][3] = 0.f;

    stage_ab(Ast, Bst, 0, A1, A2, swc, aKu, Bg, bKu, 0, tid);
    cp_commit();

#pragma unroll 1
    for (int c = 0; c < nch; c++) {
        const int st = c & 1;
        if (c > 0) __syncthreads();
        if (c + 1 < nch) stage_ab(Ast, Bst, st ^ 1, A1, A2, swc, aKu, Bg, bKu, c + 1, tid);
        cp_commit();
        cp_wait1();
        __syncthreads();

        const unsigned Aa = Abase + st * 18432;
        const unsigned Ba = Bbase + st * 18432;
#pragma unroll
        for (int ko = 0; ko < 4; ko++) {
            unsigned A0[4], A1r[4];
            ldm4(A0,  Aa + ((arow * 36 + ko * 8 + akoff) << 2));
            ldm4(A1r, Aa + (((arow + 16) * 36 + ko * 8 + akoff) << 2));
#pragma unroll
            for (int ntp = 0; ntp < 4; ntp++) {
                unsigned B[4];
                ldm4(B, Ba + (((cb + ntp * 16 + brow) * 36 + ko * 8 + bkoff) << 2));
                mma16f(acc[0][2 * ntp],     A0[0], A0[1], A0[2], A0[3], B[0], B[1]);
                mma16f(acc[1][2 * ntp],     A1r[0], A1r[1], A1r[2], A1r[3], B[0], B[1]);
                mma16f(acc[0][2 * ntp + 1], A0[0], A0[1], A0[2], A0[3], B[2], B[3]);
                mma16f(acc[1][2 * ntp + 1], A1r[0], A1r[1], A1r[2], A1r[3], B[2], B[3]);
            }
        }
    }
}

// ---------------- K1: merged QKV (A resident). grid 256 x 256 --------------
__device__ __forceinline__ void qkv_compute(unsigned Aa, unsigned Ba,
                                            float acc[2][8][4], int rb, int cb, int lane) {
    const int mat = lane >> 3, rid = lane & 7;
    const int arow = rb + ((mat & 1) << 3) + rid;
    const int akoff = (mat & 2) ? 4 : 0;
    const int brow = ((mat >> 1) << 3) + rid;
    const int bkoff = (mat & 1) ? 4 : 0;
#pragma unroll
    for (int mt = 0; mt < 2; mt++)
#pragma unroll
        for (int nt = 0; nt < 8; nt++)
            acc[mt][nt][0] = acc[mt][nt][1] = acc[mt][nt][2] = acc[mt][nt][3] = 0.f;
#pragma unroll
    for (int ko = 0; ko < 8; ko++) {
        unsigned A0[4], A1r[4];
        ldm4(A0,  Aa + ((arow * 68 + ko * 8 + akoff) << 2));
        ldm4(A1r, Aa + (((arow + 16) * 68 + ko * 8 + akoff) << 2));
#pragma unroll
        for (int ntp = 0; ntp < 4; ntp++) {
            unsigned B[4];
            ldm4(B, Ba + (((cb + ntp * 16 + brow) * 68 + ko * 8 + bkoff) << 2));
            mma16f(acc[0][2 * ntp],     A0[0], A0[1], A0[2], A0[3], B[0], B[1]);
            mma16f(acc[1][2 * ntp],     A1r[0], A1r[1], A1r[2], A1r[3], B[0], B[1]);
            mma16f(acc[0][2 * ntp + 1], A0[0], A0[1], A0[2], A0[3], B[2], B[3]);
            mma16f(acc[1][2 * ntp + 1], A1r[0], A1r[1], A1r[2], A1r[3], B[2], B[3]);
        }
    }
}

__global__ __launch_bounds__(256, 2) void k_qkv() {
    extern __shared__ unsigned sm[];
    unsigned* As  = sm;                 // [128][68]
    unsigned* Bst = sm + 8704;          // 2 x [128][68]
    int* rows     = (int*)(Bst + 17408);

    const int tid = threadIdx.x, tile = blockIdx.x;
    const int warp = tid >> 5, lane = tid & 31, g = lane >> 2, t4 = lane & 3;
    const int rb = (warp >> 1) * 32, cb = (warp & 1) * 64;
    const unsigned Aa = smu32(As), Ba = smu32(Bst);

    if (tid < 128) rows[tid] = win_src_row(tile * 128 + tid);
    __syncthreads();

    for (int i = tid; i < 2048; i += 256) {
        int r = i >> 4, q = i & 15;
        cpa16(As + r * 68 + q * 4, g_tgth + (size_t)rows[r] * 64 + q * 4);
    }
    for (int i = tid; i < 2048; i += 256) {
        int n = i >> 4, q = i & 15;
        cpa16(Bst + n * 68 + q * 4, g_Wqkvh + 8192 + n * 64 + q * 4);
    }
    cp_commit();
    for (int i = tid; i < 2048; i += 256) {
        int n = i >> 4, q = i & 15;
        cpa16(Bst + 8704 + n * 68 + q * 4, g_Wqkvh + 16384 + n * 64 + q * 4);
    }
    cp_commit();
    cp_wait1();
    __syncthreads();

    float acc[2][8][4];
    qkv_compute(Aa, Ba, acc, rb, cb, lane);        // K
#pragma unroll
    for (int mt = 0; mt < 2; mt++) {
        int row0 = tile * 128 + rb + mt * 16 + g, row1 = row0 + 8;
#pragma unroll
        for (int nt = 0; nt < 8; nt++) {
            int uc = (cb >> 1) + nt * 4 + t4;
            g_Kh[(size_t)row0 * 64 + uc] = phf(acc[mt][nt][0], acc[mt][nt][1]);
            g_Kh[(size_t)row1 * 64 + uc] = phf(acc[mt][nt][2], acc[mt][nt][3]);
        }
    }
    __syncthreads();   // all warps done reading Wk before Wq overwrites Bst[0]

    for (int i = tid; i < 2048; i += 256) {
        int n = i >> 4, q = i & 15;
        cpa16(Bst + n * 68 + q * 4, g_Wqkvh + n * 64 + q * 4);
    }
    cp_commit();
    cp_wait1();
    __syncthreads();

    qkv_compute(Aa, Ba + 8704 * 4, acc, rb, cb, lane);   // V
    {
        __half* Vh = g_Vh + (size_t)(tile >> 4) * 262144;
#pragma unroll
        for (int mt = 0; mt < 2; mt++) {
            int kk = (tile * 128 + rb + mt * 16 + g) & 2047;
#pragma unroll
            for (int nt = 0; nt < 8; nt++) {
                int cc = cb + nt * 8 + 2 * t4;
                Vh[(size_t)cc * 2048 + kk]           = __float2half(acc[mt][nt][0]);
                Vh[(size_t)(cc + 1) * 2048 + kk]     = __float2half(acc[mt][nt][1]);
                Vh[(size_t)cc * 2048 + kk + 8]       = __float2half(acc[mt][nt][2]);
                Vh[(size_t)(cc + 1) * 2048 + kk + 8] = __float2half(acc[mt][nt][3]);
            }
        }
    }
    __syncthreads();

    for (int i = tid; i < 2048; i += 256) {
        int r = i >> 4, q = i & 15;
        cpa16(As + r * 68 + q * 4, g_srch + (size_t)rows[r] * 64 + q * 4);
    }
    cp_commit();
    cp_wait0();
    __syncthreads();

    qkv_compute(Aa, Ba, acc, rb, cb, lane);        // Q
#pragma unroll
    for (int mt = 0; mt < 2; mt++) {
        int row0 = tile * 128 + rb + mt * 16 + g, row1 = row0 + 8;
#pragma unroll
        for (int nt = 0; nt < 8; nt++) {
            int uc = (cb >> 1) + nt * 4 + t4;
            g_Qh[(size_t)row0 * 64 + uc] = phf(acc[mt][nt][0], acc[mt][nt][1]);
            g_Qh[(size_t)row1 * 64 + uc] = phf(acc[mt][nt][2], acc[mt][nt][3]);
        }
    }
}

// ---------------- K2: flash attention, all-fp16 + ldmatrix. ----------------
#define AQ_W 8704   // [128][68]
#define AK_W 4352   // [64][68]
#define AV_W 4608   // [128][36]
__global__ __launch_bounds__(256, 2) void k_attn(const float* __restrict__ mask) {
    extern __shared__ unsigned sm[];
    unsigned* Qs  = sm;
    unsigned* Kst = sm + AQ_W;
    unsigned* Vs  = Kst + 2 * AK_W;

    const int tid = threadIdx.x, warp = tid >> 5, lane = tid & 31;
    const int g = lane >> 2, t4 = lane & 3;
    const int qw = warp * 16;
    const int qbase = blockIdx.x * 128, win = blockIdx.y, w4 = win & 3;
    const int mat = lane >> 3, rid = lane & 7;
    const int qrow = qw + ((mat & 1) << 3) + rid;
    const int akoff = (mat & 2) ? 4 : 0;
    const int brow = ((mat >> 1) << 3) + rid;
    const int bkoff = (mat & 1) ? 4 : 0;
    const unsigned Qa = smu32(Qs), Ka = smu32(Kst), Va = smu32(Vs);

    const unsigned* Qg  = g_Qh + (size_t)(win * LL + qbase) * 64;
    const unsigned* Kgb = g_Kh + (size_t)(win * LL) * 64;
    const unsigned* Vu  = (const unsigned*)g_Vh + (size_t)win * 131072;
    const float* Mrow = mask + (size_t)w4 * LL * LL + (size_t)qbase * LL;

    for (int i = tid; i < 2048; i += 256) {
        int r = i >> 4, q = i & 15;
        cpa16(Qs + r * 68 + q * 4, Qg + (size_t)r * 64 + q * 4);
    }
    for (int i = tid; i < 1024; i += 256) {
        int r = i >> 4, q = i & 15;
        cpa16(Kst + r * 68 + q * 4, Kgb + (size_t)r * 64 + q * 4);
    }
    cp_commit();

    float o[16][4];
#pragma unroll
    for (int dt = 0; dt < 16; dt++) o[dt][0] = o[dt][1] = o[dt][2] = o[dt][3] = 0.f;
    float m0 = -1e30f, m1 = -1e30f, l0 = 0.f, l1 = 0.f;

#pragma unroll 1
    for (int kt = 0; kt < 32; kt++) {
        const int st = kt & 1;
        const int kbase = kt * 64;

        if (kt > 0) __syncthreads();
        for (int i = tid; i < 1024; i += 256) {
            int d = i >> 3, q = i & 7;
            cpa16(Vs + d * 36 + q * 4, Vu + (size_t)d * 1024 + (kbase >> 1) + q * 4);
        }
        cp_commit();
        if (kt + 1 < 32) {
            const unsigned* Kg = Kgb + (size_t)(kt + 1) * 64 * 64;
            unsigned* Kd = Kst + (st ^ 1) * AK_W;
            for (int i = tid; i < 1024; i += 256) {
                int r = i >> 4, q = i & 15;
                cpa16(Kd + r * 68 + q * 4, Kg + (size_t)r * 64 + q * 4);
            }
        }
        cp_commit();
        cp_wait2();
        __syncthreads();

        const unsigned Ksa = Ka + st * (AK_W * 4);

        // ---- S = Q K^T ----
        float s[8][4];
#pragma unroll
        for (int nt = 0; nt < 8; nt++) s[nt][0] = s[nt][1] = s[nt][2] = s[nt][3] = 0.f;
#pragma unroll
        for (int d2 = 0; d2 < 64; d2 += 8) {
            unsigned A0[4];
            ldm4(A0, Qa + ((qrow * 68 + d2 + akoff) << 2));
#pragma unroll
            for (int ntp = 0; ntp < 4; ntp++) {
                unsigned B[4];
                ldm4(B, Ksa + (((ntp * 16 + brow) * 68 + d2 + bkoff) << 2));
                mma16f(s[2 * ntp],     A0[0], A0[1], A0[2], A0[3], B[0], B[1]);
                mma16f(s[2 * ntp + 1], A0[0], A0[1], A0[2], A0[3], B[2], B[3]);
            }
        }

        // ---- scale + mask + row max ----
        float ml0 = -1e30f, ml1 = -1e30f;
#pragma unroll
        for (int nt = 0; nt < 8; nt++) {
            int col = nt * 8 + 2 * t4;
            float2 ma = __ldg((const float2*)(Mrow + (size_t)(qw + g) * LL + kbase + col));
            float2 mb = __ldg((const float2*)(Mrow + (size_t)(qw + 8 + g) * LL + kbase + col));
            s[nt][0] = s[nt][0] * ATT_SCALE + ma.x;
            s[nt][1] = s[nt][1] * ATT_SCALE + ma.y;
            s[nt][2] = s[nt][2] * ATT_SCALE + mb.x;
            s[nt][3] = s[nt][3] * ATT_SCALE + mb.y;
            ml0 = fmaxf(ml0, fmaxf(s[nt][0], s[nt][1]));
            ml1 = fmaxf(ml1, fmaxf(s[nt][2], s[nt][3]));
        }
        ml0 = fmaxf(ml0, __shfl_xor_sync(~0u, ml0, 1));
        ml0 = fmaxf(ml0, __shfl_xor_sync(~0u, ml0, 2));
        ml1 = fmaxf(ml1, __shfl_xor_sync(~0u, ml1, 1));
        ml1 = fmaxf(ml1, __shfl_xor_sync(~0u, ml1, 2));

        float mn0 = fmaxf(m0, ml0), mn1 = fmaxf(m1, ml1);
        float al0 = __expf(m0 - mn0), al1 = __expf(m1 - mn1);
        m0 = mn0; m1 = mn1;

        // ---- exp; P packed into A-fragments ----
        float rs0 = 0.f, rs1 = 0.f;
        unsigned ph0[8], ph1[8];
#pragma unroll
        for (int nt = 0; nt < 8; nt++) {
            float p0 = __expf(s[nt][0] - mn0);
            float p1 = __expf(s[nt][1] - mn0);
            float p2 = __expf(s[nt][2] - mn1);
            float p3 = __expf(s[nt][3] - mn1);
            rs0 += p0 + p1; rs1 += p2 + p3;
            ph0[nt] = phf(p0, p1);
            ph1[nt] = phf(p2, p3);
        }
        rs0 += __shfl_xor_sync(~0u, rs0, 1);
        rs0 += __shfl_xor_sync(~0u, rs0, 2);
        rs1 += __shfl_xor_sync(~0u, rs1, 1);
        rs1 += __shfl_xor_sync(~0u, rs1, 2);
        l0 = l0 * al0 + rs0;
        l1 = l1 * al1 + rs1;

#pragma unroll
        for (int dt = 0; dt < 16; dt++) {
            o[dt][0] *= al0; o[dt][1] *= al0;
            o[dt][2] *= al1; o[dt][3] *= al1;
        }
        cp_wait1();
        __syncthreads();

        // ---- O += P V ----
#pragma unroll
        for (int ko = 0; ko < 4; ko++) {
            unsigned a0 = ph0[2 * ko], a1 = ph1[2 * ko];
            unsigned a2 = ph0[2 * ko + 1], a3 = ph1[2 * ko + 1];
#pragma unroll
            for (int dtp = 0; dtp < 8; dtp++) {
                unsigned B[4];
                ldm4(B, Va + (((dtp * 16 + brow) * 36 + ko * 8 + bkoff) << 2));
                mma16f(o[2 * dtp],     a0, a1, a2, a3, B[0], B[1]);
                mma16f(o[2 * dtp + 1], a0, a1, a2, a3, B[2], B[3]);
            }
        }
    }

    float i0 = 1.f / l0, i1 = 1.f / l1;
    int row0 = win_src_row(win * LL + qbase + qw + g);
    int row1 = win_src_row(win * LL + qbase + qw + 8 + g);
#pragma unroll
    for (int dt = 0; dt < 16; dt++) {
        int uc = dt * 4 + t4;
        g_attnh[(size_t)row0 * 64 + uc] = phf(o[dt][0] * i0, o[dt][1] * i0);
        g_attnh[(size_t)row1 * 64 + uc] = phf(o[dt][2] * i1, o[dt][3] * i1);
    }
}

// ---------------- K3: message = LN(attn @ Wm). grid 256 x 256 --------------
__global__ __launch_bounds__(256, 2) void k_wm_ln(const float* __restrict__ g1,
                                                  const float* __restrict__ b1) {
    extern __shared__ unsigned sm[];
    float* Rs = (float*)sm;

    const int tid = threadIdx.x, tile = blockIdx.x;
    const int warp = tid >> 5, lane = tid & 31, g = lane >> 2, t4 = lane & 3;
    const int rb = (warp >> 1) * 32, cb = (warp & 1) * 64;

    float acc[2][8][4];
    gemm_h(sm, g_attnh + (size_t)tile * 128 * 64, 0, 99, 64,
           g_Wqkvh + 24576, 64, 2, acc);

    __syncthreads();
#pragma unroll
    for (int mt = 0; mt < 2; mt++) {
        int r0 = rb + mt * 16 + g;
#pragma unroll
        for (int nt = 0; nt < 8; nt++) {
            int cc = cb + nt * 8 + 2 * t4;
            Rs[r0 * 132 + cc]           = acc[mt][nt][0];
            Rs[r0 * 132 + cc + 1]       = acc[mt][nt][1];
            Rs[(r0 + 8) * 132 + cc]     = acc[mt][nt][2];
            Rs[(r0 + 8) * 132 + cc + 1] = acc[mt][nt][3];
        }
    }
    __syncthreads();

    int row = tid >> 1, half = tid & 1;
    float sum = 0.f, sq = 0.f;
    for (int j = 0; j < 64; j++) {
        float v = Rs[row * 132 + half * 64 + j];
        sum += v; sq += v * v;
    }
    sum += __shfl_xor_sync(~0u, sum, 1);
    sq  += __shfl_xor_sync(~0u, sq, 1);
    float mean = sum * 0.0078125f;
    float rstd = rsqrtf(sq * 0.0078125f - mean * mean + 1e-5f);
    size_t orow = (size_t)(tile * 128 + row) * 64 + half * 32;
    for (int j = 0; j < 32; j++) {
        int c0 = half * 64 + 2 * j;
        float v0 = (Rs[row * 132 + c0] - mean) * rstd * g1[c0] + b1[c0];
        float v1 = (Rs[row * 132 + c0 + 1] - mean) * rstd * g1[c0 + 1] + b1[c0 + 1];
        g_msgh[orow + j] = phf(v0, v1);
    }
}

// ---------------- K4: hidden = gelu([src|msg] @ W1). grid(8,256) x 256 -----
__global__ __launch_bounds__(256, 2) void k_mlp1() {
    extern __shared__ unsigned sm[];
    const int tid = threadIdx.x, nb = blockIdx.x * 128, tile = blockIdx.y;
    const int warp = tid >> 5, lane = tid & 31, g = lane >> 2, t4 = lane & 3;
    const int rb = (warp >> 1) * 32, cb = (warp & 1) * 64;

    float acc[2][8][4];
    gemm_h(sm, g_srch + (size_t)tile * 128 * 64, g_msgh + (size_t)tile * 128 * 64,
           2, 64, g_W1h + (size_t)nb * 128, 128, 4, acc);

#pragma unroll
    for (int mt = 0; mt < 2; mt++) {
        int row0 = tile * 128 + rb + mt * 16 + g, row1 = row0 + 8;
#pragma unroll
        for (int nt = 0; nt < 8; nt++) {
            int uc = (nb >> 1) + (cb >> 1) + nt * 4 + t4;
            float x0 = acc[mt][nt][0], x1 = acc[mt][nt][1];
            float x2 = acc[mt][nt][2], x3 = acc[mt][nt][3];
            x0 = 0.5f * x0 * (1.f + erff(x0 * 0.70710678f));
            x1 = 0.5f * x1 * (1.f + erff(x1 * 0.70710678f));
            x2 = 0.5f * x2 * (1.f + erff(x2 * 0.70710678f));
            x3 = 0.5f * x3 * (1.f + erff(x3 * 0.70710678f));
            g_hidh[(size_t)row0 * 512 + uc] = phf(x0, x1);
            g_hidh[(size_t)row1 * 512 + uc] = phf(x2, x3);
        }
    }
}

// ---------------- K5: out = src + LN(hidden @ W2). grid 256 x 256 ----------
__global__ __launch_bounds__(256, 2) void k_mlp2(const float* __restrict__ src,
                                                 const float* __restrict__ g2,
                                                 const float* __restrict__ b2,
                                                 float* __restrict__ out) {
    extern __shared__ unsigned sm[];
    float* Rs = (float*)sm;
    const int tid = threadIdx.x, tile = blockIdx.x;
    const int warp = tid >> 5, lane = tid & 31, g = lane >> 2, t4 = lane & 3;
    const int rb = (warp >> 1) * 32, cb = (warp & 1) * 64;

    float acc[2][8][4];
    gemm_h(sm, g_hidh + (size_t)tile * 128 * 512, 0, 99, 512, g_W2h, 512, 16, acc);

    __syncthreads();
#pragma unroll
    for (int mt = 0; mt < 2; mt++) {
        int r0 = rb + mt * 16 + g;
#pragma unroll
        for (int nt = 0; nt < 8; nt++) {
            int cc = cb + nt * 8 + 2 * t4;
            Rs[r0 * 132 + cc]           = acc[mt][nt][0];
            Rs[r0 * 132 + cc + 1]       = acc[mt][nt][1];
            Rs[(r0 + 8) * 132 + cc]     = acc[mt][nt][2];
            Rs[(r0 + 8) * 132 + cc + 1] = acc[mt][nt][3];
        }
    }
    __syncthreads();

    int row = tid >> 1, half = tid & 1;
    float sum = 0.f, sq = 0.f;
    for (int j = 0; j < 64; j++) {
        float v = Rs[row * 132 + half * 64 + j];
        sum += v; sq += v * v;
    }
    sum += __shfl_xor_sync(~0u, sum, 1);
    sq  += __shfl_xor_sync(~0u, sq, 1);
    float mean = sum * 0.0078125f;
    float rstd = rsqrtf(sq * 0.0078125f - mean * mean + 1e-5f);
    size_t grow = (size_t)(tile * 128 + row) * 128 + half * 64;
    for (int j = 0; j < 64; j += 2) {
        int cc = half * 64 + j;
        float2 sv = *(const float2*)(src + grow + j);
        float2 ov;
        ov.x = sv.x + (Rs[row * 132 + cc] - mean) * rstd * g2[cc] + b2[cc];
        ov.y = sv.y + (Rs[row * 132 + cc + 1] - mean) * rstd * g2[cc + 1] + b2[cc + 1];
        *(float2*)(out + grow + j) = ov;
    }
}

extern "C" void kernel_launch(void* const* d_in, const int* in_sizes, int n_in,
                              void* d_out, int out_size) {
    (void)in_sizes; (void)n_in; (void)out_size;
    const float* src  = (const float*)d_in[0];
    const float* tgt  = (const float*)d_in[1];
    const float* mask = (const float*)d_in[2];
    const float* Wq   = (const float*)d_in[8];
    const float* Wk   = (const float*)d_in[9];
    const float* Wv   = (const float*)d_in[10];
    const float* Wm   = (const float*)d_in[11];
    const float* g1   = (const float*)d_in[12];
    const float* b1   = (const float*)d_in[13];
    const float* W1   = (const float*)d_in[14];
    const float* W2   = (const float*)d_in[15];
    const float* g2   = (const float*)d_in[16];
    const float* b2   = (const float*)d_in[17];
    float* out = (float*)d_out;

    const int SMQ = (8704 + 2 * 8704 + 128) * 4;             // 104960
    const int SMA = (AQ_W + 2 * AK_W + AV_W) * 4;            // 88064
    const int SMG = 18432 * 4;                               // 73728

    cudaFuncSetAttribute(k_qkv,   cudaFuncAttributeMaxDynamicSharedMemorySize, SMQ);
    cudaFuncSetAttribute(k_attn,  cudaFuncAttributeMaxDynamicSharedMemorySize, SMA);
    cudaFuncSetAttribute(k_wm_ln, cudaFuncAttributeMaxDynamicSharedMemorySize, SMG);
    cudaFuncSetAttribute(k_mlp1,  cudaFuncAttributeMaxDynamicSharedMemorySize, SMG);
    cudaFuncSetAttribute(k_mlp2,  cudaFuncAttributeMaxDynamicSharedMemorySize, SMG);

    k_prep <<<9089, 256>>>(src, tgt, W1, W2, Wq, Wk, Wv, Wm);
    k_qkv  <<<256,          256, SMQ>>>();
    k_attn <<<dim3(16, 16), 256, SMA>>>(mask);
    k_wm_ln<<<256,          256, SMG>>>(g1, b1);
    k_mlp1 <<<dim3(8, 256), 256, SMG>>>();
    k_mlp2 <<<256,          256, SMG>>>(src, g2, b2, out);
}

// round 13
// speedup vs baseline: 4.2571x; 1.0042x over previous
#include <cuda_runtime.h>
#include <cuda_fp16.h>
#include <math.h>

#define TOK   32768
#define LL    2048
#define ATT_SCALE 0.08838834764831845f

// All operands packed fp16 (u32 = half2 pair along k/cols).
__device__ unsigned g_srch[TOK * 64];
__device__ unsigned g_tgth[TOK * 64];
__device__ unsigned g_msgh[TOK * 64];
__device__ unsigned g_Qh[TOK * 64];
__device__ unsigned g_Kh[TOK * 64];
__device__ __half   g_Vh[(size_t)TOK * 128];   // [win][d=128][k=2048]
__device__ unsigned g_attnh[TOK * 64];
__device__ unsigned g_hidh[(size_t)TOK * 512];
__device__ unsigned g_Wqkvh[4 * 8192];         // [Wq|Wk|Wv|Wm], each [n=128][k/2=64]
__device__ unsigned g_W1h[1024 * 128];         // [n][k/2]
__device__ unsigned g_W2h[128 * 512];          // [n][k/2]

__device__ __forceinline__ unsigned phf(float lo, float hi) {
    __half2 h = __floats2half2_rn(lo, hi);
    return *(unsigned*)&h;
}
__device__ __forceinline__ void mma16f(float* c, unsigned a0, unsigned a1,
                                       unsigned a2, unsigned a3,
                                       unsigned b0, unsigned b1) {
    asm volatile(
        "mma.sync.aligned.m16n8k16.row.col.f32.f16.f16.f32 "
        "{%0,%1,%2,%3},{%4,%5,%6,%7},{%8,%9},{%0,%1,%2,%3};"
        : "+f"(c[0]), "+f"(c[1]), "+f"(c[2]), "+f"(c[3])
        : "r"(a0), "r"(a1), "r"(a2), "r"(a3), "r"(b0), "r"(b1));
}
__device__ __forceinline__ void ldm4(unsigned* r, unsigned addr) {
    asm volatile("ldmatrix.sync.aligned.m8n8.x4.shared.b16 {%0,%1,%2,%3}, [%4];"
                 : "=r"(r[0]), "=r"(r[1]), "=r"(r[2]), "=r"(r[3]) : "r"(addr));
}
__device__ __forceinline__ unsigned smu32(const void* p) {
    return (unsigned)__cvta_generic_to_shared(p);
}
__device__ __forceinline__ void cpa16(void* dst_smem, const void* src) {
    unsigned a = (unsigned)__cvta_generic_to_shared(dst_smem);
    asm volatile("cp.async.cg.shared.global [%0], [%1], 16;\n" :: "r"(a), "l"(src));
}
__device__ __forceinline__ void cp_commit() { asm volatile("cp.async.commit_group;\n"); }
__device__ __forceinline__ void cp_wait0()  { asm volatile("cp.async.wait_group 0;\n"); }
__device__ __forceinline__ void cp_wait1()  { asm volatile("cp.async.wait_group 1;\n"); }
__device__ __forceinline__ void cp_wait2()  { asm volatile("cp.async.wait_group 2;\n"); }

__device__ __forceinline__ int win_src_row(int gr) {
    int b = gr >> 13, rem = gr & 8191;
    int w4 = rem >> 11, p = rem & 2047;
    int wi = w4 >> 1, wj = w4 & 1;
    int iy = p >> 6, ix = p & 63;
    int y = (wi * 32 + iy + 16) & 63;
    int x = (wj * 64 + ix + 32) & 127;
    return (b << 13) + (y << 7) + x;
}

// ---------------- K0: pack inputs/weights to fp16 --------------------------
#define SRCU  2097152
__global__ void k_prep(const float* __restrict__ src, const float* __restrict__ tgt,
                       const float* __restrict__ W1, const float* __restrict__ W2,
                       const float* __restrict__ Wq, const float* __restrict__ Wk,
                       const float* __restrict__ Wv, const float* __restrict__ Wm) {
    int i = blockIdx.x * 256 + threadIdx.x;
    if (i < SRCU) {
        float2 v = ((const float2*)src)[i];
        g_srch[i] = phf(v.x, v.y);
        float2 t = ((const float2*)tgt)[i];
        g_tgth[i] = phf(t.x, t.y);
    } else {
        int j = i - SRCU;
        if (j < 32768) {
            int sel = j >> 13, r = j & 8191;
            int n = r >> 6, kp = r & 63;
            const float* W = (sel == 0) ? Wq : (sel == 1) ? Wk : (sel == 2) ? Wv : Wm;
            g_Wqkvh[sel * 8192 + n * 64 + kp] = phf(W[2 * kp * 128 + n], W[(2 * kp + 1) * 128 + n]);
        } else if (j < 32768 + 131072) {
            int jj = j - 32768;
            int n = jj >> 7, kp = jj & 127;
            g_W1h[n * 128 + kp] = phf(W1[2 * kp * 1024 + n], W1[(2 * kp + 1) * 1024 + n]);
        } else if (j < 32768 + 131072 + 65536) {
            int jj = j - 32768 - 131072;
            int n = jj >> 9, kp = jj & 511;
            g_W2h[n * 512 + kp] = phf(W2[2 * kp * 128 + n], W2[(2 * kp + 1) * 128 + n]);
        }
    }
}

// ============ shared fp16 dense-GEMM mainloop (tile 128x128) ===============
__device__ __forceinline__ void stage_ab(unsigned* Ast, unsigned* Bst, int buf,
                                         const unsigned* A1, const unsigned* A2, int swc,
                                         int aKu, const unsigned* Bg, int bKu, int c, int tid) {
    const unsigned* asrc = (c < swc) ? A1 + c * 32 : A2 + (c - swc) * 32;
    for (int i = tid; i < 1024; i += 256) {
        int r = i >> 3, q = i & 7;
        cpa16(Ast + buf * 4608 + r * 36 + q * 4, asrc + (size_t)r * aKu + q * 4);
    }
    for (int i = tid; i < 1024; i += 256) {
        int n = i >> 3, q = i & 7;
        cpa16(Bst + buf * 4608 + n * 36 + q * 4, Bg + (size_t)n * bKu + c * 32 + q * 4);
    }
}

__device__ __forceinline__ void gemm_h(unsigned* sm, const unsigned* A1, const unsigned* A2,
                                       int swc, int aKu, const unsigned* Bg, int bKu,
                                       int nch, float acc[2][8][4]) {
    const int tid = threadIdx.x;
    const int warp = tid >> 5, lane = tid & 31;
    const int rb = (warp >> 1) * 32, cb = (warp & 1) * 64;
    const int mat = lane >> 3, rid = lane & 7;
    const int arow = rb + ((mat & 1) << 3) + rid;     // A m-tile 0 row
    const int akoff = (mat & 2) ? 4 : 0;
    const int brow = ((mat >> 1) << 3) + rid;          // B intra-pair row
    const int bkoff = (mat & 1) ? 4 : 0;
    unsigned* Ast = sm;
    unsigned* Bst = sm + 9216;
    const unsigned Abase = smu32(Ast), Bbase = smu32(Bst);

#pragma unroll
    for (int mt = 0; mt < 2; mt++)
#pragma unroll
        for (int nt = 0; nt < 8; nt++)
            acc[mt][nt][0] = acc[mt][nt][1] = acc[mt][nt][2] = acc[mt][nt][3] = 0.f;

    stage_ab(Ast, Bst, 0, A1, A2, swc, aKu, Bg, bKu, 0, tid);
    cp_commit();

#pragma unroll 1
    for (int c = 0; c < nch; c++) {
        const int st = c & 1;
        if (c > 0) __syncthreads();
        if (c + 1 < nch) stage_ab(Ast, Bst, st ^ 1, A1, A2, swc, aKu, Bg, bKu, c + 1, tid);
        cp_commit();
        cp_wait1();
        __syncthreads();

        const unsigned Aa = Abase + st * 18432;
        const unsigned Ba = Bbase + st * 18432;
#pragma unroll
        for (int ko = 0; ko < 4; ko++) {
            unsigned A0[4], A1r[4];
            ldm4(A0,  Aa + ((arow * 36 + ko * 8 + akoff) << 2));
            ldm4(A1r, Aa + (((arow + 16) * 36 + ko * 8 + akoff) << 2));
#pragma unroll
            for (int ntp = 0; ntp < 4; ntp++) {
                unsigned B[4];
                ldm4(B, Ba + (((cb + ntp * 16 + brow) * 36 + ko * 8 + bkoff) << 2));
                mma16f(acc[0][2 * ntp],     A0[0], A0[1], A0[2], A0[3], B[0], B[1]);
                mma16f(acc[1][2 * ntp],     A1r[0], A1r[1], A1r[2], A1r[3], B[0], B[1]);
                mma16f(acc[0][2 * ntp + 1], A0[0], A0[1], A0[2], A0[3], B[2], B[3]);
                mma16f(acc[1][2 * ntp + 1], A1r[0], A1r[1], A1r[2], A1r[3], B[2], B[3]);
            }
        }
    }
}

// ---------------- K1: merged QKV (A resident). grid 256 x 256 --------------
__device__ __forceinline__ void qkv_compute(unsigned Aa, unsigned Ba,
                                            float acc[2][8][4], int rb, int cb, int lane) {
    const int mat = lane >> 3, rid = lane & 7;
    const int arow = rb + ((mat & 1) << 3) + rid;
    const int akoff = (mat & 2) ? 4 : 0;
    const int brow = ((mat >> 1) << 3) + rid;
    const int bkoff = (mat & 1) ? 4 : 0;
#pragma unroll
    for (int mt = 0; mt < 2; mt++)
#pragma unroll
        for (int nt = 0; nt < 8; nt++)
            acc[mt][nt][0] = acc[mt][nt][1] = acc[mt][nt][2] = acc[mt][nt][3] = 0.f;
#pragma unroll
    for (int ko = 0; ko < 8; ko++) {
        unsigned A0[4], A1r[4];
        ldm4(A0,  Aa + ((arow * 68 + ko * 8 + akoff) << 2));
        ldm4(A1r, Aa + (((arow + 16) * 68 + ko * 8 + akoff) << 2));
#pragma unroll
        for (int ntp = 0; ntp < 4; ntp++) {
            unsigned B[4];
            ldm4(B, Ba + (((cb + ntp * 16 + brow) * 68 + ko * 8 + bkoff) << 2));
            mma16f(acc[0][2 * ntp],     A0[0], A0[1], A0[2], A0[3], B[0], B[1]);
            mma16f(acc[1][2 * ntp],     A1r[0], A1r[1], A1r[2], A1r[3], B[0], B[1]);
            mma16f(acc[0][2 * ntp + 1], A0[0], A0[1], A0[2], A0[3], B[2], B[3]);
            mma16f(acc[1][2 * ntp + 1], A1r[0], A1r[1], A1r[2], A1r[3], B[2], B[3]);
        }
    }
}

__global__ __launch_bounds__(256, 2) void k_qkv() {
    extern __shared__ unsigned sm[];
    unsigned* As  = sm;                 // [128][68]
    unsigned* Bst = sm + 8704;          // 2 x [128][68]
    int* rows     = (int*)(Bst + 17408);

    const int tid = threadIdx.x, tile = blockIdx.x;
    const int warp = tid >> 5, lane = tid & 31, g = lane >> 2, t4 = lane & 3;
    const int rb = (warp >> 1) * 32, cb = (warp & 1) * 64;
    const unsigned Aa = smu32(As), Ba = smu32(Bst);

    if (tid < 128) rows[tid] = win_src_row(tile * 128 + tid);
    __syncthreads();

    for (int i = tid; i < 2048; i += 256) {
        int r = i >> 4, q = i & 15;
        cpa16(As + r * 68 + q * 4, g_tgth + (size_t)rows[r] * 64 + q * 4);
    }
    for (int i = tid; i < 2048; i += 256) {
        int n = i >> 4, q = i & 15;
        cpa16(Bst + n * 68 + q * 4, g_Wqkvh + 8192 + n * 64 + q * 4);
    }
    cp_commit();
    for (int i = tid; i < 2048; i += 256) {
        int n = i >> 4, q = i & 15;
        cpa16(Bst + 8704 + n * 68 + q * 4, g_Wqkvh + 16384 + n * 64 + q * 4);
    }
    cp_commit();
    cp_wait1();
    __syncthreads();

    float acc[2][8][4];
    qkv_compute(Aa, Ba, acc, rb, cb, lane);        // K
#pragma unroll
    for (int mt = 0; mt < 2; mt++) {
        int row0 = tile * 128 + rb + mt * 16 + g, row1 = row0 + 8;
#pragma unroll
        for (int nt = 0; nt < 8; nt++) {
            int uc = (cb >> 1) + nt * 4 + t4;
            g_Kh[(size_t)row0 * 64 + uc] = phf(acc[mt][nt][0], acc[mt][nt][1]);
            g_Kh[(size_t)row1 * 64 + uc] = phf(acc[mt][nt][2], acc[mt][nt][3]);
        }
    }
    __syncthreads();   // all warps done reading Wk before Wq overwrites Bst[0]

    for (int i = tid; i < 2048; i += 256) {
        int n = i >> 4, q = i & 15;
        cpa16(Bst + n * 68 + q * 4, g_Wqkvh + n * 64 + q * 4);
    }
    cp_commit();
    cp_wait1();
    __syncthreads();

    qkv_compute(Aa, Ba + 8704 * 4, acc, rb, cb, lane);   // V
    {
        __half* Vh = g_Vh + (size_t)(tile >> 4) * 262144;
#pragma unroll
        for (int mt = 0; mt < 2; mt++) {
            int kk = (tile * 128 + rb + mt * 16 + g) & 2047;
#pragma unroll
            for (int nt = 0; nt < 8; nt++) {
                int cc = cb + nt * 8 + 2 * t4;
                Vh[(size_t)cc * 2048 + kk]           = __float2half(acc[mt][nt][0]);
                Vh[(size_t)(cc + 1) * 2048 + kk]     = __float2half(acc[mt][nt][1]);
                Vh[(size_t)cc * 2048 + kk + 8]       = __float2half(acc[mt][nt][2]);
                Vh[(size_t)(cc + 1) * 2048 + kk + 8] = __float2half(acc[mt][nt][3]);
            }
        }
    }
    __syncthreads();

    for (int i = tid; i < 2048; i += 256) {
        int r = i >> 4, q = i & 15;
        cpa16(As + r * 68 + q * 4, g_srch + (size_t)rows[r] * 64 + q * 4);
    }
    cp_commit();
    cp_wait0();
    __syncthreads();

    qkv_compute(Aa, Ba, acc, rb, cb, lane);        // Q
#pragma unroll
    for (int mt = 0; mt < 2; mt++) {
        int row0 = tile * 128 + rb + mt * 16 + g, row1 = row0 + 8;
#pragma unroll
        for (int nt = 0; nt < 8; nt++) {
            int uc = (cb >> 1) + nt * 4 + t4;
            g_Qh[(size_t)row0 * 64 + uc] = phf(acc[mt][nt][0], acc[mt][nt][1]);
            g_Qh[(size_t)row1 * 64 + uc] = phf(acc[mt][nt][2], acc[mt][nt][3]);
        }
    }
}

// ---------------- K2: flash attention, all-fp16 + ldmatrix. ----------------
#define AQ_W 8704   // [128][68]
#define AK_W 4352   // [64][68]
#define AV_W 4608   // [128][36]
__global__ __launch_bounds__(256, 2) void k_attn(const float* __restrict__ mask) {
    extern __shared__ unsigned sm[];
    unsigned* Qs  = sm;
    unsigned* Kst = sm + AQ_W;
    unsigned* Vs  = Kst + 2 * AK_W;

    const int tid = threadIdx.x, warp = tid >> 5, lane = tid & 31;
    const int g = lane >> 2, t4 = lane & 3;
    const int qw = warp * 16;
    const int qbase = blockIdx.x * 128, win = blockIdx.y, w4 = win & 3;
    const int mat = lane >> 3, rid = lane & 7;
    const int qrow = qw + ((mat & 1) << 3) + rid;
    const int akoff = (mat & 2) ? 4 : 0;
    const int brow = ((mat >> 1) << 3) + rid;
    const int bkoff = (mat & 1) ? 4 : 0;
    const unsigned Qa = smu32(Qs), Ka = smu32(Kst), Va = smu32(Vs);

    const unsigned* Qg  = g_Qh + (size_t)(win * LL + qbase) * 64;
    const unsigned* Kgb = g_Kh + (size_t)(win * LL) * 64;
    const unsigned* Vu  = (const unsigned*)g_Vh + (size_t)win * 131072;
    const float* Mrow = mask + (size_t)w4 * LL * LL + (size_t)qbase * LL;

    for (int i = tid; i < 2048; i += 256) {
        int r = i >> 4, q = i & 15;
        cpa16(Qs + r * 68 + q * 4, Qg + (size_t)r * 64 + q * 4);
    }
    for (int i = tid; i < 1024; i += 256) {
        int r = i >> 4, q = i & 15;
        cpa16(Kst + r * 68 + q * 4, Kgb + (size_t)r * 64 + q * 4);
    }
    cp_commit();

    float o[16][4];
#pragma unroll
    for (int dt = 0; dt < 16; dt++) o[dt][0] = o[dt][1] = o[dt][2] = o[dt][3] = 0.f;
    float m0 = -1e30f, m1 = -1e30f, l0 = 0.f, l1 = 0.f;

#pragma unroll 1
    for (int kt = 0; kt < 32; kt++) {
        const int st = kt & 1;
        const int kbase = kt * 64;

        if (kt > 0) __syncthreads();
        for (int i = tid; i < 1024; i += 256) {
            int d = i >> 3, q = i & 7;
            cpa16(Vs + d * 36 + q * 4, Vu + (size_t)d * 1024 + (kbase >> 1) + q * 4);
        }
        cp_commit();
        if (kt + 1 < 32) {
            const unsigned* Kg = Kgb + (size_t)(kt + 1) * 64 * 64;
            unsigned* Kd = Kst + (st ^ 1) * AK_W;
            for (int i = tid; i < 1024; i += 256) {
                int r = i >> 4, q = i & 15;
                cpa16(Kd + r * 68 + q * 4, Kg + (size_t)r * 64 + q * 4);
            }
        }
        cp_commit();
        cp_wait2();
        __syncthreads();

        const unsigned Ksa = Ka + st * (AK_W * 4);

        // ---- S = Q K^T ----
        float s[8][4];
#pragma unroll
        for (int nt = 0; nt < 8; nt++) s[nt][0] = s[nt][1] = s[nt][2] = s[nt][3] = 0.f;
#pragma unroll
        for (int d2 = 0; d2 < 64; d2 += 8) {
            unsigned A0[4];
            ldm4(A0, Qa + ((qrow * 68 + d2 + akoff) << 2));
#pragma unroll
            for (int ntp = 0; ntp < 4; ntp++) {
                unsigned B[4];
                ldm4(B, Ksa + (((ntp * 16 + brow) * 68 + d2 + bkoff) << 2));
                mma16f(s[2 * ntp],     A0[0], A0[1], A0[2], A0[3], B[0], B[1]);
                mma16f(s[2 * ntp + 1], A0[0], A0[1], A0[2], A0[3], B[2], B[3]);
            }
        }

        // ---- scale + mask + row max ----
        float ml0 = -1e30f, ml1 = -1e30f;
#pragma unroll
        for (int nt = 0; nt < 8; nt++) {
            int col = nt * 8 + 2 * t4;
            float2 ma = __ldg((const float2*)(Mrow + (size_t)(qw + g) * LL + kbase + col));
            float2 mb = __ldg((const float2*)(Mrow + (size_t)(qw + 8 + g) * LL + kbase + col));
            s[nt][0] = s[nt][0] * ATT_SCALE + ma.x;
            s[nt][1] = s[nt][1] * ATT_SCALE + ma.y;
            s[nt][2] = s[nt][2] * ATT_SCALE + mb.x;
            s[nt][3] = s[nt][3] * ATT_SCALE + mb.y;
            ml0 = fmaxf(ml0, fmaxf(s[nt][0], s[nt][1]));
            ml1 = fmaxf(ml1, fmaxf(s[nt][2], s[nt][3]));
        }
        ml0 = fmaxf(ml0, __shfl_xor_sync(~0u, ml0, 1));
        ml0 = fmaxf(ml0, __shfl_xor_sync(~0u, ml0, 2));
        ml1 = fmaxf(ml1, __shfl_xor_sync(~0u, ml1, 1));
        ml1 = fmaxf(ml1, __shfl_xor_sync(~0u, ml1, 2));

        float mn0 = fmaxf(m0, ml0), mn1 = fmaxf(m1, ml1);
        float al0 = __expf(m0 - mn0), al1 = __expf(m1 - mn1);
        m0 = mn0; m1 = mn1;

        // ---- exp; P packed into A-fragments ----
        float rs0 = 0.f, rs1 = 0.f;
        unsigned ph0[8], ph1[8];
#pragma unroll
        for (int nt = 0; nt < 8; nt++) {
            float p0 = __expf(s[nt][0] - mn0);
            float p1 = __expf(s[nt][1] - mn0);
            float p2 = __expf(s[nt][2] - mn1);
            float p3 = __expf(s[nt][3] - mn1);
            rs0 += p0 + p1; rs1 += p2 + p3;
            ph0[nt] = phf(p0, p1);
            ph1[nt] = phf(p2, p3);
        }
        rs0 += __shfl_xor_sync(~0u, rs0, 1);
        rs0 += __shfl_xor_sync(~0u, rs0, 2);
        rs1 += __shfl_xor_sync(~0u, rs1, 1);
        rs1 += __shfl_xor_sync(~0u, rs1, 2);
        l0 = l0 * al0 + rs0;
        l1 = l1 * al1 + rs1;

#pragma unroll
        for (int dt = 0; dt < 16; dt++) {
            o[dt][0] *= al0; o[dt][1] *= al0;
            o[dt][2] *= al1; o[dt][3] *= al1;
        }
        cp_wait1();
        __syncthreads();

        // ---- O += P V ----
#pragma unroll
        for (int ko = 0; ko < 4; ko++) {
            unsigned a0 = ph0[2 * ko], a1 = ph1[2 * ko];
            unsigned a2 = ph0[2 * ko + 1], a3 = ph1[2 * ko + 1];
#pragma unroll
            for (int dtp = 0; dtp < 8; dtp++) {
                unsigned B[4];
                ldm4(B, Va + (((dtp * 16 + brow) * 36 + ko * 8 + bkoff) << 2));
                mma16f(o[2 * dtp],     a0, a1, a2, a3, B[0], B[1]);
                mma16f(o[2 * dtp + 1], a0, a1, a2, a3, B[2], B[3]);
            }
        }
    }

    float i0 = 1.f / l0, i1 = 1.f / l1;
    int row0 = win_src_row(win * LL + qbase + qw + g);
    int row1 = win_src_row(win * LL + qbase + qw + 8 + g);
#pragma unroll
    for (int dt = 0; dt < 16; dt++) {
        int uc = dt * 4 + t4;
        g_attnh[(size_t)row0 * 64 + uc] = phf(o[dt][0] * i0, o[dt][1] * i0);
        g_attnh[(size_t)row1 * 64 + uc] = phf(o[dt][2] * i1, o[dt][3] * i1);
    }
}

// ---------------- K3: message = LN(attn @ Wm). grid 256 x 256 --------------
__global__ __launch_bounds__(256, 2) void k_wm_ln(const float* __restrict__ g1,
                                                  const float* __restrict__ b1) {
    extern __shared__ unsigned sm[];
    float* Rs = (float*)sm;

    const int tid = threadIdx.x, tile = blockIdx.x;
    const int warp = tid >> 5, lane = tid & 31, g = lane >> 2, t4 = lane & 3;
    const int rb = (warp >> 1) * 32, cb = (warp & 1) * 64;

    float acc[2][8][4];
    gemm_h(sm, g_attnh + (size_t)tile * 128 * 64, 0, 99, 64,
           g_Wqkvh + 24576, 64, 2, acc);

    __syncthreads();
#pragma unroll
    for (int mt = 0; mt < 2; mt++) {
        int r0 = rb + mt * 16 + g;
#pragma unroll
        for (int nt = 0; nt < 8; nt++) {
            int cc = cb + nt * 8 + 2 * t4;
            Rs[r0 * 132 + cc]           = acc[mt][nt][0];
            Rs[r0 * 132 + cc + 1]       = acc[mt][nt][1];
            Rs[(r0 + 8) * 132 + cc]     = acc[mt][nt][2];
            Rs[(r0 + 8) * 132 + cc + 1] = acc[mt][nt][3];
        }
    }
    __syncthreads();

    int row = tid >> 1, half = tid & 1;
    float sum = 0.f, sq = 0.f;
    for (int j = 0; j < 64; j++) {
        float v = Rs[row * 132 + half * 64 + j];
        sum += v; sq += v * v;
    }
    sum += __shfl_xor_sync(~0u, sum, 1);
    sq  += __shfl_xor_sync(~0u, sq, 1);
    float mean = sum * 0.0078125f;
    float rstd = rsqrtf(sq * 0.0078125f - mean * mean + 1e-5f);
    size_t orow = (size_t)(tile * 128 + row) * 64 + half * 32;
    for (int j = 0; j < 32; j++) {
        int c0 = half * 64 + 2 * j;
        float v0 = (Rs[row * 132 + c0] - mean) * rstd * g1[c0] + b1[c0];
        float v1 = (Rs[row * 132 + c0 + 1] - mean) * rstd * g1[c0 + 1] + b1[c0 + 1];
        g_msgh[orow + j] = phf(v0, v1);
    }
}

// ---------------- K4: hidden = gelu([src|msg] @ W1). grid(8,256) x 256 -----
__global__ __launch_bounds__(256, 2) void k_mlp1() {
    extern __shared__ unsigned sm[];
    const int tid = threadIdx.x, nb = blockIdx.x * 128, tile = blockIdx.y;
    const int warp = tid >> 5, lane = tid & 31, g = lane >> 2, t4 = lane & 3;
    const int rb = (warp >> 1) * 32, cb = (warp & 1) * 64;

    float acc[2][8][4];
    gemm_h(sm, g_srch + (size_t)tile * 128 * 64, g_msgh + (size_t)tile * 128 * 64,
           2, 64, g_W1h + (size_t)nb * 128, 128, 4, acc);

#pragma unroll
    for (int mt = 0; mt < 2; mt++) {
        int row0 = tile * 128 + rb + mt * 16 + g, row1 = row0 + 8;
#pragma unroll
        for (int nt = 0; nt < 8; nt++) {
            int uc = (nb >> 1) + (cb >> 1) + nt * 4 + t4;
            float x0 = acc[mt][nt][0], x1 = acc[mt][nt][1];
            float x2 = acc[mt][nt][2], x3 = acc[mt][nt][3];
            x0 = 0.5f * x0 * (1.f + erff(x0 * 0.70710678f));
            x1 = 0.5f * x1 * (1.f + erff(x1 * 0.70710678f));
            x2 = 0.5f * x2 * (1.f + erff(x2 * 0.70710678f));
            x3 = 0.5f * x3 * (1.f + erff(x3 * 0.70710678f));
            g_hidh[(size_t)row0 * 512 + uc] = phf(x0, x1);
            g_hidh[(size_t)row1 * 512 + uc] = phf(x2, x3);
        }
    }
}

// ---------------- K5: out = src + LN(hidden @ W2). grid 256 x 256 ----------
__global__ __launch_bounds__(256, 2) void k_mlp2(const float* __restrict__ src,
                                                 const float* __restrict__ g2,
                                                 const float* __restrict__ b2,
                                                 float* __restrict__ out) {
    extern __shared__ unsigned sm[];
    float* Rs = (float*)sm;
    const int tid = threadIdx.x, tile = blockIdx.x;
    const int warp = tid >> 5, lane = tid & 31, g = lane >> 2, t4 = lane & 3;
    const int rb = (warp >> 1) * 32, cb = (warp & 1) * 64;

    float acc[2][8][4];
    gemm_h(sm, g_hidh + (size_t)tile * 128 * 512, 0, 99, 512, g_W2h, 512, 16, acc);

    __syncthreads();
#pragma unroll
    for (int mt = 0; mt < 2; mt++) {
        int r0 = rb + mt * 16 + g;
#pragma unroll
        for (int nt = 0; nt < 8; nt++) {
            int cc = cb + nt * 8 + 2 * t4;
            Rs[r0 * 132 + cc]           = acc[mt][nt][0];
            Rs[r0 * 132 + cc + 1]       = acc[mt][nt][1];
            Rs[(r0 + 8) * 132 + cc]     = acc[mt][nt][2];
            Rs[(r0 + 8) * 132 + cc + 1] = acc[mt][nt][3];
        }
    }
    __syncthreads();

    int row = tid >> 1, half = tid & 1;
    float sum = 0.f, sq = 0.f;
    for (int j = 0; j < 64; j++) {
        float v = Rs[row * 132 + half * 64 + j];
        sum += v; sq += v * v;
    }
    sum += __shfl_xor_sync(~0u, sum, 1);
    sq  += __shfl_xor_sync(~0u, sq, 1);
    float mean = sum * 0.0078125f;
    float rstd = rsqrtf(sq * 0.0078125f - mean * mean + 1e-5f);
    size_t grow = (size_t)(tile * 128 + row) * 128 + half * 64;
    for (int j = 0; j < 64; j += 2) {
        int cc = half * 64 + j;
        float2 sv = *(const float2*)(src + grow + j);
        float2 ov;
        ov.x = sv.x + (Rs[row * 132 + cc] - mean) * rstd * g2[cc] + b2[cc];
        ov.y = sv.y + (Rs[row * 132 + cc + 1] - mean) * rstd * g2[cc + 1] + b2[cc + 1];
        *(float2*)(out + grow + j) = ov;
    }
}

extern "C" void kernel_launch(void* const* d_in, const int* in_sizes, int n_in,
                              void* d_out, int out_size) {
    (void)in_sizes; (void)n_in; (void)out_size;
    const float* src  = (const float*)d_in[0];
    const float* tgt  = (const float*)d_in[1];
    const float* mask = (const float*)d_in[2];
    const float* Wq   = (const float*)d_in[8];
    const float* Wk   = (const float*)d_in[9];
    const float* Wv   = (const float*)d_in[10];
    const float* Wm   = (const float*)d_in[11];
    const float* g1   = (const float*)d_in[12];
    const float* b1   = (const float*)d_in[13];
    const float* W1   = (const float*)d_in[14];
    const float* W2   = (const float*)d_in[15];
    const float* g2   = (const float*)d_in[16];
    const float* b2   = (const float*)d_in[17];
    float* out = (float*)d_out;

    const int SMQ = (8704 + 2 * 8704 + 128) * 4;             // 104960
    const int SMA = (AQ_W + 2 * AK_W + AV_W) * 4;            // 88064
    const int SMG = 18432 * 4;                               // 73728

    cudaFuncSetAttribute(k_qkv,   cudaFuncAttributeMaxDynamicSharedMemorySize, SMQ);
    cudaFuncSetAttribute(k_attn,  cudaFuncAttributeMaxDynamicSharedMemorySize, SMA);
    cudaFuncSetAttribute(k_wm_ln, cudaFuncAttributeMaxDynamicSharedMemorySize, SMG);
    cudaFuncSetAttribute(k_mlp1,  cudaFuncAttributeMaxDynamicSharedMemorySize, SMG);
    cudaFuncSetAttribute(k_mlp2,  cudaFuncAttributeMaxDynamicSharedMemorySize, SMG);

    k_prep <<<9089, 256>>>(src, tgt, W1, W2, Wq, Wk, Wv, Wm);
    k_qkv  <<<256,          256, SMQ>>>();
    k_attn <<<dim3(16, 16), 256, SMA>>>(mask);
    k_wm_ln<<<256,          256, SMG>>>(g1, b1);
    k_mlp1 <<<dim3(8, 256), 256, SMG>>>();
    k_mlp2 <<<256,          256, SMG>>>(src, g2, b2, out);
}

// round 16
// speedup vs baseline: 4.4720x; 1.0505x over previous
#include <cuda_runtime.h>
#include <cuda_fp16.h>
#include <math.h>

#define TOK   32768
#define LL    2048
#define ATT_SCALE 0.08838834764831845f

// All operands packed fp16 (u32 = half2 pair along k/cols).
__device__ unsigned g_srch[TOK * 64];
__device__ unsigned g_tgth[TOK * 64];
__device__ unsigned g_msgh[TOK * 64];
__device__ unsigned g_Qh[TOK * 64];
__device__ unsigned g_Kh[TOK * 64];
__device__ __half   g_Vh[(size_t)TOK * 128];   // [win][d=128][k=2048]
__device__ unsigned g_hidh[(size_t)TOK * 512];
__device__ unsigned g_Wqkvh[4 * 8192];         // [Wq|Wk|Wv|Wm], each [n=128][k/2=64]
__device__ unsigned g_W1h[1024 * 128];         // [n][k/2]
__device__ unsigned g_W2h[128 * 512];          // [n][k/2]

__device__ __forceinline__ unsigned phf(float lo, float hi) {
    __half2 h = __floats2half2_rn(lo, hi);
    return *(unsigned*)&h;
}
__device__ __forceinline__ void mma16f(float* c, unsigned a0, unsigned a1,
                                       unsigned a2, unsigned a3,
                                       unsigned b0, unsigned b1) {
    asm volatile(
        "mma.sync.aligned.m16n8k16.row.col.f32.f16.f16.f32 "
        "{%0,%1,%2,%3},{%4,%5,%6,%7},{%8,%9},{%0,%1,%2,%3};"
        : "+f"(c[0]), "+f"(c[1]), "+f"(c[2]), "+f"(c[3])
        : "r"(a0), "r"(a1), "r"(a2), "r"(a3), "r"(b0), "r"(b1));
}
__device__ __forceinline__ void ldm4(unsigned* r, unsigned addr) {
    asm volatile("ldmatrix.sync.aligned.m8n8.x4.shared.b16 {%0,%1,%2,%3}, [%4];"
                 : "=r"(r[0]), "=r"(r[1]), "=r"(r[2]), "=r"(r[3]) : "r"(addr));
}
__device__ __forceinline__ unsigned smu32(const void* p) {
    return (unsigned)__cvta_generic_to_shared(p);
}
__device__ __forceinline__ void cpa16(void* dst_smem, const void* src) {
    unsigned a = (unsigned)__cvta_generic_to_shared(dst_smem);
    asm volatile("cp.async.cg.shared.global [%0], [%1], 16;\n" :: "r"(a), "l"(src));
}
__device__ __forceinline__ void cp_commit() { asm volatile("cp.async.commit_group;\n"); }
__device__ __forceinline__ void cp_wait0()  { asm volatile("cp.async.wait_group 0;\n"); }
__device__ __forceinline__ void cp_wait1()  { asm volatile("cp.async.wait_group 1;\n"); }

__device__ __forceinline__ int win_src_row(int gr) {
    int b = gr >> 13, rem = gr & 8191;
    int w4 = rem >> 11, p = rem & 2047;
    int wi = w4 >> 1, wj = w4 & 1;
    int iy = p >> 6, ix = p & 63;
    int y = (wi * 32 + iy + 16) & 63;
    int x = (wj * 64 + ix + 32) & 127;
    return (b << 13) + (y << 7) + x;
}

// ---------------- K0: pack inputs/weights to fp16 --------------------------
#define SRCU  2097152
__global__ void k_prep(const float* __restrict__ src, const float* __restrict__ tgt,
                       const float* __restrict__ W1, const float* __restrict__ W2,
                       const float* __restrict__ Wq, const float* __restrict__ Wk,
                       const float* __restrict__ Wv, const float* __restrict__ Wm) {
    int i = blockIdx.x * 256 + threadIdx.x;
    if (i < SRCU) {
        float2 v = ((const float2*)src)[i];
        g_srch[i] = phf(v.x, v.y);
        float2 t = ((const float2*)tgt)[i];
        g_tgth[i] = phf(t.x, t.y);
    } else {
        int j = i - SRCU;
        if (j < 32768) {
            int sel = j >> 13, r = j & 8191;
            int n = r >> 6, kp = r & 63;
            const float* W = (sel == 0) ? Wq : (sel == 1) ? Wk : (sel == 2) ? Wv : Wm;
            g_Wqkvh[sel * 8192 + n * 64 + kp] = phf(W[2 * kp * 128 + n], W[(2 * kp + 1) * 128 + n]);
        } else if (j < 32768 + 131072) {
            int jj = j - 32768;
            int n = jj >> 7, kp = jj & 127;
            g_W1h[n * 128 + kp] = phf(W1[2 * kp * 1024 + n], W1[(2 * kp + 1) * 1024 + n]);
        } else if (j < 32768 + 131072 + 65536) {
            int jj = j - 32768 - 131072;
            int n = jj >> 9, kp = jj & 511;
            g_W2h[n * 512 + kp] = phf(W2[2 * kp * 128 + n], W2[(2 * kp + 1) * 128 + n]);
        }
    }
}

// ============ shared fp16 dense-GEMM mainloop (tile 128x128) ===============
__device__ __forceinline__ void stage_ab(unsigned* Ast, unsigned* Bst, int buf,
                                         const unsigned* A1, const unsigned* A2, int swc,
                                         int aKu, const unsigned* Bg, int bKu, int c, int tid) {
    const unsigned* asrc = (c < swc) ? A1 + c * 32 : A2 + (c - swc) * 32;
    for (int i = tid; i < 1024; i += 256) {
        int r = i >> 3, q = i & 7;
        cpa16(Ast + buf * 4608 + r * 36 + q * 4, asrc + (size_t)r * aKu + q * 4);
    }
    for (int i = tid; i < 1024; i += 256) {
        int n = i >> 3, q = i & 7;
        cpa16(Bst + buf * 4608 + n * 36 + q * 4, Bg + (size_t)n * bKu + c * 32 + q * 4);
    }
}

__device__ __forceinline__ void gemm_h(unsigned* sm, const unsigned* A1, const unsigned* A2,
                                       int swc, int aKu, const unsigned* Bg, int bKu,
                                       int nch, float acc[2][8][4]) {
    const int tid = threadIdx.x;
    const int warp = tid >> 5, lane = tid & 31;
    const int rb = (warp >> 1) * 32, cb = (warp & 1) * 64;
    const int mat = lane >> 3, rid = lane & 7;
    const int arow = rb + ((mat & 1) << 3) + rid;
    const int akoff = (mat & 2) ? 4 : 0;
    const int brow = ((mat >> 1) << 3) + rid;
    const int bkoff = (mat & 1) ? 4 : 0;
    unsigned* Ast = sm;
    unsigned* Bst = sm + 9216;
    const unsigned Abase = smu32(Ast), Bbase = smu32(Bst);

#pragma unroll
    for (int mt = 0; mt < 2; mt++)
#pragma unroll
        for (int nt = 0; nt < 8; nt++)
            acc[mt][nt][0] = acc[mt][nt][1] = acc[mt][nt][2] = acc[mt][nt][3] = 0.f;

    stage_ab(Ast, Bst, 0, A1, A2, swc, aKu, Bg, bKu, 0, tid);
    cp_commit();

#pragma unroll 1
    for (int c = 0; c < nch; c++) {
        const int st = c & 1;
        if (c > 0) __syncthreads();
        if (c + 1 < nch) stage_ab(Ast, Bst, st ^ 1, A1, A2, swc, aKu, Bg, bKu, c + 1, tid);
        cp_commit();
        cp_wait1();
        __syncthreads();

        const unsigned Aa = Abase + st * 18432;
        const unsigned Ba = Bbase + st * 18432;
#pragma unroll
        for (int ko = 0; ko < 4; ko++) {
            unsigned A0[4], A1r[4];
            ldm4(A0,  Aa + ((arow * 36 + ko * 8 + akoff) << 2));
            ldm4(A1r, Aa + (((arow + 16) * 36 + ko * 8 + akoff) << 2));
#pragma unroll
            for (int ntp = 0; ntp < 4; ntp++) {
                unsigned B[4];
                ldm4(B, Ba + (((cb + ntp * 16 + brow) * 36 + ko * 8 + bkoff) << 2));
                mma16f(acc[0][2 * ntp],     A0[0], A0[1], A0[2], A0[3], B[0], B[1]);
                mma16f(acc[1][2 * ntp],     A1r[0], A1r[1], A1r[2], A1r[3], B[0], B[1]);
                mma16f(acc[0][2 * ntp + 1], A0[0], A0[1], A0[2], A0[3], B[2], B[3]);
                mma16f(acc[1][2 * ntp + 1], A1r[0], A1r[1], A1r[2], A1r[3], B[2], B[3]);
            }
        }
    }
}

// ---------------- K1: merged QKV (A resident). grid 256 x 256 --------------
__device__ __forceinline__ void qkv_compute(unsigned Aa, unsigned Ba,
                                            float acc[2][8][4], int rb, int cb, int lane) {
    const int mat = lane >> 3, rid = lane & 7;
    const int arow = rb + ((mat & 1) << 3) + rid;
    const int akoff = (mat & 2) ? 4 : 0;
    const int brow = ((mat >> 1) << 3) + rid;
    const int bkoff = (mat & 1) ? 4 : 0;
#pragma unroll
    for (int mt = 0; mt < 2; mt++)
#pragma unroll
        for (int nt = 0; nt < 8; nt++)
            acc[mt][nt][0] = acc[mt][nt][1] = acc[mt][nt][2] = acc[mt][nt][3] = 0.f;
#pragma unroll
    for (int ko = 0; ko < 8; ko++) {
        unsigned A0[4], A1r[4];
        ldm4(A0,  Aa + ((arow * 68 + ko * 8 + akoff) << 2));
        ldm4(A1r, Aa + (((arow + 16) * 68 + ko * 8 + akoff) << 2));
#pragma unroll
        for (int ntp = 0; ntp < 4; ntp++) {
            unsigned B[4];
            ldm4(B, Ba + (((cb + ntp * 16 + brow) * 68 + ko * 8 + bkoff) << 2));
            mma16f(acc[0][2 * ntp],     A0[0], A0[1], A0[2], A0[3], B[0], B[1]);
            mma16f(acc[1][2 * ntp],     A1r[0], A1r[1], A1r[2], A1r[3], B[0], B[1]);
            mma16f(acc[0][2 * ntp + 1], A0[0], A0[1], A0[2], A0[3], B[2], B[3]);
            mma16f(acc[1][2 * ntp + 1], A1r[0], A1r[1], A1r[2], A1r[3], B[2], B[3]);
        }
    }
}

__global__ __launch_bounds__(256, 2) void k_qkv() {
    extern __shared__ unsigned sm[];
    unsigned* As  = sm;                 // [128][68]
    unsigned* Bst = sm + 8704;          // 2 x [128][68]
    int* rows     = (int*)(Bst + 17408);

    const int tid = threadIdx.x, tile = blockIdx.x;
    const int warp = tid >> 5, lane = tid & 31, g = lane >> 2, t4 = lane & 3;
    const int rb = (warp >> 1) * 32, cb = (warp & 1) * 64;
    const unsigned Aa = smu32(As), Ba = smu32(Bst);

    if (tid < 128) rows[tid] = win_src_row(tile * 128 + tid);
    __syncthreads();

    for (int i = tid; i < 2048; i += 256) {
        int r = i >> 4, q = i & 15;
        cpa16(As + r * 68 + q * 4, g_tgth + (size_t)rows[r] * 64 + q * 4);
    }
    for (int i = tid; i < 2048; i += 256) {
        int n = i >> 4, q = i & 15;
        cpa16(Bst + n * 68 + q * 4, g_Wqkvh + 8192 + n * 64 + q * 4);
    }
    cp_commit();
    for (int i = tid; i < 2048; i += 256) {
        int n = i >> 4, q = i & 15;
        cpa16(Bst + 8704 + n * 68 + q * 4, g_Wqkvh + 16384 + n * 64 + q * 4);
    }
    cp_commit();
    cp_wait1();
    __syncthreads();

    float acc[2][8][4];
    qkv_compute(Aa, Ba, acc, rb, cb, lane);        // K
#pragma unroll
    for (int mt = 0; mt < 2; mt++) {
        int row0 = tile * 128 + rb + mt * 16 + g, row1 = row0 + 8;
#pragma unroll
        for (int nt = 0; nt < 8; nt++) {
            int uc = (cb >> 1) + nt * 4 + t4;
            g_Kh[(size_t)row0 * 64 + uc] = phf(acc[mt][nt][0], acc[mt][nt][1]);
            g_Kh[(size_t)row1 * 64 + uc] = phf(acc[mt][nt][2], acc[mt][nt][3]);
        }
    }
    __syncthreads();   // all warps done reading Wk before Wq overwrites Bst[0]

    for (int i = tid; i < 2048; i += 256) {
        int n = i >> 4, q = i & 15;
        cpa16(Bst + n * 68 + q * 4, g_Wqkvh + n * 64 + q * 4);
    }
    cp_commit();
    cp_wait1();
    __syncthreads();

    qkv_compute(Aa, Ba + 8704 * 4, acc, rb, cb, lane);   // V
    {
        __half* Vh = g_Vh + (size_t)(tile >> 4) * 262144;
#pragma unroll
        for (int mt = 0; mt < 2; mt++) {
            int kk = (tile * 128 + rb + mt * 16 + g) & 2047;
#pragma unroll
            for (int nt = 0; nt < 8; nt++) {
                int cc = cb + nt * 8 + 2 * t4;
                Vh[(size_t)cc * 2048 + kk]           = __float2half(acc[mt][nt][0]);
                Vh[(size_t)(cc + 1) * 2048 + kk]     = __float2half(acc[mt][nt][1]);
                Vh[(size_t)cc * 2048 + kk + 8]       = __float2half(acc[mt][nt][2]);
                Vh[(size_t)(cc + 1) * 2048 + kk + 8] = __float2half(acc[mt][nt][3]);
            }
        }
    }
    __syncthreads();

    for (int i = tid; i < 2048; i += 256) {
        int r = i >> 4, q = i & 15;
        cpa16(As + r * 68 + q * 4, g_srch + (size_t)rows[r] * 64 + q * 4);
    }
    cp_commit();
    cp_wait0();
    __syncthreads();

    qkv_compute(Aa, Ba, acc, rb, cb, lane);        // Q
#pragma unroll
    for (int mt = 0; mt < 2; mt++) {
        int row0 = tile * 128 + rb + mt * 16 + g, row1 = row0 + 8;
#pragma unroll
        for (int nt = 0; nt < 8; nt++) {
            int uc = (cb >> 1) + nt * 4 + t4;
            g_Qh[(size_t)row0 * 64 + uc] = phf(acc[mt][nt][0], acc[mt][nt][1]);
            g_Qh[(size_t)row1 * 64 + uc] = phf(acc[mt][nt][2], acc[mt][nt][3]);
        }
    }
}

// ------- K2: flash attention + fused message=LN(O@Wm). grid(16,16) x 256 ---
// V double-buffered: 2 barriers/iter. Epilogue reuses Qs for Wm.
#define AQ_W 8704   // [128][68]
#define AK_W 4352   // [64][68]
#define AV_W 4608   // [128][36]
__global__ __launch_bounds__(256, 2) void k_attn(const float* __restrict__ mask,
                                                 const float* __restrict__ g1,
                                                 const float* __restrict__ b1) {
    extern __shared__ unsigned sm[];
    unsigned* Qs  = sm;
    unsigned* Kst = sm + AQ_W;
    unsigned* Vst = Kst + 2 * AK_W;

    const int tid = threadIdx.x, warp = tid >> 5, lane = tid & 31;
    const int g = lane >> 2, t4 = lane & 3;
    const int qw = warp * 16;
    const int qbase = blockIdx.x * 128, win = blockIdx.y, w4 = win & 3;
    const int mat = lane >> 3, rid = lane & 7;
    const int qrow = qw + ((mat & 1) << 3) + rid;
    const int akoff = (mat & 2) ? 4 : 0;
    const int brow = ((mat >> 1) << 3) + rid;
    const int bkoff = (mat & 1) ? 4 : 0;
    const unsigned Qa = smu32(Qs), Ka = smu32(Kst), Va = smu32(Vst);

    const unsigned* Qg  = g_Qh + (size_t)(win * LL + qbase) * 64;
    const unsigned* Kgb = g_Kh + (size_t)(win * LL) * 64;
    const unsigned* Vu  = (const unsigned*)g_Vh + (size_t)win * 131072;
    const float* Mrow = mask + (size_t)w4 * LL * LL + (size_t)qbase * LL;

    // prologue: Q + K0 + V0 in one group
    for (int i = tid; i < 2048; i += 256) {
        int r = i >> 4, q = i & 15;
        cpa16(Qs + r * 68 + q * 4, Qg + (size_t)r * 64 + q * 4);
    }
    for (int i = tid; i < 1024; i += 256) {
        int r = i >> 4, q = i & 15;
        cpa16(Kst + r * 68 + q * 4, Kgb + (size_t)r * 64 + q * 4);
    }
    for (int i = tid; i < 1024; i += 256) {
        int d = i >> 3, q = i & 7;
        cpa16(Vst + d * 36 + q * 4, Vu + (size_t)d * 1024 + q * 4);
    }
    cp_commit();                                 // G0

    float o[16][4];
#pragma unroll
    for (int dt = 0; dt < 16; dt++) o[dt][0] = o[dt][1] = o[dt][2] = o[dt][3] = 0.f;
    float m0 = -1e30f, m1 = -1e30f, l0 = 0.f, l1 = 0.f;

#pragma unroll 1
    for (int kt = 0; kt < 32; kt++) {
        const int st = kt & 1;
        const int kbase = kt * 64;

        if (kt > 0) __syncthreads();             // B0: prev iter readers of buf st^1 done
        if (kt + 1 < 32) {
            const unsigned* Kg = Kgb + (size_t)(kt + 1) * 64 * 64;
            unsigned* Kd = Kst + (st ^ 1) * AK_W;
            unsigned* Vd = Vst + (st ^ 1) * AV_W;
            for (int i = tid; i < 1024; i += 256) {
                int r = i >> 4, q = i & 15;
                cpa16(Kd + r * 68 + q * 4, Kg + (size_t)r * 64 + q * 4);
            }
            for (int i = tid; i < 1024; i += 256) {
                int d = i >> 3, q = i & 7;
                cpa16(Vd + d * 36 + q * 4, Vu + (size_t)d * 1024 + ((kt + 1) * 32) + q * 4);
            }
        }
        cp_commit();                             // G_{kt+1}
        cp_wait1();                              // G_kt complete
        __syncthreads();                         // B1: publish buf st

        const unsigned Ksa = Ka + st * (AK_W * 4);
        const unsigned Vsa = Va + st * (AV_W * 4);

        // ---- S = Q K^T ----
        float s[8][4];
#pragma unroll
        for (int nt = 0; nt < 8; nt++) s[nt][0] = s[nt][1] = s[nt][2] = s[nt][3] = 0.f;
#pragma unroll
        for (int d2 = 0; d2 < 64; d2 += 8) {
            unsigned A0[4];
            ldm4(A0, Qa + ((qrow * 68 + d2 + akoff) << 2));
#pragma unroll
            for (int ntp = 0; ntp < 4; ntp++) {
                unsigned B[4];
                ldm4(B, Ksa + (((ntp * 16 + brow) * 68 + d2 + bkoff) << 2));
                mma16f(s[2 * ntp],     A0[0], A0[1], A0[2], A0[3], B[0], B[1]);
                mma16f(s[2 * ntp + 1], A0[0], A0[1], A0[2], A0[3], B[2], B[3]);
            }
        }

        // ---- scale + mask + row max ----
        float ml0 = -1e30f, ml1 = -1e30f;
#pragma unroll
        for (int nt = 0; nt < 8; nt++) {
            int col = nt * 8 + 2 * t4;
            float2 ma = __ldg((const float2*)(Mrow + (size_t)(qw + g) * LL + kbase + col));
            float2 mb = __ldg((const float2*)(Mrow + (size_t)(qw + 8 + g) * LL + kbase + col));
            s[nt][0] = s[nt][0] * ATT_SCALE + ma.x;
            s[nt][1] = s[nt][1] * ATT_SCALE + ma.y;
            s[nt][2] = s[nt][2] * ATT_SCALE + mb.x;
            s[nt][3] = s[nt][3] * ATT_SCALE + mb.y;
            ml0 = fmaxf(ml0, fmaxf(s[nt][0], s[nt][1]));
            ml1 = fmaxf(ml1, fmaxf(s[nt][2], s[nt][3]));
        }
        ml0 = fmaxf(ml0, __shfl_xor_sync(~0u, ml0, 1));
        ml0 = fmaxf(ml0, __shfl_xor_sync(~0u, ml0, 2));
        ml1 = fmaxf(ml1, __shfl_xor_sync(~0u, ml1, 1));
        ml1 = fmaxf(ml1, __shfl_xor_sync(~0u, ml1, 2));

        float mn0 = fmaxf(m0, ml0), mn1 = fmaxf(m1, ml1);
        float al0 = __expf(m0 - mn0), al1 = __expf(m1 - mn1);
        m0 = mn0; m1 = mn1;

        // ---- exp; P packed into A-fragments ----
        float rs0 = 0.f, rs1 = 0.f;
        unsigned ph0[8], ph1[8];
#pragma unroll
        for (int nt = 0; nt < 8; nt++) {
            float p0 = __expf(s[nt][0] - mn0);
            float p1 = __expf(s[nt][1] - mn0);
            float p2 = __expf(s[nt][2] - mn1);
            float p3 = __expf(s[nt][3] - mn1);
            rs0 += p0 + p1; rs1 += p2 + p3;
            ph0[nt] = phf(p0, p1);
            ph1[nt] = phf(p2, p3);
        }
        rs0 += __shfl_xor_sync(~0u, rs0, 1);
        rs0 += __shfl_xor_sync(~0u, rs0, 2);
        rs1 += __shfl_xor_sync(~0u, rs1, 1);
        rs1 += __shfl_xor_sync(~0u, rs1, 2);
        l0 = l0 * al0 + rs0;
        l1 = l1 * al1 + rs1;

#pragma unroll
        for (int dt = 0; dt < 16; dt++) {
            o[dt][0] *= al0; o[dt][1] *= al0;
            o[dt][2] *= al1; o[dt][3] *= al1;
        }

        // ---- O += P V ----
#pragma unroll
        for (int ko = 0; ko < 4; ko++) {
            unsigned a0 = ph0[2 * ko], a1 = ph1[2 * ko];
            unsigned a2 = ph0[2 * ko + 1], a3 = ph1[2 * ko + 1];
#pragma unroll
            for (int dtp = 0; dtp < 8; dtp++) {
                unsigned B[4];
                ldm4(B, Vsa + (((dtp * 16 + brow) * 36 + ko * 8 + bkoff) << 2));
                mma16f(o[2 * dtp],     a0, a1, a2, a3, B[0], B[1]);
                mma16f(o[2 * dtp + 1], a0, a1, a2, a3, B[2], B[3]);
            }
        }
    }

    // ---- fused epilogue: message = LN((O/l) @ Wm) ----
    float i0 = 1.f / l0, i1 = 1.f / l1;
    unsigned af[8][4];
#pragma unroll
    for (int ko = 0; ko < 8; ko++) {
        af[ko][0] = phf(o[2 * ko][0] * i0,     o[2 * ko][1] * i0);
        af[ko][1] = phf(o[2 * ko][2] * i1,     o[2 * ko][3] * i1);
        af[ko][2] = phf(o[2 * ko + 1][0] * i0, o[2 * ko + 1][1] * i0);
        af[ko][3] = phf(o[2 * ko + 1][2] * i1, o[2 * ko + 1][3] * i1);
    }
    __syncthreads();                 // everyone done with Qs
    for (int i = tid; i < 2048; i += 256) {     // stage Wm into Qs [128][68]
        int n = i >> 4, q = i & 15;
        cpa16(Qs + n * 68 + q * 4, g_Wqkvh + 24576 + (size_t)n * 64 + q * 4);
    }
    cp_commit();
    cp_wait0();
    __syncthreads();

    float macc[16][4];
#pragma unroll
    for (int nt = 0; nt < 16; nt++) macc[nt][0] = macc[nt][1] = macc[nt][2] = macc[nt][3] = 0.f;
#pragma unroll
    for (int ko = 0; ko < 8; ko++) {
#pragma unroll
        for (int ntp = 0; ntp < 8; ntp++) {
            unsigned B[4];
            ldm4(B, Qa + (((ntp * 16 + brow) * 68 + ko * 8 + bkoff) << 2));
            mma16f(macc[2 * ntp],     af[ko][0], af[ko][1], af[ko][2], af[ko][3], B[0], B[1]);
            mma16f(macc[2 * ntp + 1], af[ko][0], af[ko][1], af[ko][2], af[ko][3], B[2], B[3]);
        }
    }

    // LayerNorm over each warp-owned row, then scatter to token order
    float sum0 = 0.f, sq0 = 0.f, sum1 = 0.f, sq1 = 0.f;
#pragma unroll
    for (int nt = 0; nt < 16; nt++) {
        sum0 += macc[nt][0] + macc[nt][1];
        sq0  += macc[nt][0] * macc[nt][0] + macc[nt][1] * macc[nt][1];
        sum1 += macc[nt][2] + macc[nt][3];
        sq1  += macc[nt][2] * macc[nt][2] + macc[nt][3] * macc[nt][3];
    }
    sum0 += __shfl_xor_sync(~0u, sum0, 1); sum0 += __shfl_xor_sync(~0u, sum0, 2);
    sq0  += __shfl_xor_sync(~0u, sq0, 1);  sq0  += __shfl_xor_sync(~0u, sq0, 2);
    sum1 += __shfl_xor_sync(~0u, sum1, 1); sum1 += __shfl_xor_sync(~0u, sum1, 2);
    sq1  += __shfl_xor_sync(~0u, sq1, 1);  sq1  += __shfl_xor_sync(~0u, sq1, 2);
    float mean0 = sum0 * 0.0078125f;
    float rstd0 = rsqrtf(sq0 * 0.0078125f - mean0 * mean0 + 1e-5f);
    float mean1 = sum1 * 0.0078125f;
    float rstd1 = rsqrtf(sq1 * 0.0078125f - mean1 * mean1 + 1e-5f);

    int row0 = win_src_row(win * LL + qbase + qw + g);
    int row1 = win_src_row(win * LL + qbase + qw + 8 + g);
#pragma unroll
    for (int nt = 0; nt < 16; nt++) {
        int col = nt * 8 + 2 * t4;
        float2 gg = __ldg((const float2*)(g1 + col));
        float2 bb = __ldg((const float2*)(b1 + col));
        float v0 = (macc[nt][0] - mean0) * rstd0 * gg.x + bb.x;
        float v1 = (macc[nt][1] - mean0) * rstd0 * gg.y + bb.y;
        float v2 = (macc[nt][2] - mean1) * rstd1 * gg.x + bb.x;
        float v3 = (macc[nt][3] - mean1) * rstd1 * gg.y + bb.y;
        g_msgh[(size_t)row0 * 64 + nt * 4 + t4] = phf(v0, v1);
        g_msgh[(size_t)row1 * 64 + nt * 4 + t4] = phf(v2, v3);
    }
}

// ---------------- K4: hidden = gelu([src|msg] @ W1). grid(8,256) x 256 -----
__global__ __launch_bounds__(256, 2) void k_mlp1() {
    extern __shared__ unsigned sm[];
    const int tid = threadIdx.x, nb = blockIdx.x * 128, tile = blockIdx.y;
    const int warp = tid >> 5, lane = tid & 31, g = lane >> 2, t4 = lane & 3;
    const int rb = (warp >> 1) * 32, cb = (warp & 1) * 64;

    float acc[2][8][4];
    gemm_h(sm, g_srch + (size_t)tile * 128 * 64, g_msgh + (size_t)tile * 128 * 64,
           2, 64, g_W1h + (size_t)nb * 128, 128, 4, acc);

#pragma unroll
    for (int mt = 0; mt < 2; mt++) {
        int row0 = tile * 128 + rb + mt * 16 + g, row1 = row0 + 8;
#pragma unroll
        for (int nt = 0; nt < 8; nt++) {
            int uc = (nb >> 1) + (cb >> 1) + nt * 4 + t4;
            float x0 = acc[mt][nt][0], x1 = acc[mt][nt][1];
            float x2 = acc[mt][nt][2], x3 = acc[mt][nt][3];
            x0 = 0.5f * x0 * (1.f + erff(x0 * 0.70710678f));
            x1 = 0.5f * x1 * (1.f + erff(x1 * 0.70710678f));
            x2 = 0.5f * x2 * (1.f + erff(x2 * 0.70710678f));
            x3 = 0.5f * x3 * (1.f + erff(x3 * 0.70710678f));
            g_hidh[(size_t)row0 * 512 + uc] = phf(x0, x1);
            g_hidh[(size_t)row1 * 512 + uc] = phf(x2, x3);
        }
    }
}

// ---------------- K5: out = src + LN(hidden @ W2). grid 256 x 256 ----------
__global__ __launch_bounds__(256, 2) void k_mlp2(const float* __restrict__ src,
                                                 const float* __restrict__ g2,
                                                 const float* __restrict__ b2,
                                                 float* __restrict__ out) {
    extern __shared__ unsigned sm[];
    float* Rs = (float*)sm;
    const int tid = threadIdx.x, tile = blockIdx.x;
    const int warp = tid >> 5, lane = tid & 31, g = lane >> 2, t4 = lane & 3;
    const int rb = (warp >> 1) * 32, cb = (warp & 1) * 64;

    float acc[2][8][4];
    gemm_h(sm, g_hidh + (size_t)tile * 128 * 512, 0, 99, 512, g_W2h, 512, 16, acc);

    __syncthreads();
#pragma unroll
    for (int mt = 0; mt < 2; mt++) {
        int r0 = rb + mt * 16 + g;
#pragma unroll
        for (int nt = 0; nt < 8; nt++) {
            int cc = cb + nt * 8 + 2 * t4;
            Rs[r0 * 132 + cc]           = acc[mt][nt][0];
            Rs[r0 * 132 + cc + 1]       = acc[mt][nt][1];
            Rs[(r0 + 8) * 132 + cc]     = acc[mt][nt][2];
            Rs[(r0 + 8) * 132 + cc + 1] = acc[mt][nt][3];
        }
    }
    __syncthreads();

    int row = tid >> 1, half = tid & 1;
    float sum = 0.f, sq = 0.f;
    for (int j = 0; j < 64; j++) {
        float v = Rs[row * 132 + half * 64 + j];
        sum += v; sq += v * v;
    }
    sum += __shfl_xor_sync(~0u, sum, 1);
    sq  += __shfl_xor_sync(~0u, sq, 1);
    float mean = sum * 0.0078125f;
    float rstd = rsqrtf(sq * 0.0078125f - mean * mean + 1e-5f);
    size_t grow = (size_t)(tile * 128 + row) * 128 + half * 64;
    for (int j = 0; j < 64; j += 2) {
        int cc = half * 64 + j;
        float2 sv = *(const float2*)(src + grow + j);
        float2 ov;
        ov.x = sv.x + (Rs[row * 132 + cc] - mean) * rstd * g2[cc] + b2[cc];
        ov.y = sv.y + (Rs[row * 132 + cc + 1] - mean) * rstd * g2[cc + 1] + b2[cc + 1];
        *(float2*)(out + grow + j) = ov;
    }
}

extern "C" void kernel_launch(void* const* d_in, const int* in_sizes, int n_in,
                              void* d_out, int out_size) {
    (void)in_sizes; (void)n_in; (void)out_size;
    const float* src  = (const float*)d_in[0];
    const float* tgt  = (const float*)d_in[1];
    const float* mask = (const float*)d_in[2];
    const float* Wq   = (const float*)d_in[8];
    const float* Wk   = (const float*)d_in[9];
    const float* Wv   = (const float*)d_in[10];
    const float* Wm   = (const float*)d_in[11];
    const float* g1   = (const float*)d_in[12];
    const float* b1   = (const float*)d_in[13];
    const float* W1   = (const float*)d_in[14];
    const float* W2   = (const float*)d_in[15];
    const float* g2   = (const float*)d_in[16];
    const float* b2   = (const float*)d_in[17];
    float* out = (float*)d_out;

    const int SMQ = (8704 + 2 * 8704 + 128) * 4;                 // 104960
    const int SMA = (AQ_W + 2 * AK_W + 2 * AV_W) * 4;            // 106496
    const int SMG = 18432 * 4;                                   // 73728

    cudaFuncSetAttribute(k_qkv,   cudaFuncAttributeMaxDynamicSharedMemorySize, SMQ);
    cudaFuncSetAttribute(k_attn,  cudaFuncAttributeMaxDynamicSharedMemorySize, SMA);
    cudaFuncSetAttribute(k_mlp1,  cudaFuncAttributeMaxDynamicSharedMemorySize, SMG);
    cudaFuncSetAttribute(k_mlp2,  cudaFuncAttributeMaxDynamicSharedMemorySize, SMG);

    k_prep <<<9089, 256>>>(src, tgt, W1, W2, Wq, Wk, Wv, Wm);
    k_qkv  <<<256,          256, SMQ>>>();
    k_attn <<<dim3(16, 16), 256, SMA>>>(mask, g1, b1);
    k_mlp1 <<<dim3(8, 256), 256, SMG>>>();
    k_mlp2 <<<256,          256, SMG>>>(src, g2, b2, out);
}